// round 9
// baseline (speedup 1.0000x reference)
#include <cuda_runtime.h>
#include <cuda_fp16.h>
#include <math.h>
#include <stdint.h>

#define NN 50000
#define EE 400000
#define GG 512
#define FF 128
#define KK 4
#define HH 64
#define KH 256   // K*H
#define NEG_INF __int_as_float(0xff800000)

// ---------------- device scratch (static, no runtime allocation) ----------------
__device__ float g_z[NN * KH];
__device__ float g_res[NN * KH];
__device__ float g_x[NN * KH];
__device__ float g_el[NN * KK];
__device__ float g_er[NN * KK];
__device__ float g_x3[NN * HH];
__device__ float g_gs[GG * HH];
__device__ float g_gm[GG * HH];
__device__ float g_gmax[12];        // per-layer global el max, 4 heads each
// fp16-split operand storage (half2 packed along K); lo is UNSCALED (x - fp16(x))
__device__ uint32_t g_hh2[NN * 64];
__device__ uint32_t g_hl2[NN * 64];
__device__ uint32_t g_xh2[NN * 128];
__device__ uint32_t g_xl2[NN * 128];
__device__ uint32_t g_wh[98304];   // [n=256][din/2]: W0@0, resW0@16384, W1@32768, W2@65536
__device__ uint32_t g_wl[98304];
// CSR
__device__ int g_rowptr[NN + 1];
__device__ int g_cnt[NN];
__device__ int g_fill[NN];
__device__ int g_csrc[EE];

__device__ __forceinline__ void atomicMaxF(float* addr, float v) {
    if (v >= 0.0f) atomicMax((int*)addr, __float_as_int(v));
    else           atomicMin((unsigned int*)addr, __float_as_uint(v));
}
__device__ __forceinline__ float leaky02(float v) { return v > 0.0f ? v : 0.2f * v; }

// split x into fp16 hi + fp16 lo (UNSCALED residual), packed as half2
__device__ __forceinline__ void splitpack(float a, float b, uint32_t& hi, uint32_t& lo) {
    __half ha = __float2half_rn(a), hb = __float2half_rn(b);
    __half2 hh = __halves2half2(ha, hb);
    hi = *(uint32_t*)&hh;
    float la = a - __half2float(ha);
    float lb = b - __half2float(hb);
    __half2 hl = __floats2half2_rn(la, lb);
    lo = *(uint32_t*)&hl;
}

// ================= async-copy / ldmatrix helpers =================
__device__ __forceinline__ uint32_t s2u(const void* p) {
    return (uint32_t)__cvta_generic_to_shared(p);
}
__device__ __forceinline__ void cpasync16(uint32_t dst, const void* src, uint32_t sz) {
    asm volatile("cp.async.cg.shared.global [%0], [%1], 16, %2;"
                 :: "r"(dst), "l"(src), "r"(sz) : "memory");
}
__device__ __forceinline__ void cpcommit() {
    asm volatile("cp.async.commit_group;" ::: "memory");
}
template <int N>
__device__ __forceinline__ void cpwait() {
    asm volatile("cp.async.wait_group %0;" :: "n"(N) : "memory");
}
#define LDSM4(r, a) \
    asm volatile("ldmatrix.sync.aligned.m8n8.x4.shared.b16 {%0,%1,%2,%3}, [%4];" \
                 : "=r"((r)[0]), "=r"((r)[1]), "=r"((r)[2]), "=r"((r)[3]) : "r"(a))
#define LDSM2(r, a) \
    asm volatile("ldmatrix.sync.aligned.m8n8.x2.shared.b16 {%0,%1}, [%2];" \
                 : "=r"((r)[0]), "=r"((r)[1]) : "r"(a))
#define MMA_F16(d, a, b) \
    asm volatile("mma.sync.aligned.m16n8k16.row.col.f32.f16.f16.f32 " \
                 "{%0,%1,%2,%3}, {%4,%5,%6,%7}, {%8,%9}, {%0,%1,%2,%3};" \
                 : "+f"((d)[0]), "+f"((d)[1]), "+f"((d)[2]), "+f"((d)[3]) \
                 : "r"((a)[0]), "r"((a)[1]), "r"((a)[2]), "r"((a)[3]), \
                   "r"((b)[0]), "r"((b)[1]))

// ================= operand pre-split kernels =================
__global__ void hsplit(const float* __restrict__ h) {
    int idx = blockIdx.x * blockDim.x + threadIdx.x;
    if (idx < 12) g_gmax[idx] = NEG_INF;
    if (idx >= NN * 64) return;
    int row = idx >> 6, k2 = idx & 63;
    float2 v = *(const float2*)&h[row * 128 + k2 * 2];
    splitpack(v.x, v.y, g_hh2[idx], g_hl2[idx]);
}
__global__ void wsplit(const float* __restrict__ W, int off, int din) {
    int idx = blockIdx.x * blockDim.x + threadIdx.x;
    int dh = din >> 1;
    if (idx >= 256 * dh) return;
    int nn = idx & 255, k2 = idx >> 8;
    float v0 = W[(2 * k2) * 256 + nn];
    float v1 = W[(2 * k2 + 1) * 256 + nn];
    splitpack(v0, v1, g_wh[off + nn * dh + k2], g_wl[off + nn * dh + k2]);
}

// ================= CSR build =================
__global__ void csr_zero() {
    int i = blockIdx.x * blockDim.x + threadIdx.x;
    if (i < NN) { g_cnt[i] = 0; g_fill[i] = 0; }
}
__global__ void csr_hist(const int* __restrict__ dst) {
    int e = blockIdx.x * blockDim.x + threadIdx.x;
    if (e < EE) atomicAdd(&g_cnt[dst[e]], 1);
}
__global__ void csr_scan() {
    __shared__ int smW[32];
    __shared__ int sOff;
    int tid = threadIdx.x, lane = tid & 31, wid = tid >> 5;
    if (tid == 0) sOff = 0;
    __syncthreads();
    for (int base = 0; base < NN; base += 1024) {
        int i = base + tid;
        int v = (i < NN) ? g_cnt[i] : 0;
        int inc = v;
#pragma unroll
        for (int o = 1; o < 32; o <<= 1) {
            int t = __shfl_up_sync(0xffffffffu, inc, o);
            if (lane >= o) inc += t;
        }
        if (lane == 31) smW[wid] = inc;
        __syncthreads();
        if (wid == 0) {
            int t = smW[lane];
#pragma unroll
            for (int o = 1; o < 32; o <<= 1) {
                int u = __shfl_up_sync(0xffffffffu, t, o);
                if (lane >= o) t += u;
            }
            smW[lane] = t;
        }
        __syncthreads();
        int warpOff = wid ? smW[wid - 1] : 0;
        if (i < NN) g_rowptr[i] = sOff + warpOff + inc - v;
        int blockTot = smW[31];
        __syncthreads();
        if (tid == 0) sOff += blockTot;
        __syncthreads();
    }
    if (tid == 0) g_rowptr[NN] = sOff;
}
__global__ void csr_fill_k(const int* __restrict__ src, const int* __restrict__ dst) {
    int e = blockIdx.x * blockDim.x + threadIdx.x;
    if (e >= EE) return;
    int d = dst[e];
    int pos = g_rowptr[d] + atomicAdd(&g_fill[d], 1);
    g_csrc[pos] = src[e];
}

// ================= fp16-split GEMM (ldmatrix + cp.async + single acc) ========
// C[n x 256] = A[n x din] @ B[din x 256], operands pre-split hi + lo(unscaled).
// Block tile 128x64, BK=32, 256 threads (8 warps 4x2), warp tile 32x32.
// If alp: also emits g_el/g_er for head blockIdx.x and atomicMax into gmax[hd].
__global__ void __launch_bounds__(256, 3) gemm_h3(
        const uint32_t* __restrict__ Ah2, const uint32_t* __restrict__ Al2,
        const uint32_t* __restrict__ Bh2, const uint32_t* __restrict__ Bl2,
        float* __restrict__ C, int n, int din,
        const float* __restrict__ alp, const float* __restrict__ arp,
        float* __restrict__ gmax) {
    extern __shared__ __align__(16) uint8_t smx[];
    __shared__ float sEl[2][128], sEr[2][128];
    const int tid  = threadIdx.x;
    const int wid  = tid >> 5;
    const int lane = tid & 31;
    const int row0 = blockIdx.y * 128;
    const int col0 = blockIdx.x * 64;
    const int wm0  = (wid >> 1) * 32;
    const int wn0  = (wid & 1) * 32;
    const int grp  = lane >> 2;
    const int qid  = lane & 3;
    const int dh   = din >> 1;
    const int ntiles = dh >> 4;          // k32 tiles

    const uint32_t uA = s2u(smx);        // Ah base
    const uint32_t uB = uA + 40960;      // Bh base

    float acc[2][4][4] = {};

    const int arow = tid >> 2;
    const int ach  = (tid & 3) * 4;

    auto load_tile = [&](int buf, int tile) {
        const int kof = tile * 16;
#pragma unroll
        for (int t = 0; t < 2; t++) {
            int row = arow + t * 64;
            int gr  = row0 + row;
            uint32_t sz = (gr < n) ? 16u : 0u;
            size_t off = (gr < n) ? ((size_t)gr * dh + kof + ach) : 0;
            uint32_t d = uA + buf * 10240 + (row * 20 + ach) * 4;
            cpasync16(d,         Ah2 + off, sz);
            cpasync16(d + 20480, Al2 + off, sz);
        }
        {
            int row = tid >> 2;
            size_t off = (size_t)(col0 + row) * dh + kof + ach;
            uint32_t d = uB + buf * 5120 + (row * 20 + ach) * 4;
            cpasync16(d,         Bh2 + off, 16u);
            cpasync16(d + 10240, Bl2 + off, 16u);
        }
        cpcommit();
    };

    load_tile(0, 0);
    for (int ti = 0; ti < ntiles; ti++) {
        if (ti + 1 < ntiles) { load_tile((ti + 1) & 1, ti + 1); cpwait<1>(); }
        else cpwait<0>();
        __syncthreads();
        const int buf = ti & 1;
        const uint32_t aB = uA + buf * 10240;
        const uint32_t bB = uB + buf * 5120;
#pragma unroll
        for (int ks = 0; ks < 2; ks++) {
            const int kb2 = ks * 8;
            uint32_t afh[2][4], afl[2][4], bfh[4][2], bfl[4][2];
#pragma unroll
            for (int mt = 0; mt < 2; mt++) {
                uint32_t ad = aB + (((wm0 + mt * 16 + (lane & 15)) * 20 + kb2 +
                                     ((lane >> 4) << 2)) << 2);
                LDSM4(afh[mt], ad);
                LDSM4(afl[mt], ad + 20480);
            }
#pragma unroll
            for (int nt = 0; nt < 4; nt++) {
                uint32_t bd = bB + (((wn0 + nt * 8 + (lane & 7)) * 20 + kb2 +
                                     (((lane >> 3) & 1) << 2)) << 2);
                LDSM2(bfh[nt], bd);
                LDSM2(bfl[nt], bd + 10240);
            }
#pragma unroll
            for (int mt = 0; mt < 2; mt++)
#pragma unroll
                for (int nt = 0; nt < 4; nt++) {
                    MMA_F16(acc[mt][nt], afh[mt], bfh[nt]);
                    MMA_F16(acc[mt][nt], afh[mt], bfl[nt]);
                    MMA_F16(acc[mt][nt], afl[mt], bfh[nt]);
                }
        }
        __syncthreads();
    }

    // ---- store C ----
#pragma unroll
    for (int mt = 0; mt < 2; mt++) {
#pragma unroll
        for (int nt = 0; nt < 4; nt++) {
            int r  = row0 + wm0 + mt * 16 + grp;
            int cC = col0 + wn0 + nt * 8 + qid * 2;
            if (r < n)
                *(float2*)&C[(size_t)r * KH + cC] = make_float2(acc[mt][nt][0], acc[mt][nt][1]);
            if (r + 8 < n)
                *(float2*)&C[(size_t)(r + 8) * KH + cC] = make_float2(acc[mt][nt][2], acc[mt][nt][3]);
        }
    }
    // ---- fused attention projections el/er + global el-max ----
    if (alp != nullptr) {
        const int hd = blockIdx.x;
        float alv[4][2], arv[4][2];
#pragma unroll
        for (int nt = 0; nt < 4; nt++)
#pragma unroll
            for (int j = 0; j < 2; j++) {
                int c = wn0 + nt * 8 + qid * 2 + j;
                alv[nt][j] = alp[hd * 64 + c];
                arv[nt][j] = arp[hd * 64 + c];
            }
#pragma unroll
        for (int mt = 0; mt < 2; mt++) {
            float ea = 0.f, eb = 0.f, ra = 0.f, rb = 0.f;
#pragma unroll
            for (int nt = 0; nt < 4; nt++) {
                ea += acc[mt][nt][0] * alv[nt][0] + acc[mt][nt][1] * alv[nt][1];
                eb += acc[mt][nt][2] * alv[nt][0] + acc[mt][nt][3] * alv[nt][1];
                ra += acc[mt][nt][0] * arv[nt][0] + acc[mt][nt][1] * arv[nt][1];
                rb += acc[mt][nt][2] * arv[nt][0] + acc[mt][nt][3] * arv[nt][1];
            }
#pragma unroll
            for (int o = 1; o < 4; o <<= 1) {
                ea += __shfl_down_sync(0xffffffffu, ea, o, 4);
                eb += __shfl_down_sync(0xffffffffu, eb, o, 4);
                ra += __shfl_down_sync(0xffffffffu, ra, o, 4);
                rb += __shfl_down_sync(0xffffffffu, rb, o, 4);
            }
            if (qid == 0) {
                int rr = wm0 + mt * 16 + grp;
                int hf = wn0 >> 5;
                sEl[hf][rr] = ea; sEl[hf][rr + 8] = eb;
                sEr[hf][rr] = ra; sEr[hf][rr + 8] = rb;
            }
        }
        __syncthreads();
        if (tid < 128) {
            int gr = row0 + tid;
            float elv = sEl[0][tid] + sEl[1][tid];
            if (gr < n) {
                g_el[gr * 4 + hd] = elv;
                g_er[gr * 4 + hd] = sEr[0][tid] + sEr[1][tid];
            } else {
                elv = NEG_INF;
            }
            // warp-reduce max, one atomic per warp (4 per CTA)
#pragma unroll
            for (int o = 16; o; o >>= 1)
                elv = fmaxf(elv, __shfl_xor_sync(0xffffffffu, elv, o));
            if (lane == 0) atomicMaxF(&gmax[hd], elv);
        }
    }
}

// ================= fused GAT attention + aggregation + combine =================
// Single edge pass: softmax shift = leaky(gmax + er) (>= true segment max).
__global__ void gat_fused(const float* __restrict__ z, const float* __restrict__ res,
                          const float* __restrict__ bias, float* __restrict__ xout,
                          int mode, uint32_t* __restrict__ xh2, uint32_t* __restrict__ xl2,
                          const float* __restrict__ gmax) {
    __shared__ float sm[8][256];
    const int wIB  = threadIdx.x >> 5;
    const int n    = (blockIdx.x * blockDim.x + threadIdx.x) >> 5;
    const int lane = threadIdx.x & 31;
    if (n >= NN) return;
    const int r0 = g_rowptr[n];
    const int nE = g_rowptr[n + 1] - r0;
    const float4 erv = *(const float4*)&g_er[n * 4];
    const int myK = lane >> 3;

    const float m0 = leaky02(gmax[0] + erv.x);
    const float m1 = leaky02(gmax[1] + erv.y);
    const float m2 = leaky02(gmax[2] + erv.z);
    const float m3 = leaky02(gmax[3] + erv.w);

    float acc[8] = {};
    float sl0 = 0.f, sl1 = 0.f, sl2 = 0.f, sl3 = 0.f;
    for (int b = 0; b < nE; b += 32) {
        int idx = b + lane;
        int cnt = min(32, nE - b);
        float p0 = 0.f, p1 = 0.f, p2 = 0.f, p3 = 0.f;
        int sN = 0;
        if (idx < nE) {
            sN = g_csrc[r0 + idx];
            float4 l = *(const float4*)&g_el[sN * 4];
            p0 = __expf(leaky02(l.x + erv.x) - m0);
            p1 = __expf(leaky02(l.y + erv.y) - m1);
            p2 = __expf(leaky02(l.z + erv.z) - m2);
            p3 = __expf(leaky02(l.w + erv.w) - m3);
            sl0 += p0; sl1 += p1; sl2 += p2; sl3 += p3;
        }
        int i = 0;
        for (; i + 4 <= cnt; i += 4) {
            int ss[4]; float pa[4];
#pragma unroll
            for (int j = 0; j < 4; j++) {
                ss[j] = __shfl_sync(0xffffffffu, sN, i + j);
                float q0 = __shfl_sync(0xffffffffu, p0, i + j);
                float q1 = __shfl_sync(0xffffffffu, p1, i + j);
                float q2 = __shfl_sync(0xffffffffu, p2, i + j);
                float q3 = __shfl_sync(0xffffffffu, p3, i + j);
                pa[j] = (myK == 0) ? q0 : (myK == 1) ? q1 : (myK == 2) ? q2 : q3;
            }
            float4 za[4], zb[4];
#pragma unroll
            for (int j = 0; j < 4; j++) {
                const float4* zr = (const float4*)(z + (size_t)ss[j] * KH + lane * 8);
                za[j] = zr[0]; zb[j] = zr[1];
            }
#pragma unroll
            for (int j = 0; j < 4; j++) {
                acc[0] += pa[j] * za[j].x; acc[1] += pa[j] * za[j].y;
                acc[2] += pa[j] * za[j].z; acc[3] += pa[j] * za[j].w;
                acc[4] += pa[j] * zb[j].x; acc[5] += pa[j] * zb[j].y;
                acc[6] += pa[j] * zb[j].z; acc[7] += pa[j] * zb[j].w;
            }
        }
        for (; i < cnt; i++) {
            int ss   = __shfl_sync(0xffffffffu, sN, i);
            float q0 = __shfl_sync(0xffffffffu, p0, i);
            float q1 = __shfl_sync(0xffffffffu, p1, i);
            float q2 = __shfl_sync(0xffffffffu, p2, i);
            float q3 = __shfl_sync(0xffffffffu, p3, i);
            float pa = (myK == 0) ? q0 : (myK == 1) ? q1 : (myK == 2) ? q2 : q3;
            const float4* zr = (const float4*)(z + (size_t)ss * KH + lane * 8);
            float4 za = zr[0], zb = zr[1];
            acc[0] += pa * za.x; acc[1] += pa * za.y;
            acc[2] += pa * za.z; acc[3] += pa * za.w;
            acc[4] += pa * zb.x; acc[5] += pa * zb.y;
            acc[6] += pa * zb.z; acc[7] += pa * zb.w;
        }
    }
#pragma unroll
    for (int off = 16; off; off >>= 1) {
        sl0 += __shfl_xor_sync(0xffffffffu, sl0, off);
        sl1 += __shfl_xor_sync(0xffffffffu, sl1, off);
        sl2 += __shfl_xor_sync(0xffffffffu, sl2, off);
        sl3 += __shfl_xor_sync(0xffffffffu, sl3, off);
    }
    float sk = (myK == 0) ? sl0 : (myK == 1) ? sl1 : (myK == 2) ? sl2 : sl3;
    float inv = (nE > 0) ? (1.0f / sk) : 0.0f;

    const int base = n * KH + lane * 8;
    float v[8];
    const float4* rp = (const float4*)(res + base);
    const float4* bp = (const float4*)(bias + lane * 8);
    float4 r4a = rp[0], r4b = rp[1], b4a = bp[0], b4b = bp[1];
    v[0] = acc[0] * inv + r4a.x + b4a.x; v[1] = acc[1] * inv + r4a.y + b4a.y;
    v[2] = acc[2] * inv + r4a.z + b4a.z; v[3] = acc[3] * inv + r4a.w + b4a.w;
    v[4] = acc[4] * inv + r4b.x + b4b.x; v[5] = acc[5] * inv + r4b.y + b4b.y;
    v[6] = acc[6] * inv + r4b.z + b4b.z; v[7] = acc[7] * inv + r4b.w + b4b.w;
#pragma unroll
    for (int j = 0; j < 8; j++) v[j] = v[j] > 0.f ? v[j] : 0.f;

    if (mode == 0) {
        float4* op = (float4*)(xout + base);
        op[0] = make_float4(v[0], v[1], v[2], v[3]);
        op[1] = make_float4(v[4], v[5], v[6], v[7]);
        uint32_t oh[4], ol[4];
        splitpack(v[0], v[1], oh[0], ol[0]);
        splitpack(v[2], v[3], oh[1], ol[1]);
        splitpack(v[4], v[5], oh[2], ol[2]);
        splitpack(v[6], v[7], oh[3], ol[3]);
        *(uint4*)&xh2[(size_t)n * 128 + lane * 4] = make_uint4(oh[0], oh[1], oh[2], oh[3]);
        *(uint4*)&xl2[(size_t)n * 128 + lane * 4] = make_uint4(ol[0], ol[1], ol[2], ol[3]);
    } else {
#pragma unroll
        for (int j = 0; j < 8; j++) sm[wIB][lane * 8 + j] = v[j];
        __syncwarp();
        float h0 = (sm[wIB][lane]       + sm[wIB][64 + lane] +
                    sm[wIB][128 + lane] + sm[wIB][192 + lane]) * 0.25f;
        float h1 = (sm[wIB][32 + lane]  + sm[wIB][96 + lane] +
                    sm[wIB][160 + lane] + sm[wIB][224 + lane]) * 0.25f;
        g_x3[n * 64 + lane]      = h0;
        g_x3[n * 64 + lane + 32] = h1;
    }
}

// ================= readout + MLP =================
__global__ void init_readout() {
    int i = blockIdx.x * blockDim.x + threadIdx.x;
    if (i < GG * HH) { g_gs[i] = 0.0f; g_gm[i] = NEG_INF; }
}
__global__ void readout(const int* __restrict__ gid, const float* __restrict__ Wg,
                        const float* __restrict__ bg) {
    int w    = (blockIdx.x * blockDim.x + threadIdx.x) >> 5;
    int lane = threadIdx.x & 31;
    if (w >= NN) return;
    int g = gid[w];
    const float* xr = g_x3 + (size_t)w * 64;
    float x0 = xr[lane], x1 = xr[lane + 32];
    float p = x0 * Wg[lane] + x1 * Wg[lane + 32];
#pragma unroll
    for (int off = 16; off; off >>= 1) p += __shfl_down_sync(0xffffffffu, p, off);
    p = __shfl_sync(0xffffffffu, p, 0);
    float wgt = 1.0f / (1.0f + expf(-(p + bg[0])));
    atomicAdd(&g_gs[g * 64 + lane],      wgt * x0);
    atomicAdd(&g_gs[g * 64 + lane + 32], wgt * x1);
    atomicMaxF(&g_gm[g * 64 + lane],      x0);
    atomicMaxF(&g_gm[g * 64 + lane + 32], x1);
}
__global__ void mlp_head(const float* __restrict__ Wm1, const float* __restrict__ bm1,
                         const float* __restrict__ bn_g, const float* __restrict__ bn_b,
                         const float* __restrict__ bn_m, const float* __restrict__ bn_v,
                         const float* __restrict__ Wm2, const float* __restrict__ bm2,
                         float* __restrict__ out) {
    int g = blockIdx.x, j = threadIdx.x;
    __shared__ float gf[128];
    gf[j]      = g_gs[g * 64 + j];
    gf[j + 64] = g_gm[g * 64 + j];
    __syncthreads();
    float acc = bm1[j];
#pragma unroll 8
    for (int i = 0; i < 128; i++) acc += gf[i] * Wm1[i * 64 + j];
    float y = acc > 0.0f ? acc : 0.0f;
    y = (y - bn_m[j]) * rsqrtf(bn_v[j] + 1e-5f) * bn_g[j] + bn_b[j];
    __shared__ float red[64];
    red[j] = y * Wm2[j];
    __syncthreads();
    if (j == 0) {
        float t = 0.0f;
#pragma unroll
        for (int i = 0; i < 64; i++) t += red[i];
        out[g] = 1.0f / (1.0f + expf(-(t + bm2[0])));
    }
}

// ================= host launcher =================
extern "C" void kernel_launch(void* const* d_in, const int* in_sizes, int n_in,
                              void* d_out, int out_size) {
    (void)in_sizes; (void)n_in; (void)out_size;
    const float* h     = (const float*)d_in[0];
    const int*   src   = (const int*)d_in[1];
    const int*   dst   = (const int*)d_in[2];
    const int*   gid   = (const int*)d_in[3];
    const float* W0    = (const float*)d_in[4];
    const float* al0   = (const float*)d_in[5];
    const float* ar0   = (const float*)d_in[6];
    const float* b0    = (const float*)d_in[7];
    const float* resW0 = (const float*)d_in[8];
    const float* W1    = (const float*)d_in[9];
    const float* al1   = (const float*)d_in[10];
    const float* ar1   = (const float*)d_in[11];
    const float* b1    = (const float*)d_in[12];
    const float* W2    = (const float*)d_in[13];
    const float* al2   = (const float*)d_in[14];
    const float* ar2   = (const float*)d_in[15];
    const float* b2    = (const float*)d_in[16];
    const float* Wg    = (const float*)d_in[17];
    const float* bg    = (const float*)d_in[18];
    const float* Wm1   = (const float*)d_in[19];
    const float* bm1   = (const float*)d_in[20];
    const float* bng   = (const float*)d_in[21];
    const float* bnb   = (const float*)d_in[22];
    const float* bnm   = (const float*)d_in[23];
    const float* bnv   = (const float*)d_in[24];
    const float* Wm2   = (const float*)d_in[25];
    const float* bm2   = (const float*)d_in[26];

    float *p_z, *p_res, *p_x, *p_gmax;
    uint32_t *p_hh2, *p_hl2, *p_xh2, *p_xl2, *p_wh, *p_wl;
    cudaGetSymbolAddress((void**)&p_z,    g_z);
    cudaGetSymbolAddress((void**)&p_res,  g_res);
    cudaGetSymbolAddress((void**)&p_x,    g_x);
    cudaGetSymbolAddress((void**)&p_gmax, g_gmax);
    cudaGetSymbolAddress((void**)&p_hh2,  g_hh2);
    cudaGetSymbolAddress((void**)&p_hl2,  g_hl2);
    cudaGetSymbolAddress((void**)&p_xh2,  g_xh2);
    cudaGetSymbolAddress((void**)&p_xl2,  g_xl2);
    cudaGetSymbolAddress((void**)&p_wh,   g_wh);
    cudaGetSymbolAddress((void**)&p_wl,   g_wl);

    const int SMEM_GEMM = 61440;
    cudaFuncSetAttribute(gemm_h3, cudaFuncAttributeMaxDynamicSharedMemorySize, SMEM_GEMM);

    dim3 gemmGrid(KH / 64, (NN + 127) / 128);
    const int edgeB  = (EE + 255) / 256;
    const int nWarpB = (NN + 7) / 8;

    // ---- pre-splits + layer-0 GEMMs (GEMM at launch indices 3-4 for ncu) ----
    hsplit<<<(NN * 64 + 255) / 256, 256>>>(h);
    wsplit<<<(256 * 64 + 255) / 256, 256>>>(W0, 0, FF);
    wsplit<<<(256 * 64 + 255) / 256, 256>>>(resW0, 16384, FF);
    gemm_h3<<<gemmGrid, 256, SMEM_GEMM>>>(p_hh2, p_hl2, p_wh, p_wl, p_z, NN, FF,
                                          al0, ar0, p_gmax);
    gemm_h3<<<gemmGrid, 256, SMEM_GEMM>>>(p_hh2, p_hl2, p_wh + 16384, p_wl + 16384, p_res,
                                          NN, FF, nullptr, nullptr, nullptr);
    wsplit<<<(256 * 128 + 255) / 256, 256>>>(W1, 32768, KH);
    wsplit<<<(256 * 128 + 255) / 256, 256>>>(W2, 65536, KH);

    // ---- CSR build ----
    csr_zero<<<(NN + 255) / 256, 256>>>();
    csr_hist<<<edgeB, 256>>>(dst);
    csr_scan<<<1, 1024>>>();
    csr_fill_k<<<edgeB, 256>>>(src, dst);

    // ---- Layer 0 combine ----
    gat_fused<<<nWarpB, 256>>>(p_z, p_res, b0, p_x, 0, p_xh2, p_xl2, p_gmax);

    // ---- Layer 1 ----
    gemm_h3<<<gemmGrid, 256, SMEM_GEMM>>>(p_xh2, p_xl2, p_wh + 32768, p_wl + 32768, p_z,
                                          NN, KH, al1, ar1, p_gmax + 4);
    gat_fused<<<nWarpB, 256>>>(p_z, p_x, b1, p_x, 0, p_xh2, p_xl2, p_gmax + 4);

    // ---- Layer 2 ----
    gemm_h3<<<gemmGrid, 256, SMEM_GEMM>>>(p_xh2, p_xl2, p_wh + 65536, p_wl + 65536, p_z,
                                          NN, KH, al2, ar2, p_gmax + 8);
    gat_fused<<<nWarpB, 256>>>(p_z, p_x, b2, nullptr, 1, nullptr, nullptr, p_gmax + 8);

    // ---- Readout + MLP ----
    init_readout<<<(GG * HH + 255) / 256, 256>>>();
    readout<<<nWarpB, 256>>>(gid, Wg, bg);
    mlp_head<<<GG, 64>>>(Wm1, bm1, bng, bnb, bnm, bnv, Wm2, bm2, (float*)d_out);
}

// round 10
// speedup vs baseline: 1.0574x; 1.0574x over previous
#include <cuda_runtime.h>
#include <cuda_fp16.h>
#include <math.h>
#include <stdint.h>

#define NN 50000
#define EE 400000
#define GG 512
#define FF 128
#define KK 4
#define HH 64
#define KH 256   // K*H
#define NEG_INF __int_as_float(0xff800000)

// ---------------- device scratch (static, no runtime allocation) ----------------
__device__ float g_z[NN * KH];
__device__ float g_res[NN * KH];
__device__ float g_x[NN * KH];
__device__ float g_el[NN * KK];
__device__ float g_er[NN * KK];
__device__ float g_x3[NN * HH];
__device__ float g_gs[GG * HH];
__device__ float g_gm[GG * HH];
// fp16-split operand storage (half2 packed along K); lo is UNSCALED (x - fp16(x))
__device__ uint32_t g_hh2[NN * 64];
__device__ uint32_t g_hl2[NN * 64];
__device__ uint32_t g_xh2[NN * 128];
__device__ uint32_t g_xl2[NN * 128];
__device__ uint32_t g_wh[98304];   // [n=256][din/2]: W0@0, resW0@16384, W1@32768, W2@65536
__device__ uint32_t g_wl[98304];
// CSR
__device__ int g_rowptr[NN + 1];
__device__ int g_cnt[NN];
__device__ int g_fill[NN];
__device__ int g_csrc[EE];

__device__ __forceinline__ void atomicMaxF(float* addr, float v) {
    if (v >= 0.0f) atomicMax((int*)addr, __float_as_int(v));
    else           atomicMin((unsigned int*)addr, __float_as_uint(v));
}
__device__ __forceinline__ float leaky02(float v) { return v > 0.0f ? v : 0.2f * v; }

// split x into fp16 hi + fp16 lo (UNSCALED residual), packed as half2
__device__ __forceinline__ void splitpack(float a, float b, uint32_t& hi, uint32_t& lo) {
    __half ha = __float2half_rn(a), hb = __float2half_rn(b);
    __half2 hh = __halves2half2(ha, hb);
    hi = *(uint32_t*)&hh;
    float la = a - __half2float(ha);
    float lb = b - __half2float(hb);
    __half2 hl = __floats2half2_rn(la, lb);
    lo = *(uint32_t*)&hl;
}

// ================= async-copy / ldmatrix helpers =================
__device__ __forceinline__ uint32_t s2u(const void* p) {
    return (uint32_t)__cvta_generic_to_shared(p);
}
__device__ __forceinline__ void cpasync16(uint32_t dst, const void* src, uint32_t sz) {
    asm volatile("cp.async.cg.shared.global [%0], [%1], 16, %2;"
                 :: "r"(dst), "l"(src), "r"(sz) : "memory");
}
__device__ __forceinline__ void cpcommit() {
    asm volatile("cp.async.commit_group;" ::: "memory");
}
template <int N>
__device__ __forceinline__ void cpwait() {
    asm volatile("cp.async.wait_group %0;" :: "n"(N) : "memory");
}
#define LDSM4(r, a) \
    asm volatile("ldmatrix.sync.aligned.m8n8.x4.shared.b16 {%0,%1,%2,%3}, [%4];" \
                 : "=r"((r)[0]), "=r"((r)[1]), "=r"((r)[2]), "=r"((r)[3]) : "r"(a))
#define MMA_F16(d, a, b0, b1) \
    asm volatile("mma.sync.aligned.m16n8k16.row.col.f32.f16.f16.f32 " \
                 "{%0,%1,%2,%3}, {%4,%5,%6,%7}, {%8,%9}, {%0,%1,%2,%3};" \
                 : "+f"((d)[0]), "+f"((d)[1]), "+f"((d)[2]), "+f"((d)[3]) \
                 : "r"((a)[0]), "r"((a)[1]), "r"((a)[2]), "r"((a)[3]), \
                   "r"(b0), "r"(b1))

// ================= operand pre-split kernels =================
__global__ void hsplit(const float* __restrict__ h) {
    int idx = blockIdx.x * blockDim.x + threadIdx.x;
    if (idx >= NN * 64) return;
    int row = idx >> 6, k2 = idx & 63;
    float2 v = *(const float2*)&h[row * 128 + k2 * 2];
    splitpack(v.x, v.y, g_hh2[idx], g_hl2[idx]);
}
__global__ void wsplit(const float* __restrict__ W, int off, int din) {
    int idx = blockIdx.x * blockDim.x + threadIdx.x;
    int dh = din >> 1;
    if (idx >= 256 * dh) return;
    int nn = idx & 255, k2 = idx >> 8;
    float v0 = W[(2 * k2) * 256 + nn];
    float v1 = W[(2 * k2 + 1) * 256 + nn];
    splitpack(v0, v1, g_wh[off + nn * dh + k2], g_wl[off + nn * dh + k2]);
}

// ================= CSR build =================
__global__ void csr_zero() {
    int i = blockIdx.x * blockDim.x + threadIdx.x;
    if (i < NN) { g_cnt[i] = 0; g_fill[i] = 0; }
}
__global__ void csr_hist(const int* __restrict__ dst) {
    int e = blockIdx.x * blockDim.x + threadIdx.x;
    if (e < EE) atomicAdd(&g_cnt[dst[e]], 1);
}
__global__ void csr_scan() {
    __shared__ int smW[32];
    __shared__ int sOff;
    int tid = threadIdx.x, lane = tid & 31, wid = tid >> 5;
    if (tid == 0) sOff = 0;
    __syncthreads();
    for (int base = 0; base < NN; base += 1024) {
        int i = base + tid;
        int v = (i < NN) ? g_cnt[i] : 0;
        int inc = v;
#pragma unroll
        for (int o = 1; o < 32; o <<= 1) {
            int t = __shfl_up_sync(0xffffffffu, inc, o);
            if (lane >= o) inc += t;
        }
        if (lane == 31) smW[wid] = inc;
        __syncthreads();
        if (wid == 0) {
            int t = smW[lane];
#pragma unroll
            for (int o = 1; o < 32; o <<= 1) {
                int u = __shfl_up_sync(0xffffffffu, t, o);
                if (lane >= o) t += u;
            }
            smW[lane] = t;
        }
        __syncthreads();
        int warpOff = wid ? smW[wid - 1] : 0;
        if (i < NN) g_rowptr[i] = sOff + warpOff + inc - v;
        int blockTot = smW[31];
        __syncthreads();
        if (tid == 0) sOff += blockTot;
        __syncthreads();
    }
    if (tid == 0) g_rowptr[NN] = sOff;
}
__global__ void csr_fill_k(const int* __restrict__ src, const int* __restrict__ dst) {
    int e = blockIdx.x * blockDim.x + threadIdx.x;
    if (e >= EE) return;
    int d = dst[e];
    int pos = g_rowptr[d] + atomicAdd(&g_fill[d], 1);
    g_csrc[pos] = src[e];
}

// ================= fp16-split GEMM, 128x128 tile =================
// C[n x 256] = A[n x din] @ B[din x 256], operands pre-split hi + lo(unscaled).
// Block tile 128x128, BK=32, 256 threads (8 warps 4x2), warp tile 32x64.
// smem (dynamic, 81920B): Ah[2][128][20]@0, Al@20480(+buf*10240),
//                         Bh[2][128][20]@40960, Bl@61440(+buf*10240)
__global__ void __launch_bounds__(256, 2) gemm_h4(
        const uint32_t* __restrict__ Ah2, const uint32_t* __restrict__ Al2,
        const uint32_t* __restrict__ Bh2, const uint32_t* __restrict__ Bl2,
        float* __restrict__ C, int n, int din,
        const float* __restrict__ alp, const float* __restrict__ arp) {
    extern __shared__ __align__(16) uint8_t smx[];
    __shared__ float sEl[2][128], sEr[2][128];
    const int tid  = threadIdx.x;
    const int wid  = tid >> 5;
    const int lane = tid & 31;
    const int row0 = blockIdx.y * 128;
    const int col0 = blockIdx.x * 128;
    const int wm0  = (wid >> 1) * 32;       // 4 m-warps
    const int wn0  = (wid & 1) * 64;        // 2 n-warps
    const int grp  = lane >> 2;
    const int qid  = lane & 3;
    const int dh   = din >> 1;
    const int ntiles = dh >> 4;             // k32 tiles

    const uint32_t uA = s2u(smx);
    const uint32_t uB = uA + 40960;

    float acc[2][8][4] = {};

    const int arow = tid >> 1;              // 0..127
    const int ach  = (tid & 1) * 8;         // 0 or 8

    auto load_tile = [&](int buf, int tile) {
        const int kof = tile * 16;
        {
            int gr = row0 + arow;
            uint32_t sz = (gr < n) ? 16u : 0u;
            size_t off = (gr < n) ? ((size_t)gr * dh + kof + ach) : 0;
            uint32_t d = uA + buf * 10240 + (arow * 20 + ach) * 4;
            cpasync16(d,              Ah2 + off,     sz);
            cpasync16(d + 16,         Ah2 + off + 4, sz);
            cpasync16(d + 20480,      Al2 + off,     sz);
            cpasync16(d + 20480 + 16, Al2 + off + 4, sz);
        }
        {
            size_t off = (size_t)(col0 + arow) * dh + kof + ach;
            uint32_t d = uB + buf * 10240 + (arow * 20 + ach) * 4;
            cpasync16(d,              Bh2 + off,     16u);
            cpasync16(d + 16,         Bh2 + off + 4, 16u);
            cpasync16(d + 20480,      Bl2 + off,     16u);
            cpasync16(d + 20480 + 16, Bl2 + off + 4, 16u);
        }
        cpcommit();
    };

    load_tile(0, 0);
    for (int ti = 0; ti < ntiles; ti++) {
        if (ti + 1 < ntiles) { load_tile((ti + 1) & 1, ti + 1); cpwait<1>(); }
        else cpwait<0>();
        __syncthreads();
        const int buf = ti & 1;
        const uint32_t aB = uA + buf * 10240;
        const uint32_t bB = uB + buf * 10240;
#pragma unroll
        for (int ks = 0; ks < 2; ks++) {
            const int kb2 = ks * 8;
            uint32_t afh[2][4], afl[2][4];
#pragma unroll
            for (int mt = 0; mt < 2; mt++) {
                uint32_t ad = aB + (((wm0 + mt * 16 + (lane & 15)) * 20 + kb2 +
                                     ((lane >> 4) << 2)) << 2);
                LDSM4(afh[mt], ad);
                LDSM4(afl[mt], ad + 20480);
            }
#pragma unroll
            for (int ntp = 0; ntp < 4; ntp++) {
                int nrow = wn0 + ntp * 16 + (lane & 7) + ((lane >> 4) << 3);
                int koff = kb2 + (((lane >> 3) & 1) << 2);
                uint32_t bd = bB + ((nrow * 20 + koff) << 2);
                uint32_t bh4[4], bl4[4];
                LDSM4(bh4, bd);
                LDSM4(bl4, bd + 20480);
#pragma unroll
                for (int mt = 0; mt < 2; mt++)
#pragma unroll
                    for (int nb = 0; nb < 2; nb++) {
                        float* d = acc[mt][ntp * 2 + nb];
                        MMA_F16(d, afh[mt], bh4[nb * 2], bh4[nb * 2 + 1]);
                        MMA_F16(d, afh[mt], bl4[nb * 2], bl4[nb * 2 + 1]);
                        MMA_F16(d, afl[mt], bh4[nb * 2], bh4[nb * 2 + 1]);
                    }
            }
        }
        __syncthreads();
    }

    // ---- store C ----
#pragma unroll
    for (int mt = 0; mt < 2; mt++) {
#pragma unroll
        for (int nt = 0; nt < 8; nt++) {
            int r  = row0 + wm0 + mt * 16 + grp;
            int cC = col0 + wn0 + nt * 8 + qid * 2;
            if (r < n)
                *(float2*)&C[(size_t)r * KH + cC] = make_float2(acc[mt][nt][0], acc[mt][nt][1]);
            if (r + 8 < n)
                *(float2*)&C[(size_t)(r + 8) * KH + cC] = make_float2(acc[mt][nt][2], acc[mt][nt][3]);
        }
    }
    // ---- fused attention projections: each warp's 64 cols = one full head ----
    if (alp != nullptr) {
        const int hf = wn0 >> 6;                 // 0 or 1
        const int hd = blockIdx.x * 2 + hf;      // global head
        float alv[8][2], arv[8][2];
#pragma unroll
        for (int nt = 0; nt < 8; nt++)
#pragma unroll
            for (int j = 0; j < 2; j++) {
                int c = nt * 8 + qid * 2 + j;    // col within head
                alv[nt][j] = alp[hd * 64 + c];
                arv[nt][j] = arp[hd * 64 + c];
            }
#pragma unroll
        for (int mt = 0; mt < 2; mt++) {
            float ea = 0.f, eb = 0.f, ra = 0.f, rb = 0.f;
#pragma unroll
            for (int nt = 0; nt < 8; nt++) {
                ea += acc[mt][nt][0] * alv[nt][0] + acc[mt][nt][1] * alv[nt][1];
                eb += acc[mt][nt][2] * alv[nt][0] + acc[mt][nt][3] * alv[nt][1];
                ra += acc[mt][nt][0] * arv[nt][0] + acc[mt][nt][1] * arv[nt][1];
                rb += acc[mt][nt][2] * arv[nt][0] + acc[mt][nt][3] * arv[nt][1];
            }
#pragma unroll
            for (int o = 1; o < 4; o <<= 1) {
                ea += __shfl_down_sync(0xffffffffu, ea, o, 4);
                eb += __shfl_down_sync(0xffffffffu, eb, o, 4);
                ra += __shfl_down_sync(0xffffffffu, ra, o, 4);
                rb += __shfl_down_sync(0xffffffffu, rb, o, 4);
            }
            if (qid == 0) {
                int rr = wm0 + mt * 16 + grp;
                sEl[hf][rr] = ea; sEl[hf][rr + 8] = eb;
                sEr[hf][rr] = ra; sEr[hf][rr + 8] = rb;
            }
        }
        __syncthreads();
        if (tid < 128) {
            int gr = row0 + tid;
            if (gr < n) {
                int hb = blockIdx.x * 2;
                g_el[gr * 4 + hb]     = sEl[0][tid];
                g_el[gr * 4 + hb + 1] = sEl[1][tid];
                g_er[gr * 4 + hb]     = sEr[0][tid];
                g_er[gr * 4 + hb + 1] = sEr[1][tid];
            }
        }
    }
}

// ================= fused GAT attention + aggregation + combine (two-pass) ======
__global__ void gat_fused(const float* __restrict__ z, const float* __restrict__ res,
                          const float* __restrict__ bias, float* __restrict__ xout,
                          int mode, uint32_t* __restrict__ xh2, uint32_t* __restrict__ xl2) {
    __shared__ float sm[8][256];
    const int wIB  = threadIdx.x >> 5;
    const int n    = (blockIdx.x * blockDim.x + threadIdx.x) >> 5;
    const int lane = threadIdx.x & 31;
    if (n >= NN) return;
    const int r0 = g_rowptr[n];
    const int nE = g_rowptr[n + 1] - r0;
    const float4 erv = *(const float4*)&g_er[n * 4];
    const int myK = lane >> 3;

    float m0 = NEG_INF, m1 = NEG_INF, m2 = NEG_INF, m3 = NEG_INF;
    for (int b = 0; b < nE; b += 32) {
        int idx = b + lane;
        if (idx < nE) {
            int s = g_csrc[r0 + idx];
            float4 l = *(const float4*)&g_el[s * 4];
            m0 = fmaxf(m0, leaky02(l.x + erv.x));
            m1 = fmaxf(m1, leaky02(l.y + erv.y));
            m2 = fmaxf(m2, leaky02(l.z + erv.z));
            m3 = fmaxf(m3, leaky02(l.w + erv.w));
        }
    }
#pragma unroll
    for (int off = 16; off; off >>= 1) {
        m0 = fmaxf(m0, __shfl_xor_sync(0xffffffffu, m0, off));
        m1 = fmaxf(m1, __shfl_xor_sync(0xffffffffu, m1, off));
        m2 = fmaxf(m2, __shfl_xor_sync(0xffffffffu, m2, off));
        m3 = fmaxf(m3, __shfl_xor_sync(0xffffffffu, m3, off));
    }

    float acc[8] = {};
    float sl0 = 0.f, sl1 = 0.f, sl2 = 0.f, sl3 = 0.f;
    for (int b = 0; b < nE; b += 32) {
        int idx = b + lane;
        int cnt = min(32, nE - b);
        float p0 = 0.f, p1 = 0.f, p2 = 0.f, p3 = 0.f;
        int sN = 0;
        if (idx < nE) {
            sN = g_csrc[r0 + idx];
            float4 l = *(const float4*)&g_el[sN * 4];
            p0 = __expf(leaky02(l.x + erv.x) - m0);
            p1 = __expf(leaky02(l.y + erv.y) - m1);
            p2 = __expf(leaky02(l.z + erv.z) - m2);
            p3 = __expf(leaky02(l.w + erv.w) - m3);
            sl0 += p0; sl1 += p1; sl2 += p2; sl3 += p3;
        }
        int i = 0;
        for (; i + 4 <= cnt; i += 4) {
            int ss[4]; float pa[4];
#pragma unroll
            for (int j = 0; j < 4; j++) {
                ss[j] = __shfl_sync(0xffffffffu, sN, i + j);
                float q0 = __shfl_sync(0xffffffffu, p0, i + j);
                float q1 = __shfl_sync(0xffffffffu, p1, i + j);
                float q2 = __shfl_sync(0xffffffffu, p2, i + j);
                float q3 = __shfl_sync(0xffffffffu, p3, i + j);
                pa[j] = (myK == 0) ? q0 : (myK == 1) ? q1 : (myK == 2) ? q2 : q3;
            }
            float4 za[4], zb[4];
#pragma unroll
            for (int j = 0; j < 4; j++) {
                const float4* zr = (const float4*)(z + (size_t)ss[j] * KH + lane * 8);
                za[j] = zr[0]; zb[j] = zr[1];
            }
#pragma unroll
            for (int j = 0; j < 4; j++) {
                acc[0] += pa[j] * za[j].x; acc[1] += pa[j] * za[j].y;
                acc[2] += pa[j] * za[j].z; acc[3] += pa[j] * za[j].w;
                acc[4] += pa[j] * zb[j].x; acc[5] += pa[j] * zb[j].y;
                acc[6] += pa[j] * zb[j].z; acc[7] += pa[j] * zb[j].w;
            }
        }
        for (; i < cnt; i++) {
            int ss   = __shfl_sync(0xffffffffu, sN, i);
            float q0 = __shfl_sync(0xffffffffu, p0, i);
            float q1 = __shfl_sync(0xffffffffu, p1, i);
            float q2 = __shfl_sync(0xffffffffu, p2, i);
            float q3 = __shfl_sync(0xffffffffu, p3, i);
            float pa = (myK == 0) ? q0 : (myK == 1) ? q1 : (myK == 2) ? q2 : q3;
            const float4* zr = (const float4*)(z + (size_t)ss * KH + lane * 8);
            float4 za = zr[0], zb = zr[1];
            acc[0] += pa * za.x; acc[1] += pa * za.y;
            acc[2] += pa * za.z; acc[3] += pa * za.w;
            acc[4] += pa * zb.x; acc[5] += pa * zb.y;
            acc[6] += pa * zb.z; acc[7] += pa * zb.w;
        }
    }
#pragma unroll
    for (int off = 16; off; off >>= 1) {
        sl0 += __shfl_xor_sync(0xffffffffu, sl0, off);
        sl1 += __shfl_xor_sync(0xffffffffu, sl1, off);
        sl2 += __shfl_xor_sync(0xffffffffu, sl2, off);
        sl3 += __shfl_xor_sync(0xffffffffu, sl3, off);
    }
    float sk = (myK == 0) ? sl0 : (myK == 1) ? sl1 : (myK == 2) ? sl2 : sl3;
    float inv = (nE > 0) ? (1.0f / sk) : 0.0f;

    const int base = n * KH + lane * 8;
    float v[8];
    const float4* rp = (const float4*)(res + base);
    const float4* bp = (const float4*)(bias + lane * 8);
    float4 r4a = rp[0], r4b = rp[1], b4a = bp[0], b4b = bp[1];
    v[0] = acc[0] * inv + r4a.x + b4a.x; v[1] = acc[1] * inv + r4a.y + b4a.y;
    v[2] = acc[2] * inv + r4a.z + b4a.z; v[3] = acc[3] * inv + r4a.w + b4a.w;
    v[4] = acc[4] * inv + r4b.x + b4b.x; v[5] = acc[5] * inv + r4b.y + b4b.y;
    v[6] = acc[6] * inv + r4b.z + b4b.z; v[7] = acc[7] * inv + r4b.w + b4b.w;
#pragma unroll
    for (int j = 0; j < 8; j++) v[j] = v[j] > 0.f ? v[j] : 0.f;

    if (mode == 0) {
        float4* op = (float4*)(xout + base);
        op[0] = make_float4(v[0], v[1], v[2], v[3]);
        op[1] = make_float4(v[4], v[5], v[6], v[7]);
        uint32_t oh[4], ol[4];
        splitpack(v[0], v[1], oh[0], ol[0]);
        splitpack(v[2], v[3], oh[1], ol[1]);
        splitpack(v[4], v[5], oh[2], ol[2]);
        splitpack(v[6], v[7], oh[3], ol[3]);
        *(uint4*)&xh2[(size_t)n * 128 + lane * 4] = make_uint4(oh[0], oh[1], oh[2], oh[3]);
        *(uint4*)&xl2[(size_t)n * 128 + lane * 4] = make_uint4(ol[0], ol[1], ol[2], ol[3]);
    } else {
#pragma unroll
        for (int j = 0; j < 8; j++) sm[wIB][lane * 8 + j] = v[j];
        __syncwarp();
        float h0 = (sm[wIB][lane]       + sm[wIB][64 + lane] +
                    sm[wIB][128 + lane] + sm[wIB][192 + lane]) * 0.25f;
        float h1 = (sm[wIB][32 + lane]  + sm[wIB][96 + lane] +
                    sm[wIB][160 + lane] + sm[wIB][224 + lane]) * 0.25f;
        g_x3[n * 64 + lane]      = h0;
        g_x3[n * 64 + lane + 32] = h1;
    }
}

// ================= readout + MLP =================
__global__ void init_readout() {
    int i = blockIdx.x * blockDim.x + threadIdx.x;
    if (i < GG * HH) { g_gs[i] = 0.0f; g_gm[i] = NEG_INF; }
}
__global__ void readout(const int* __restrict__ gid, const float* __restrict__ Wg,
                        const float* __restrict__ bg) {
    int w    = (blockIdx.x * blockDim.x + threadIdx.x) >> 5;
    int lane = threadIdx.x & 31;
    if (w >= NN) return;
    int g = gid[w];
    const float* xr = g_x3 + (size_t)w * 64;
    float x0 = xr[lane], x1 = xr[lane + 32];
    float p = x0 * Wg[lane] + x1 * Wg[lane + 32];
#pragma unroll
    for (int off = 16; off; off >>= 1) p += __shfl_down_sync(0xffffffffu, p, off);
    p = __shfl_sync(0xffffffffu, p, 0);
    float wgt = 1.0f / (1.0f + expf(-(p + bg[0])));
    atomicAdd(&g_gs[g * 64 + lane],      wgt * x0);
    atomicAdd(&g_gs[g * 64 + lane + 32], wgt * x1);
    atomicMaxF(&g_gm[g * 64 + lane],      x0);
    atomicMaxF(&g_gm[g * 64 + lane + 32], x1);
}
__global__ void mlp_head(const float* __restrict__ Wm1, const float* __restrict__ bm1,
                         const float* __restrict__ bn_g, const float* __restrict__ bn_b,
                         const float* __restrict__ bn_m, const float* __restrict__ bn_v,
                         const float* __restrict__ Wm2, const float* __restrict__ bm2,
                         float* __restrict__ out) {
    int g = blockIdx.x, j = threadIdx.x;
    __shared__ float gf[128];
    gf[j]      = g_gs[g * 64 + j];
    gf[j + 64] = g_gm[g * 64 + j];
    __syncthreads();
    float acc = bm1[j];
#pragma unroll 8
    for (int i = 0; i < 128; i++) acc += gf[i] * Wm1[i * 64 + j];
    float y = acc > 0.0f ? acc : 0.0f;
    y = (y - bn_m[j]) * rsqrtf(bn_v[j] + 1e-5f) * bn_g[j] + bn_b[j];
    __shared__ float red[64];
    red[j] = y * Wm2[j];
    __syncthreads();
    if (j == 0) {
        float t = 0.0f;
#pragma unroll
        for (int i = 0; i < 64; i++) t += red[i];
        out[g] = 1.0f / (1.0f + expf(-(t + bm2[0])));
    }
}

// ================= host launcher =================
extern "C" void kernel_launch(void* const* d_in, const int* in_sizes, int n_in,
                              void* d_out, int out_size) {
    (void)in_sizes; (void)n_in; (void)out_size;
    const float* h     = (const float*)d_in[0];
    const int*   src   = (const int*)d_in[1];
    const int*   dst   = (const int*)d_in[2];
    const int*   gid   = (const int*)d_in[3];
    const float* W0    = (const float*)d_in[4];
    const float* al0   = (const float*)d_in[5];
    const float* ar0   = (const float*)d_in[6];
    const float* b0    = (const float*)d_in[7];
    const float* resW0 = (const float*)d_in[8];
    const float* W1    = (const float*)d_in[9];
    const float* al1   = (const float*)d_in[10];
    const float* ar1   = (const float*)d_in[11];
    const float* b1    = (const float*)d_in[12];
    const float* W2    = (const float*)d_in[13];
    const float* al2   = (const float*)d_in[14];
    const float* ar2   = (const float*)d_in[15];
    const float* b2    = (const float*)d_in[16];
    const float* Wg    = (const float*)d_in[17];
    const float* bg    = (const float*)d_in[18];
    const float* Wm1   = (const float*)d_in[19];
    const float* bm1   = (const float*)d_in[20];
    const float* bng   = (const float*)d_in[21];
    const float* bnb   = (const float*)d_in[22];
    const float* bnm   = (const float*)d_in[23];
    const float* bnv   = (const float*)d_in[24];
    const float* Wm2   = (const float*)d_in[25];
    const float* bm2   = (const float*)d_in[26];

    float *p_z, *p_res, *p_x;
    uint32_t *p_hh2, *p_hl2, *p_xh2, *p_xl2, *p_wh, *p_wl;
    cudaGetSymbolAddress((void**)&p_z,   g_z);
    cudaGetSymbolAddress((void**)&p_res, g_res);
    cudaGetSymbolAddress((void**)&p_x,   g_x);
    cudaGetSymbolAddress((void**)&p_hh2, g_hh2);
    cudaGetSymbolAddress((void**)&p_hl2, g_hl2);
    cudaGetSymbolAddress((void**)&p_xh2, g_xh2);
    cudaGetSymbolAddress((void**)&p_xl2, g_xl2);
    cudaGetSymbolAddress((void**)&p_wh,  g_wh);
    cudaGetSymbolAddress((void**)&p_wl,  g_wl);

    const int SMEM_GEMM = 81920;
    cudaFuncSetAttribute(gemm_h4, cudaFuncAttributeMaxDynamicSharedMemorySize, SMEM_GEMM);

    dim3 gemmGrid(KH / 128, (NN + 127) / 128);   // (2, 391)
    const int edgeB  = (EE + 255) / 256;
    const int nWarpB = (NN + 7) / 8;

    // ---- pre-splits + layer-0 GEMMs (GEMM at launch indices 3-4 for ncu) ----
    hsplit<<<(NN * 64 + 255) / 256, 256>>>(h);
    wsplit<<<(256 * 64 + 255) / 256, 256>>>(W0, 0, FF);
    wsplit<<<(256 * 64 + 255) / 256, 256>>>(resW0, 16384, FF);
    gemm_h4<<<gemmGrid, 256, SMEM_GEMM>>>(p_hh2, p_hl2, p_wh, p_wl, p_z, NN, FF, al0, ar0);
    gemm_h4<<<gemmGrid, 256, SMEM_GEMM>>>(p_hh2, p_hl2, p_wh + 16384, p_wl + 16384, p_res,
                                          NN, FF, nullptr, nullptr);
    wsplit<<<(256 * 128 + 255) / 256, 256>>>(W1, 32768, KH);
    wsplit<<<(256 * 128 + 255) / 256, 256>>>(W2, 65536, KH);

    // ---- CSR build ----
    csr_zero<<<(NN + 255) / 256, 256>>>();
    csr_hist<<<edgeB, 256>>>(dst);
    csr_scan<<<1, 1024>>>();
    csr_fill_k<<<edgeB, 256>>>(src, dst);

    // ---- Layer 0 combine ----
    gat_fused<<<nWarpB, 256>>>(p_z, p_res, b0, p_x, 0, p_xh2, p_xl2);

    // ---- Layer 1 ----
    gemm_h4<<<gemmGrid, 256, SMEM_GEMM>>>(p_xh2, p_xl2, p_wh + 32768, p_wl + 32768, p_z,
                                          NN, KH, al1, ar1);
    gat_fused<<<nWarpB, 256>>>(p_z, p_x, b1, p_x, 0, p_xh2, p_xl2);

    // ---- Layer 2 ----
    gemm_h4<<<gemmGrid, 256, SMEM_GEMM>>>(p_xh2, p_xl2, p_wh + 65536, p_wl + 65536, p_z,
                                          NN, KH, al2, ar2);
    gat_fused<<<nWarpB, 256>>>(p_z, p_x, b2, nullptr, 1, nullptr, nullptr);

    // ---- Readout + MLP ----
    init_readout<<<(GG * HH + 255) / 256, 256>>>();
    readout<<<nWarpB, 256>>>(gid, Wg, bg);
    mlp_head<<<GG, 64>>>(Wm1, bm1, bng, bnb, bnm, bnv, Wm2, bm2, (float*)d_out);
}

// round 11
// speedup vs baseline: 1.1217x; 1.0608x over previous
#include <cuda_runtime.h>
#include <cuda_fp16.h>
#include <math.h>
#include <stdint.h>

#define NN 50000
#define EE 400000
#define GG 512
#define FF 128
#define KK 4
#define HH 64
#define KH 256   // K*H
#define NEG_INF __int_as_float(0xff800000)

// ---------------- device scratch (static, no runtime allocation) ----------------
__device__ float g_z[NN * KH];
__device__ float g_res[NN * KH];
__device__ float g_x[NN * KH];
__device__ float g_el[NN * KK];
__device__ float g_er[NN * KK];
__device__ float g_x3[NN * HH];
__device__ float g_gs[GG * HH];
__device__ float g_gm[GG * HH];
// fp16-split operand storage (half2 packed along K); lo is UNSCALED (x - fp16(x))
__device__ uint32_t g_hh2[NN * 64];
__device__ uint32_t g_hl2[NN * 64];
__device__ uint32_t g_xh2[NN * 128];
__device__ uint32_t g_xl2[NN * 128];
__device__ uint32_t g_wh[98304];   // [n][din/2]: W0 rows 0-255 @0, resW0 rows 256-511 @16384, W1@32768, W2@65536
__device__ uint32_t g_wl[98304];
// CSR
__device__ int g_rowptr[NN + 1];
__device__ int g_cnt[NN];
__device__ int g_fill[NN];
__device__ int g_csrc[EE];

__device__ __forceinline__ void atomicMaxF(float* addr, float v) {
    if (v >= 0.0f) atomicMax((int*)addr, __float_as_int(v));
    else           atomicMin((unsigned int*)addr, __float_as_uint(v));
}
__device__ __forceinline__ float leaky02(float v) { return v > 0.0f ? v : 0.2f * v; }

// split x into fp16 hi + fp16 lo (UNSCALED residual), packed as half2
__device__ __forceinline__ void splitpack(float a, float b, uint32_t& hi, uint32_t& lo) {
    __half ha = __float2half_rn(a), hb = __float2half_rn(b);
    __half2 hh = __halves2half2(ha, hb);
    hi = *(uint32_t*)&hh;
    float la = a - __half2float(ha);
    float lb = b - __half2float(hb);
    __half2 hl = __floats2half2_rn(la, lb);
    lo = *(uint32_t*)&hl;
}

// ================= async-copy / ldmatrix helpers =================
__device__ __forceinline__ uint32_t s2u(const void* p) {
    return (uint32_t)__cvta_generic_to_shared(p);
}
__device__ __forceinline__ void cpasync16(uint32_t dst, const void* src, uint32_t sz) {
    asm volatile("cp.async.cg.shared.global [%0], [%1], 16, %2;"
                 :: "r"(dst), "l"(src), "r"(sz) : "memory");
}
__device__ __forceinline__ void cpcommit() {
    asm volatile("cp.async.commit_group;" ::: "memory");
}
template <int N>
__device__ __forceinline__ void cpwait() {
    asm volatile("cp.async.wait_group %0;" :: "n"(N) : "memory");
}
#define LDSM4(r, a) \
    asm volatile("ldmatrix.sync.aligned.m8n8.x4.shared.b16 {%0,%1,%2,%3}, [%4];" \
                 : "=r"((r)[0]), "=r"((r)[1]), "=r"((r)[2]), "=r"((r)[3]) : "r"(a))
#define LDSM2(r, a) \
    asm volatile("ldmatrix.sync.aligned.m8n8.x2.shared.b16 {%0,%1}, [%2];" \
                 : "=r"((r)[0]), "=r"((r)[1]) : "r"(a))
#define MMA_F16(d, a, b0, b1) \
    asm volatile("mma.sync.aligned.m16n8k16.row.col.f32.f16.f16.f32 " \
                 "{%0,%1,%2,%3}, {%4,%5,%6,%7}, {%8,%9}, {%0,%1,%2,%3};" \
                 : "+f"((d)[0]), "+f"((d)[1]), "+f"((d)[2]), "+f"((d)[3]) \
                 : "r"((a)[0]), "r"((a)[1]), "r"((a)[2]), "r"((a)[3]), \
                   "r"(b0), "r"(b1))

// ================= pre-split + init (fused) =================
__global__ void hsplit(const float* __restrict__ h) {
    int idx = blockIdx.x * blockDim.x + threadIdx.x;
    if (idx < NN) { g_cnt[idx] = 0; g_fill[idx] = 0; }
    if (idx < GG * HH) { g_gs[idx] = 0.0f; g_gm[idx] = NEG_INF; }
    if (idx >= NN * 64) return;
    int row = idx >> 6, k2 = idx & 63;
    float2 v = *(const float2*)&h[row * 128 + k2 * 2];
    splitpack(v.x, v.y, g_hh2[idx], g_hl2[idx]);
}
// all 4 weight matrices in one kernel
__global__ void wsplit_all(const float* __restrict__ W0, const float* __restrict__ resW0,
                           const float* __restrict__ W1, const float* __restrict__ W2) {
    int idx = blockIdx.x * blockDim.x + threadIdx.x;
    if (idx >= 98304) return;
    const float* W; int off, dh, lid;
    if (idx < 16384)      { W = W0;    off = 0;     dh = 64;  lid = idx; }
    else if (idx < 32768) { W = resW0; off = 16384; dh = 64;  lid = idx - 16384; }
    else if (idx < 65536) { W = W1;    off = 32768; dh = 128; lid = idx - 32768; }
    else                  { W = W2;    off = 65536; dh = 128; lid = idx - 65536; }
    int nn = lid & 255, k2 = lid >> 8;
    float v0 = W[(2 * k2) * 256 + nn];
    float v1 = W[(2 * k2 + 1) * 256 + nn];
    splitpack(v0, v1, g_wh[off + nn * dh + k2], g_wl[off + nn * dh + k2]);
}

// ================= CSR build =================
__global__ void csr_hist(const int* __restrict__ dst) {
    int e = blockIdx.x * blockDim.x + threadIdx.x;
    if (e < EE) atomicAdd(&g_cnt[dst[e]], 1);
}
__global__ void csr_scan() {
    __shared__ int smW[32];
    __shared__ int sOff;
    int tid = threadIdx.x, lane = tid & 31, wid = tid >> 5;
    if (tid == 0) sOff = 0;
    __syncthreads();
    for (int base = 0; base < NN; base += 1024) {
        int i = base + tid;
        int v = (i < NN) ? g_cnt[i] : 0;
        int inc = v;
#pragma unroll
        for (int o = 1; o < 32; o <<= 1) {
            int t = __shfl_up_sync(0xffffffffu, inc, o);
            if (lane >= o) inc += t;
        }
        if (lane == 31) smW[wid] = inc;
        __syncthreads();
        if (wid == 0) {
            int t = smW[lane];
#pragma unroll
            for (int o = 1; o < 32; o <<= 1) {
                int u = __shfl_up_sync(0xffffffffu, t, o);
                if (lane >= o) t += u;
            }
            smW[lane] = t;
        }
        __syncthreads();
        int warpOff = wid ? smW[wid - 1] : 0;
        if (i < NN) g_rowptr[i] = sOff + warpOff + inc - v;
        int blockTot = smW[31];
        __syncthreads();
        if (tid == 0) sOff += blockTot;
        __syncthreads();
    }
    if (tid == 0) g_rowptr[NN] = sOff;
}
__global__ void csr_fill_k(const int* __restrict__ src, const int* __restrict__ dst) {
    int e = blockIdx.x * blockDim.x + threadIdx.x;
    if (e >= EE) return;
    int d = dst[e];
    int pos = g_rowptr[d] + atomicAdd(&g_fill[d], 1);
    g_csrc[pos] = src[e];
}

// ================= fp16-split GEMM (128x64, single-sync double buffer) ========
// C = A @ B^T, operands pre-split hi + lo(unscaled). Block 128x64, BK=32.
// If Cres != nullptr (merged layer-0): blockIdx.x in [0,8); bx<4 -> Cmain cols
// bx*64 with attention epilogue (head bx); bx>=4 -> Cres cols (bx-4)*64.
// B row index always bx*64 (weights stacked along rows).
__global__ void __launch_bounds__(256, 3) gemm_h3(
        const uint32_t* __restrict__ Ah2, const uint32_t* __restrict__ Al2,
        const uint32_t* __restrict__ Bh2, const uint32_t* __restrict__ Bl2,
        float* __restrict__ Cmain, float* __restrict__ Cres, int n, int din,
        const float* __restrict__ alp, const float* __restrict__ arp) {
    extern __shared__ __align__(16) uint8_t smx[];
    __shared__ float sEl[2][128], sEr[2][128];
    const int tid  = threadIdx.x;
    const int wid  = tid >> 5;
    const int lane = tid & 31;
    const int bx   = blockIdx.x;
    const bool isres = (Cres != nullptr) && (bx >= 4);
    float* C = isres ? Cres : Cmain;
    const int row0  = blockIdx.y * 128;
    const int col0B = bx * 64;                    // row offset into stacked B
    const int col0C = isres ? (bx - 4) * 64 : bx * 64;
    const bool doattn = (alp != nullptr) && !isres;
    const int wm0  = (wid >> 1) * 32;
    const int wn0  = (wid & 1) * 32;
    const int grp  = lane >> 2;
    const int qid  = lane & 3;
    const int dh   = din >> 1;
    const int ntiles = dh >> 4;                   // k32 tiles

    const uint32_t uA = s2u(smx);
    const uint32_t uB = uA + 40960;

    float acc[2][4][4] = {};

    const int arow = tid >> 2;
    const int ach  = (tid & 3) * 4;

    auto load_tile = [&](int buf, int tile) {
        const int kof = tile * 16;
#pragma unroll
        for (int t = 0; t < 2; t++) {
            int row = arow + t * 64;
            int gr  = row0 + row;
            uint32_t sz = (gr < n) ? 16u : 0u;
            size_t off = (gr < n) ? ((size_t)gr * dh + kof + ach) : 0;
            uint32_t d = uA + buf * 10240 + (row * 20 + ach) * 4;
            cpasync16(d,         Ah2 + off, sz);
            cpasync16(d + 20480, Al2 + off, sz);
        }
        {
            int row = tid >> 2;
            size_t off = (size_t)(col0B + row) * dh + kof + ach;
            uint32_t d = uB + buf * 5120 + (row * 20 + ach) * 4;
            cpasync16(d,         Bh2 + off, 16u);
            cpasync16(d + 10240, Bl2 + off, 16u);
        }
        cpcommit();
    };

    load_tile(0, 0);
    for (int ti = 0; ti < ntiles; ti++) {
        cpwait<0>();
        __syncthreads();
        if (ti + 1 < ntiles) load_tile((ti + 1) & 1, ti + 1);
        const int buf = ti & 1;
        const uint32_t aB = uA + buf * 10240;
        const uint32_t bB = uB + buf * 5120;
#pragma unroll
        for (int ks = 0; ks < 2; ks++) {
            const int kb2 = ks * 8;
            uint32_t afh[2][4], afl[2][4], bfh[4][2], bfl[4][2];
#pragma unroll
            for (int mt = 0; mt < 2; mt++) {
                uint32_t ad = aB + (((wm0 + mt * 16 + (lane & 15)) * 20 + kb2 +
                                     ((lane >> 4) << 2)) << 2);
                LDSM4(afh[mt], ad);
                LDSM4(afl[mt], ad + 20480);
            }
#pragma unroll
            for (int nt = 0; nt < 4; nt++) {
                uint32_t bd = bB + (((wn0 + nt * 8 + (lane & 7)) * 20 + kb2 +
                                     (((lane >> 3) & 1) << 2)) << 2);
                LDSM2(bfh[nt], bd);
                LDSM2(bfl[nt], bd + 10240);
            }
#pragma unroll
            for (int mt = 0; mt < 2; mt++)
#pragma unroll
                for (int nt = 0; nt < 4; nt++) {
                    MMA_F16(acc[mt][nt], afh[mt], bfh[nt][0], bfh[nt][1]);
                    MMA_F16(acc[mt][nt], afh[mt], bfl[nt][0], bfl[nt][1]);
                    MMA_F16(acc[mt][nt], afl[mt], bfh[nt][0], bfh[nt][1]);
                }
        }
    }

    // ---- store C ----
#pragma unroll
    for (int mt = 0; mt < 2; mt++) {
#pragma unroll
        for (int nt = 0; nt < 4; nt++) {
            int r  = row0 + wm0 + mt * 16 + grp;
            int cC = col0C + wn0 + nt * 8 + qid * 2;
            if (r < n)
                *(float2*)&C[(size_t)r * KH + cC] = make_float2(acc[mt][nt][0], acc[mt][nt][1]);
            if (r + 8 < n)
                *(float2*)&C[(size_t)(r + 8) * KH + cC] = make_float2(acc[mt][nt][2], acc[mt][nt][3]);
        }
    }
    // ---- fused attention projections el/er for head bx ----
    if (doattn) {
        const int hd = bx;
        float alv[4][2], arv[4][2];
#pragma unroll
        for (int nt = 0; nt < 4; nt++)
#pragma unroll
            for (int j = 0; j < 2; j++) {
                int c = wn0 + nt * 8 + qid * 2 + j;
                alv[nt][j] = alp[hd * 64 + c];
                arv[nt][j] = arp[hd * 64 + c];
            }
#pragma unroll
        for (int mt = 0; mt < 2; mt++) {
            float ea = 0.f, eb = 0.f, ra = 0.f, rb = 0.f;
#pragma unroll
            for (int nt = 0; nt < 4; nt++) {
                ea += acc[mt][nt][0] * alv[nt][0] + acc[mt][nt][1] * alv[nt][1];
                eb += acc[mt][nt][2] * alv[nt][0] + acc[mt][nt][3] * alv[nt][1];
                ra += acc[mt][nt][0] * arv[nt][0] + acc[mt][nt][1] * arv[nt][1];
                rb += acc[mt][nt][2] * arv[nt][0] + acc[mt][nt][3] * arv[nt][1];
            }
#pragma unroll
            for (int o = 1; o < 4; o <<= 1) {
                ea += __shfl_down_sync(0xffffffffu, ea, o, 4);
                eb += __shfl_down_sync(0xffffffffu, eb, o, 4);
                ra += __shfl_down_sync(0xffffffffu, ra, o, 4);
                rb += __shfl_down_sync(0xffffffffu, rb, o, 4);
            }
            if (qid == 0) {
                int rr = wm0 + mt * 16 + grp;
                int hf = wn0 >> 5;
                sEl[hf][rr] = ea; sEl[hf][rr + 8] = eb;
                sEr[hf][rr] = ra; sEr[hf][rr + 8] = rb;
            }
        }
        __syncthreads();
        if (tid < 128) {
            int gr = row0 + tid;
            if (gr < n) {
                g_el[gr * 4 + hd] = sEl[0][tid] + sEl[1][tid];
                g_er[gr * 4 + hd] = sEr[0][tid] + sEr[1][tid];
            }
        }
    }
}

// ================= fused GAT attention + aggregation + combine (two-pass) ======
__global__ void gat_fused(const float* __restrict__ z, const float* __restrict__ res,
                          const float* __restrict__ bias, float* __restrict__ xout,
                          int mode, uint32_t* __restrict__ xh2, uint32_t* __restrict__ xl2) {
    __shared__ float sm[8][256];
    const int wIB  = threadIdx.x >> 5;
    const int n    = (blockIdx.x * blockDim.x + threadIdx.x) >> 5;
    const int lane = threadIdx.x & 31;
    if (n >= NN) return;
    const int r0 = g_rowptr[n];
    const int nE = g_rowptr[n + 1] - r0;
    const float4 erv = *(const float4*)&g_er[n * 4];
    const int myK = lane >> 3;

    float m0 = NEG_INF, m1 = NEG_INF, m2 = NEG_INF, m3 = NEG_INF;
    for (int b = 0; b < nE; b += 32) {
        int idx = b + lane;
        if (idx < nE) {
            int s = g_csrc[r0 + idx];
            float4 l = *(const float4*)&g_el[s * 4];
            m0 = fmaxf(m0, leaky02(l.x + erv.x));
            m1 = fmaxf(m1, leaky02(l.y + erv.y));
            m2 = fmaxf(m2, leaky02(l.z + erv.z));
            m3 = fmaxf(m3, leaky02(l.w + erv.w));
        }
    }
#pragma unroll
    for (int off = 16; off; off >>= 1) {
        m0 = fmaxf(m0, __shfl_xor_sync(0xffffffffu, m0, off));
        m1 = fmaxf(m1, __shfl_xor_sync(0xffffffffu, m1, off));
        m2 = fmaxf(m2, __shfl_xor_sync(0xffffffffu, m2, off));
        m3 = fmaxf(m3, __shfl_xor_sync(0xffffffffu, m3, off));
    }

    float acc[8] = {};
    float sl0 = 0.f, sl1 = 0.f, sl2 = 0.f, sl3 = 0.f;
    for (int b = 0; b < nE; b += 32) {
        int idx = b + lane;
        int cnt = min(32, nE - b);
        float p0 = 0.f, p1 = 0.f, p2 = 0.f, p3 = 0.f;
        int sN = 0;
        if (idx < nE) {
            sN = g_csrc[r0 + idx];
            float4 l = *(const float4*)&g_el[sN * 4];
            p0 = __expf(leaky02(l.x + erv.x) - m0);
            p1 = __expf(leaky02(l.y + erv.y) - m1);
            p2 = __expf(leaky02(l.z + erv.z) - m2);
            p3 = __expf(leaky02(l.w + erv.w) - m3);
            sl0 += p0; sl1 += p1; sl2 += p2; sl3 += p3;
        }
        int i = 0;
        for (; i + 4 <= cnt; i += 4) {
            int ss[4]; float pa[4];
#pragma unroll
            for (int j = 0; j < 4; j++) {
                ss[j] = __shfl_sync(0xffffffffu, sN, i + j);
                float q0 = __shfl_sync(0xffffffffu, p0, i + j);
                float q1 = __shfl_sync(0xffffffffu, p1, i + j);
                float q2 = __shfl_sync(0xffffffffu, p2, i + j);
                float q3 = __shfl_sync(0xffffffffu, p3, i + j);
                pa[j] = (myK == 0) ? q0 : (myK == 1) ? q1 : (myK == 2) ? q2 : q3;
            }
            float4 za[4], zb[4];
#pragma unroll
            for (int j = 0; j < 4; j++) {
                const float4* zr = (const float4*)(z + (size_t)ss[j] * KH + lane * 8);
                za[j] = zr[0]; zb[j] = zr[1];
            }
#pragma unroll
            for (int j = 0; j < 4; j++) {
                acc[0] += pa[j] * za[j].x; acc[1] += pa[j] * za[j].y;
                acc[2] += pa[j] * za[j].z; acc[3] += pa[j] * za[j].w;
                acc[4] += pa[j] * zb[j].x; acc[5] += pa[j] * zb[j].y;
                acc[6] += pa[j] * zb[j].z; acc[7] += pa[j] * zb[j].w;
            }
        }
        for (; i < cnt; i++) {
            int ss   = __shfl_sync(0xffffffffu, sN, i);
            float q0 = __shfl_sync(0xffffffffu, p0, i);
            float q1 = __shfl_sync(0xffffffffu, p1, i);
            float q2 = __shfl_sync(0xffffffffu, p2, i);
            float q3 = __shfl_sync(0xffffffffu, p3, i);
            float pa = (myK == 0) ? q0 : (myK == 1) ? q1 : (myK == 2) ? q2 : q3;
            const float4* zr = (const float4*)(z + (size_t)ss * KH + lane * 8);
            float4 za = zr[0], zb = zr[1];
            acc[0] += pa * za.x; acc[1] += pa * za.y;
            acc[2] += pa * za.z; acc[3] += pa * za.w;
            acc[4] += pa * zb.x; acc[5] += pa * zb.y;
            acc[6] += pa * zb.z; acc[7] += pa * zb.w;
        }
    }
#pragma unroll
    for (int off = 16; off; off >>= 1) {
        sl0 += __shfl_xor_sync(0xffffffffu, sl0, off);
        sl1 += __shfl_xor_sync(0xffffffffu, sl1, off);
        sl2 += __shfl_xor_sync(0xffffffffu, sl2, off);
        sl3 += __shfl_xor_sync(0xffffffffu, sl3, off);
    }
    float sk = (myK == 0) ? sl0 : (myK == 1) ? sl1 : (myK == 2) ? sl2 : sl3;
    float inv = (nE > 0) ? (1.0f / sk) : 0.0f;

    const int base = n * KH + lane * 8;
    float v[8];
    const float4* rp = (const float4*)(res + base);
    const float4* bp = (const float4*)(bias + lane * 8);
    float4 r4a = rp[0], r4b = rp[1], b4a = bp[0], b4b = bp[1];
    v[0] = acc[0] * inv + r4a.x + b4a.x; v[1] = acc[1] * inv + r4a.y + b4a.y;
    v[2] = acc[2] * inv + r4a.z + b4a.z; v[3] = acc[3] * inv + r4a.w + b4a.w;
    v[4] = acc[4] * inv + r4b.x + b4b.x; v[5] = acc[5] * inv + r4b.y + b4b.y;
    v[6] = acc[6] * inv + r4b.z + b4b.z; v[7] = acc[7] * inv + r4b.w + b4b.w;
#pragma unroll
    for (int j = 0; j < 8; j++) v[j] = v[j] > 0.f ? v[j] : 0.f;

    if (mode == 0) {
        float4* op = (float4*)(xout + base);
        op[0] = make_float4(v[0], v[1], v[2], v[3]);
        op[1] = make_float4(v[4], v[5], v[6], v[7]);
        uint32_t oh[4], ol[4];
        splitpack(v[0], v[1], oh[0], ol[0]);
        splitpack(v[2], v[3], oh[1], ol[1]);
        splitpack(v[4], v[5], oh[2], ol[2]);
        splitpack(v[6], v[7], oh[3], ol[3]);
        *(uint4*)&xh2[(size_t)n * 128 + lane * 4] = make_uint4(oh[0], oh[1], oh[2], oh[3]);
        *(uint4*)&xl2[(size_t)n * 128 + lane * 4] = make_uint4(ol[0], ol[1], ol[2], ol[3]);
    } else {
#pragma unroll
        for (int j = 0; j < 8; j++) sm[wIB][lane * 8 + j] = v[j];
        __syncwarp();
        float h0 = (sm[wIB][lane]       + sm[wIB][64 + lane] +
                    sm[wIB][128 + lane] + sm[wIB][192 + lane]) * 0.25f;
        float h1 = (sm[wIB][32 + lane]  + sm[wIB][96 + lane] +
                    sm[wIB][160 + lane] + sm[wIB][224 + lane]) * 0.25f;
        g_x3[n * 64 + lane]      = h0;
        g_x3[n * 64 + lane + 32] = h1;
    }
}

// ================= readout + MLP =================
__global__ void readout(const int* __restrict__ gid, const float* __restrict__ Wg,
                        const float* __restrict__ bg) {
    int w    = (blockIdx.x * blockDim.x + threadIdx.x) >> 5;
    int lane = threadIdx.x & 31;
    if (w >= NN) return;
    int g = gid[w];
    const float* xr = g_x3 + (size_t)w * 64;
    float x0 = xr[lane], x1 = xr[lane + 32];
    float p = x0 * Wg[lane] + x1 * Wg[lane + 32];
#pragma unroll
    for (int off = 16; off; off >>= 1) p += __shfl_down_sync(0xffffffffu, p, off);
    p = __shfl_sync(0xffffffffu, p, 0);
    float wgt = 1.0f / (1.0f + expf(-(p + bg[0])));
    atomicAdd(&g_gs[g * 64 + lane],      wgt * x0);
    atomicAdd(&g_gs[g * 64 + lane + 32], wgt * x1);
    atomicMaxF(&g_gm[g * 64 + lane],      x0);
    atomicMaxF(&g_gm[g * 64 + lane + 32], x1);
}
__global__ void mlp_head(const float* __restrict__ Wm1, const float* __restrict__ bm1,
                         const float* __restrict__ bn_g, const float* __restrict__ bn_b,
                         const float* __restrict__ bn_m, const float* __restrict__ bn_v,
                         const float* __restrict__ Wm2, const float* __restrict__ bm2,
                         float* __restrict__ out) {
    int g = blockIdx.x, j = threadIdx.x;
    __shared__ float gf[128];
    gf[j]      = g_gs[g * 64 + j];
    gf[j + 64] = g_gm[g * 64 + j];
    __syncthreads();
    float acc = bm1[j];
#pragma unroll 8
    for (int i = 0; i < 128; i++) acc += gf[i] * Wm1[i * 64 + j];
    float y = acc > 0.0f ? acc : 0.0f;
    y = (y - bn_m[j]) * rsqrtf(bn_v[j] + 1e-5f) * bn_g[j] + bn_b[j];
    __shared__ float red[64];
    red[j] = y * Wm2[j];
    __syncthreads();
    if (j == 0) {
        float t = 0.0f;
#pragma unroll
        for (int i = 0; i < 64; i++) t += red[i];
        out[g] = 1.0f / (1.0f + expf(-(t + bm2[0])));
    }
}

// ================= host launcher =================
extern "C" void kernel_launch(void* const* d_in, const int* in_sizes, int n_in,
                              void* d_out, int out_size) {
    (void)in_sizes; (void)n_in; (void)out_size;
    const float* h     = (const float*)d_in[0];
    const int*   src   = (const int*)d_in[1];
    const int*   dst   = (const int*)d_in[2];
    const int*   gid   = (const int*)d_in[3];
    const float* W0    = (const float*)d_in[4];
    const float* al0   = (const float*)d_in[5];
    const float* ar0   = (const float*)d_in[6];
    const float* b0    = (const float*)d_in[7];
    const float* resW0 = (const float*)d_in[8];
    const float* W1    = (const float*)d_in[9];
    const float* al1   = (const float*)d_in[10];
    const float* ar1   = (const float*)d_in[11];
    const float* b1    = (const float*)d_in[12];
    const float* W2    = (const float*)d_in[13];
    const float* al2   = (const float*)d_in[14];
    const float* ar2   = (const float*)d_in[15];
    const float* b2    = (const float*)d_in[16];
    const float* Wg    = (const float*)d_in[17];
    const float* bg    = (const float*)d_in[18];
    const float* Wm1   = (const float*)d_in[19];
    const float* bm1   = (const float*)d_in[20];
    const float* bng   = (const float*)d_in[21];
    const float* bnb   = (const float*)d_in[22];
    const float* bnm   = (const float*)d_in[23];
    const float* bnv   = (const float*)d_in[24];
    const float* Wm2   = (const float*)d_in[25];
    const float* bm2   = (const float*)d_in[26];

    float *p_z, *p_res, *p_x;
    uint32_t *p_hh2, *p_hl2, *p_xh2, *p_xl2, *p_wh, *p_wl;
    cudaGetSymbolAddress((void**)&p_z,   g_z);
    cudaGetSymbolAddress((void**)&p_res, g_res);
    cudaGetSymbolAddress((void**)&p_x,   g_x);
    cudaGetSymbolAddress((void**)&p_hh2, g_hh2);
    cudaGetSymbolAddress((void**)&p_hl2, g_hl2);
    cudaGetSymbolAddress((void**)&p_xh2, g_xh2);
    cudaGetSymbolAddress((void**)&p_xl2, g_xl2);
    cudaGetSymbolAddress((void**)&p_wh,  g_wh);
    cudaGetSymbolAddress((void**)&p_wl,  g_wl);

    const int SMEM_GEMM = 61440;
    cudaFuncSetAttribute(gemm_h3, cudaFuncAttributeMaxDynamicSharedMemorySize, SMEM_GEMM);

    const int edgeB  = (EE + 255) / 256;
    const int nWarpB = (NN + 7) / 8;

    // ---- pre-split + init (GEMM at launch index 2 for ncu) ----
    hsplit<<<(NN * 64 + 255) / 256, 256>>>(h);
    wsplit_all<<<(98304 + 255) / 256, 256>>>(W0, resW0, W1, W2);

    // ---- Layer 0 GEMMs merged (z + res in one launch) ----
    gemm_h3<<<dim3(8, (NN + 127) / 128), 256, SMEM_GEMM>>>(
        p_hh2, p_hl2, p_wh, p_wl, p_z, p_res, NN, FF, al0, ar0);

    // ---- CSR build ----
    csr_hist<<<edgeB, 256>>>(dst);
    csr_scan<<<1, 1024>>>();
    csr_fill_k<<<edgeB, 256>>>(src, dst);

    // ---- Layer 0 combine ----
    gat_fused<<<nWarpB, 256>>>(p_z, p_res, b0, p_x, 0, p_xh2, p_xl2);

    // ---- Layer 1 ----
    gemm_h3<<<dim3(4, (NN + 127) / 128), 256, SMEM_GEMM>>>(
        p_xh2, p_xl2, p_wh + 32768, p_wl + 32768, p_z, nullptr, NN, KH, al1, ar1);
    gat_fused<<<nWarpB, 256>>>(p_z, p_x, b1, p_x, 0, p_xh2, p_xl2);

    // ---- Layer 2 ----
    gemm_h3<<<dim3(4, (NN + 127) / 128), 256, SMEM_GEMM>>>(
        p_xh2, p_xl2, p_wh + 65536, p_wl + 65536, p_z, nullptr, NN, KH, al2, ar2);
    gat_fused<<<nWarpB, 256>>>(p_z, p_x, b2, nullptr, 1, nullptr, nullptr);

    // ---- Readout + MLP ----
    readout<<<nWarpB, 256>>>(gid, Wg, bg);
    mlp_head<<<GG, 64>>>(Wm1, bm1, bng, bnb, bnm, bnv, Wm2, bm2, (float*)d_out);
}

// round 12
// speedup vs baseline: 1.2067x; 1.0758x over previous
#include <cuda_runtime.h>
#include <cuda_fp16.h>
#include <math.h>
#include <stdint.h>

#define NN 50000
#define EE 400000
#define GG 512
#define FF 128
#define KK 4
#define HH 64
#define KH 256   // K*H
#define NEG_INF __int_as_float(0xff800000)

// ---------------- device scratch (static, no runtime allocation) ----------------
__device__ uint32_t g_zh[NN * 128];  // z as half2 [N][128]
__device__ float g_res[NN * KH];
__device__ float g_x[NN * KH];
__device__ float g_el[NN * KK];
__device__ float g_er[NN * KK];
__device__ float g_x3[NN * HH];
__device__ float g_gs[GG * HH];
__device__ float g_gm[GG * HH];
// fp16-split operand storage (half2 packed along K); lo is UNSCALED (x - fp16(x))
__device__ uint32_t g_hh2[NN * 64];
__device__ uint32_t g_hl2[NN * 64];
__device__ uint32_t g_xh2[NN * 128];
__device__ uint32_t g_xl2[NN * 128];
__device__ uint32_t g_wh[98304];   // [n][din/2]: W0@0, resW0@16384, W1@32768, W2@65536
__device__ uint32_t g_wl[98304];
// CSR
__device__ int g_rowptr[NN + 1];
__device__ int g_cnt[NN];
__device__ int g_fill[NN];
__device__ int g_csrc[EE];

__device__ __forceinline__ void atomicMaxF(float* addr, float v) {
    if (v >= 0.0f) atomicMax((int*)addr, __float_as_int(v));
    else           atomicMin((unsigned int*)addr, __float_as_uint(v));
}
__device__ __forceinline__ float leaky02(float v) { return v > 0.0f ? v : 0.2f * v; }

// split x into fp16 hi + fp16 lo (UNSCALED residual), packed as half2
__device__ __forceinline__ void splitpack(float a, float b, uint32_t& hi, uint32_t& lo) {
    __half ha = __float2half_rn(a), hb = __float2half_rn(b);
    __half2 hh = __halves2half2(ha, hb);
    hi = *(uint32_t*)&hh;
    float la = a - __half2float(ha);
    float lb = b - __half2float(hb);
    __half2 hl = __floats2half2_rn(la, lb);
    lo = *(uint32_t*)&hl;
}
__device__ __forceinline__ uint32_t packh2(float a, float b) {
    __half2 v = __floats2half2_rn(a, b);
    return *(uint32_t*)&v;
}

// ================= async-copy / ldmatrix helpers =================
__device__ __forceinline__ uint32_t s2u(const void* p) {
    return (uint32_t)__cvta_generic_to_shared(p);
}
__device__ __forceinline__ void cpasync16(uint32_t dst, const void* src, uint32_t sz) {
    asm volatile("cp.async.cg.shared.global [%0], [%1], 16, %2;"
                 :: "r"(dst), "l"(src), "r"(sz) : "memory");
}
__device__ __forceinline__ void cpcommit() {
    asm volatile("cp.async.commit_group;" ::: "memory");
}
template <int N>
__device__ __forceinline__ void cpwait() {
    asm volatile("cp.async.wait_group %0;" :: "n"(N) : "memory");
}
#define LDSM4(r, a) \
    asm volatile("ldmatrix.sync.aligned.m8n8.x4.shared.b16 {%0,%1,%2,%3}, [%4];" \
                 : "=r"((r)[0]), "=r"((r)[1]), "=r"((r)[2]), "=r"((r)[3]) : "r"(a))
#define LDSM2(r, a) \
    asm volatile("ldmatrix.sync.aligned.m8n8.x2.shared.b16 {%0,%1}, [%2];" \
                 : "=r"((r)[0]), "=r"((r)[1]) : "r"(a))
#define MMA_F16(d, a, b0, b1) \
    asm volatile("mma.sync.aligned.m16n8k16.row.col.f32.f16.f16.f32 " \
                 "{%0,%1,%2,%3}, {%4,%5,%6,%7}, {%8,%9}, {%0,%1,%2,%3};" \
                 : "+f"((d)[0]), "+f"((d)[1]), "+f"((d)[2]), "+f"((d)[3]) \
                 : "r"((a)[0]), "r"((a)[1]), "r"((a)[2]), "r"((a)[3]), \
                   "r"(b0), "r"(b1))

// ================= pre-split + init (fused) =================
__global__ void hsplit(const float* __restrict__ h) {
    int idx = blockIdx.x * blockDim.x + threadIdx.x;
    if (idx < NN) { g_cnt[idx] = 0; g_fill[idx] = 0; }
    if (idx < GG * HH) { g_gs[idx] = 0.0f; g_gm[idx] = NEG_INF; }
    if (idx >= NN * 64) return;
    int row = idx >> 6, k2 = idx & 63;
    float2 v = *(const float2*)&h[row * 128 + k2 * 2];
    splitpack(v.x, v.y, g_hh2[idx], g_hl2[idx]);
}
__global__ void wsplit_all(const float* __restrict__ W0, const float* __restrict__ resW0,
                           const float* __restrict__ W1, const float* __restrict__ W2) {
    int idx = blockIdx.x * blockDim.x + threadIdx.x;
    if (idx >= 98304) return;
    const float* W; int off, dh, lid;
    if (idx < 16384)      { W = W0;    off = 0;     dh = 64;  lid = idx; }
    else if (idx < 32768) { W = resW0; off = 16384; dh = 64;  lid = idx - 16384; }
    else if (idx < 65536) { W = W1;    off = 32768; dh = 128; lid = idx - 32768; }
    else                  { W = W2;    off = 65536; dh = 128; lid = idx - 65536; }
    int nn = lid & 255, k2 = lid >> 8;
    float v0 = W[(2 * k2) * 256 + nn];
    float v1 = W[(2 * k2 + 1) * 256 + nn];
    splitpack(v0, v1, g_wh[off + nn * dh + k2], g_wl[off + nn * dh + k2]);
}

// ================= CSR build =================
__global__ void csr_hist(const int* __restrict__ dst) {
    int e = blockIdx.x * blockDim.x + threadIdx.x;
    if (e < EE) atomicAdd(&g_cnt[dst[e]], 1);
}
__global__ void csr_scan() {
    __shared__ int smW[32];
    __shared__ int sOff;
    int tid = threadIdx.x, lane = tid & 31, wid = tid >> 5;
    if (tid == 0) sOff = 0;
    __syncthreads();
    for (int base = 0; base < NN; base += 1024) {
        int i = base + tid;
        int v = (i < NN) ? g_cnt[i] : 0;
        int inc = v;
#pragma unroll
        for (int o = 1; o < 32; o <<= 1) {
            int t = __shfl_up_sync(0xffffffffu, inc, o);
            if (lane >= o) inc += t;
        }
        if (lane == 31) smW[wid] = inc;
        __syncthreads();
        if (wid == 0) {
            int t = smW[lane];
#pragma unroll
            for (int o = 1; o < 32; o <<= 1) {
                int u = __shfl_up_sync(0xffffffffu, t, o);
                if (lane >= o) t += u;
            }
            smW[lane] = t;
        }
        __syncthreads();
        int warpOff = wid ? smW[wid - 1] : 0;
        if (i < NN) g_rowptr[i] = sOff + warpOff + inc - v;
        int blockTot = smW[31];
        __syncthreads();
        if (tid == 0) sOff += blockTot;
        __syncthreads();
    }
    if (tid == 0) g_rowptr[NN] = sOff;
}
__global__ void csr_fill_k(const int* __restrict__ src, const int* __restrict__ dst) {
    int e = blockIdx.x * blockDim.x + threadIdx.x;
    if (e >= EE) return;
    int d = dst[e];
    int pos = g_rowptr[d] + atomicAdd(&g_fill[d], 1);
    g_csrc[pos] = src[e];
}

// ================= fp16-split GEMM (128x64, single-sync double buffer) ========
// z output stored as half2; layer-0 res path stored fp32.
__global__ void __launch_bounds__(256, 3) gemm_h3(
        const uint32_t* __restrict__ Ah2, const uint32_t* __restrict__ Al2,
        const uint32_t* __restrict__ Bh2, const uint32_t* __restrict__ Bl2,
        uint32_t* __restrict__ zOut, float* __restrict__ Cres, int n, int din,
        const float* __restrict__ alp, const float* __restrict__ arp) {
    extern __shared__ __align__(16) uint8_t smx[];
    __shared__ float sEl[2][128], sEr[2][128];
    const int tid  = threadIdx.x;
    const int wid  = tid >> 5;
    const int lane = tid & 31;
    const int bx   = blockIdx.x;
    const bool isres = (Cres != nullptr) && (bx >= 4);
    const int row0  = blockIdx.y * 128;
    const int col0B = bx * 64;                    // row offset into stacked B
    const int col0C = isres ? (bx - 4) * 64 : bx * 64;
    const bool doattn = (alp != nullptr) && !isres;
    const int wm0  = (wid >> 1) * 32;
    const int wn0  = (wid & 1) * 32;
    const int grp  = lane >> 2;
    const int qid  = lane & 3;
    const int dh   = din >> 1;
    const int ntiles = dh >> 4;                   // k32 tiles

    const uint32_t uA = s2u(smx);
    const uint32_t uB = uA + 40960;

    float acc[2][4][4] = {};

    const int arow = tid >> 2;
    const int ach  = (tid & 3) * 4;

    auto load_tile = [&](int buf, int tile) {
        const int kof = tile * 16;
#pragma unroll
        for (int t = 0; t < 2; t++) {
            int row = arow + t * 64;
            int gr  = row0 + row;
            uint32_t sz = (gr < n) ? 16u : 0u;
            size_t off = (gr < n) ? ((size_t)gr * dh + kof + ach) : 0;
            uint32_t d = uA + buf * 10240 + (row * 20 + ach) * 4;
            cpasync16(d,         Ah2 + off, sz);
            cpasync16(d + 20480, Al2 + off, sz);
        }
        {
            int row = tid >> 2;
            size_t off = (size_t)(col0B + row) * dh + kof + ach;
            uint32_t d = uB + buf * 5120 + (row * 20 + ach) * 4;
            cpasync16(d,         Bh2 + off, 16u);
            cpasync16(d + 10240, Bl2 + off, 16u);
        }
        cpcommit();
    };

    load_tile(0, 0);
    for (int ti = 0; ti < ntiles; ti++) {
        cpwait<0>();
        __syncthreads();
        if (ti + 1 < ntiles) load_tile((ti + 1) & 1, ti + 1);
        const int buf = ti & 1;
        const uint32_t aB = uA + buf * 10240;
        const uint32_t bB = uB + buf * 5120;
#pragma unroll
        for (int ks = 0; ks < 2; ks++) {
            const int kb2 = ks * 8;
            uint32_t afh[2][4], afl[2][4], bfh[4][2], bfl[4][2];
#pragma unroll
            for (int mt = 0; mt < 2; mt++) {
                uint32_t ad = aB + (((wm0 + mt * 16 + (lane & 15)) * 20 + kb2 +
                                     ((lane >> 4) << 2)) << 2);
                LDSM4(afh[mt], ad);
                LDSM4(afl[mt], ad + 20480);
            }
#pragma unroll
            for (int nt = 0; nt < 4; nt++) {
                uint32_t bd = bB + (((wn0 + nt * 8 + (lane & 7)) * 20 + kb2 +
                                     (((lane >> 3) & 1) << 2)) << 2);
                LDSM2(bfh[nt], bd);
                LDSM2(bfl[nt], bd + 10240);
            }
#pragma unroll
            for (int mt = 0; mt < 2; mt++)
#pragma unroll
                for (int nt = 0; nt < 4; nt++) {
                    MMA_F16(acc[mt][nt], afh[mt], bfh[nt][0], bfh[nt][1]);
                    MMA_F16(acc[mt][nt], afh[mt], bfl[nt][0], bfl[nt][1]);
                    MMA_F16(acc[mt][nt], afl[mt], bfh[nt][0], bfh[nt][1]);
                }
        }
    }

    // ---- store: z as half2, res as fp32 ----
#pragma unroll
    for (int mt = 0; mt < 2; mt++) {
#pragma unroll
        for (int nt = 0; nt < 4; nt++) {
            int r  = row0 + wm0 + mt * 16 + grp;
            int cC = col0C + wn0 + nt * 8 + qid * 2;
            if (isres) {
                if (r < n)
                    *(float2*)&Cres[(size_t)r * KH + cC] =
                        make_float2(acc[mt][nt][0], acc[mt][nt][1]);
                if (r + 8 < n)
                    *(float2*)&Cres[(size_t)(r + 8) * KH + cC] =
                        make_float2(acc[mt][nt][2], acc[mt][nt][3]);
            } else {
                if (r < n)
                    zOut[(size_t)r * 128 + (cC >> 1)] = packh2(acc[mt][nt][0], acc[mt][nt][1]);
                if (r + 8 < n)
                    zOut[(size_t)(r + 8) * 128 + (cC >> 1)] = packh2(acc[mt][nt][2], acc[mt][nt][3]);
            }
        }
    }
    // ---- fused attention projections el/er for head bx ----
    if (doattn) {
        const int hd = bx;
        float alv[4][2], arv[4][2];
#pragma unroll
        for (int nt = 0; nt < 4; nt++)
#pragma unroll
            for (int j = 0; j < 2; j++) {
                int c = wn0 + nt * 8 + qid * 2 + j;
                alv[nt][j] = alp[hd * 64 + c];
                arv[nt][j] = arp[hd * 64 + c];
            }
#pragma unroll
        for (int mt = 0; mt < 2; mt++) {
            float ea = 0.f, eb = 0.f, ra = 0.f, rb = 0.f;
#pragma unroll
            for (int nt = 0; nt < 4; nt++) {
                ea += acc[mt][nt][0] * alv[nt][0] + acc[mt][nt][1] * alv[nt][1];
                eb += acc[mt][nt][2] * alv[nt][0] + acc[mt][nt][3] * alv[nt][1];
                ra += acc[mt][nt][0] * arv[nt][0] + acc[mt][nt][1] * arv[nt][1];
                rb += acc[mt][nt][2] * arv[nt][0] + acc[mt][nt][3] * arv[nt][1];
            }
#pragma unroll
            for (int o = 1; o < 4; o <<= 1) {
                ea += __shfl_down_sync(0xffffffffu, ea, o, 4);
                eb += __shfl_down_sync(0xffffffffu, eb, o, 4);
                ra += __shfl_down_sync(0xffffffffu, ra, o, 4);
                rb += __shfl_down_sync(0xffffffffu, rb, o, 4);
            }
            if (qid == 0) {
                int rr = wm0 + mt * 16 + grp;
                int hf = wn0 >> 5;
                sEl[hf][rr] = ea; sEl[hf][rr + 8] = eb;
                sEr[hf][rr] = ra; sEr[hf][rr + 8] = rb;
            }
        }
        __syncthreads();
        if (tid < 128) {
            int gr = row0 + tid;
            if (gr < n) {
                g_el[gr * 4 + hd] = sEl[0][tid] + sEl[1][tid];
                g_er[gr * 4 + hd] = sEr[0][tid] + sEr[1][tid];
            }
        }
    }
}

// ================= fused GAT attention + aggregation + combine (two-pass) ======
// z gathered as half2 (one LDG.128 per edge-lane).
__global__ void gat_fused(const uint32_t* __restrict__ zh, const float* __restrict__ res,
                          const float* __restrict__ bias, float* __restrict__ xout,
                          int mode, uint32_t* __restrict__ xh2, uint32_t* __restrict__ xl2) {
    __shared__ float sm[8][256];
    const int wIB  = threadIdx.x >> 5;
    const int n    = (blockIdx.x * blockDim.x + threadIdx.x) >> 5;
    const int lane = threadIdx.x & 31;
    if (n >= NN) return;
    const int r0 = g_rowptr[n];
    const int nE = g_rowptr[n + 1] - r0;
    const float4 erv = *(const float4*)&g_er[n * 4];
    const int myK = lane >> 3;

    float m0 = NEG_INF, m1 = NEG_INF, m2 = NEG_INF, m3 = NEG_INF;
    for (int b = 0; b < nE; b += 32) {
        int idx = b + lane;
        if (idx < nE) {
            int s = g_csrc[r0 + idx];
            float4 l = *(const float4*)&g_el[s * 4];
            m0 = fmaxf(m0, leaky02(l.x + erv.x));
            m1 = fmaxf(m1, leaky02(l.y + erv.y));
            m2 = fmaxf(m2, leaky02(l.z + erv.z));
            m3 = fmaxf(m3, leaky02(l.w + erv.w));
        }
    }
#pragma unroll
    for (int off = 16; off; off >>= 1) {
        m0 = fmaxf(m0, __shfl_xor_sync(0xffffffffu, m0, off));
        m1 = fmaxf(m1, __shfl_xor_sync(0xffffffffu, m1, off));
        m2 = fmaxf(m2, __shfl_xor_sync(0xffffffffu, m2, off));
        m3 = fmaxf(m3, __shfl_xor_sync(0xffffffffu, m3, off));
    }

    float acc[8] = {};
    float sl0 = 0.f, sl1 = 0.f, sl2 = 0.f, sl3 = 0.f;
    for (int b = 0; b < nE; b += 32) {
        int idx = b + lane;
        int cnt = min(32, nE - b);
        float p0 = 0.f, p1 = 0.f, p2 = 0.f, p3 = 0.f;
        int sN = 0;
        if (idx < nE) {
            sN = g_csrc[r0 + idx];
            float4 l = *(const float4*)&g_el[sN * 4];
            p0 = __expf(leaky02(l.x + erv.x) - m0);
            p1 = __expf(leaky02(l.y + erv.y) - m1);
            p2 = __expf(leaky02(l.z + erv.z) - m2);
            p3 = __expf(leaky02(l.w + erv.w) - m3);
            sl0 += p0; sl1 += p1; sl2 += p2; sl3 += p3;
        }
        int i = 0;
        for (; i + 4 <= cnt; i += 4) {
            int ss[4]; float pa[4];
#pragma unroll
            for (int j = 0; j < 4; j++) {
                ss[j] = __shfl_sync(0xffffffffu, sN, i + j);
                float q0 = __shfl_sync(0xffffffffu, p0, i + j);
                float q1 = __shfl_sync(0xffffffffu, p1, i + j);
                float q2 = __shfl_sync(0xffffffffu, p2, i + j);
                float q3 = __shfl_sync(0xffffffffu, p3, i + j);
                pa[j] = (myK == 0) ? q0 : (myK == 1) ? q1 : (myK == 2) ? q2 : q3;
            }
            uint4 zv[4];
#pragma unroll
            for (int j = 0; j < 4; j++)
                zv[j] = *(const uint4*)(zh + (size_t)ss[j] * 128 + lane * 4);
#pragma unroll
            for (int j = 0; j < 4; j++) {
                float2 f0 = __half22float2(*(__half2*)&zv[j].x);
                float2 f1 = __half22float2(*(__half2*)&zv[j].y);
                float2 f2 = __half22float2(*(__half2*)&zv[j].z);
                float2 f3 = __half22float2(*(__half2*)&zv[j].w);
                acc[0] += pa[j] * f0.x; acc[1] += pa[j] * f0.y;
                acc[2] += pa[j] * f1.x; acc[3] += pa[j] * f1.y;
                acc[4] += pa[j] * f2.x; acc[5] += pa[j] * f2.y;
                acc[6] += pa[j] * f3.x; acc[7] += pa[j] * f3.y;
            }
        }
        for (; i < cnt; i++) {
            int ss   = __shfl_sync(0xffffffffu, sN, i);
            float q0 = __shfl_sync(0xffffffffu, p0, i);
            float q1 = __shfl_sync(0xffffffffu, p1, i);
            float q2 = __shfl_sync(0xffffffffu, p2, i);
            float q3 = __shfl_sync(0xffffffffu, p3, i);
            float pa = (myK == 0) ? q0 : (myK == 1) ? q1 : (myK == 2) ? q2 : q3;
            uint4 zv = *(const uint4*)(zh + (size_t)ss * 128 + lane * 4);
            float2 f0 = __half22float2(*(__half2*)&zv.x);
            float2 f1 = __half22float2(*(__half2*)&zv.y);
            float2 f2 = __half22float2(*(__half2*)&zv.z);
            float2 f3 = __half22float2(*(__half2*)&zv.w);
            acc[0] += pa * f0.x; acc[1] += pa * f0.y;
            acc[2] += pa * f1.x; acc[3] += pa * f1.y;
            acc[4] += pa * f2.x; acc[5] += pa * f2.y;
            acc[6] += pa * f3.x; acc[7] += pa * f3.y;
        }
    }
#pragma unroll
    for (int off = 16; off; off >>= 1) {
        sl0 += __shfl_xor_sync(0xffffffffu, sl0, off);
        sl1 += __shfl_xor_sync(0xffffffffu, sl1, off);
        sl2 += __shfl_xor_sync(0xffffffffu, sl2, off);
        sl3 += __shfl_xor_sync(0xffffffffu, sl3, off);
    }
    float sk = (myK == 0) ? sl0 : (myK == 1) ? sl1 : (myK == 2) ? sl2 : sl3;
    float inv = (nE > 0) ? (1.0f / sk) : 0.0f;

    const int base = n * KH + lane * 8;
    float v[8];
    const float4* rp = (const float4*)(res + base);
    const float4* bp = (const float4*)(bias + lane * 8);
    float4 r4a = rp[0], r4b = rp[1], b4a = bp[0], b4b = bp[1];
    v[0] = acc[0] * inv + r4a.x + b4a.x; v[1] = acc[1] * inv + r4a.y + b4a.y;
    v[2] = acc[2] * inv + r4a.z + b4a.z; v[3] = acc[3] * inv + r4a.w + b4a.w;
    v[4] = acc[4] * inv + r4b.x + b4b.x; v[5] = acc[5] * inv + r4b.y + b4b.y;
    v[6] = acc[6] * inv + r4b.z + b4b.z; v[7] = acc[7] * inv + r4b.w + b4b.w;
#pragma unroll
    for (int j = 0; j < 8; j++) v[j] = v[j] > 0.f ? v[j] : 0.f;

    if (mode == 0) {
        float4* op = (float4*)(xout + base);
        op[0] = make_float4(v[0], v[1], v[2], v[3]);
        op[1] = make_float4(v[4], v[5], v[6], v[7]);
        uint32_t oh[4], ol[4];
        splitpack(v[0], v[1], oh[0], ol[0]);
        splitpack(v[2], v[3], oh[1], ol[1]);
        splitpack(v[4], v[5], oh[2], ol[2]);
        splitpack(v[6], v[7], oh[3], ol[3]);
        *(uint4*)&xh2[(size_t)n * 128 + lane * 4] = make_uint4(oh[0], oh[1], oh[2], oh[3]);
        *(uint4*)&xl2[(size_t)n * 128 + lane * 4] = make_uint4(ol[0], ol[1], ol[2], ol[3]);
    } else {
#pragma unroll
        for (int j = 0; j < 8; j++) sm[wIB][lane * 8 + j] = v[j];
        __syncwarp();
        float h0 = (sm[wIB][lane]       + sm[wIB][64 + lane] +
                    sm[wIB][128 + lane] + sm[wIB][192 + lane]) * 0.25f;
        float h1 = (sm[wIB][32 + lane]  + sm[wIB][96 + lane] +
                    sm[wIB][160 + lane] + sm[wIB][224 + lane]) * 0.25f;
        g_x3[n * 64 + lane]      = h0;
        g_x3[n * 64 + lane + 32] = h1;
    }
}

// ================= readout + MLP =================
__global__ void readout(const int* __restrict__ gid, const float* __restrict__ Wg,
                        const float* __restrict__ bg) {
    int w    = (blockIdx.x * blockDim.x + threadIdx.x) >> 5;
    int lane = threadIdx.x & 31;
    if (w >= NN) return;
    int g = gid[w];
    const float* xr = g_x3 + (size_t)w * 64;
    float x0 = xr[lane], x1 = xr[lane + 32];
    float p = x0 * Wg[lane] + x1 * Wg[lane + 32];
#pragma unroll
    for (int off = 16; off; off >>= 1) p += __shfl_down_sync(0xffffffffu, p, off);
    p = __shfl_sync(0xffffffffu, p, 0);
    float wgt = 1.0f / (1.0f + expf(-(p + bg[0])));
    atomicAdd(&g_gs[g * 64 + lane],      wgt * x0);
    atomicAdd(&g_gs[g * 64 + lane + 32], wgt * x1);
    atomicMaxF(&g_gm[g * 64 + lane],      x0);
    atomicMaxF(&g_gm[g * 64 + lane + 32], x1);
}
__global__ void mlp_head(const float* __restrict__ Wm1, const float* __restrict__ bm1,
                         const float* __restrict__ bn_g, const float* __restrict__ bn_b,
                         const float* __restrict__ bn_m, const float* __restrict__ bn_v,
                         const float* __restrict__ Wm2, const float* __restrict__ bm2,
                         float* __restrict__ out) {
    int g = blockIdx.x, j = threadIdx.x;
    __shared__ float gf[128];
    gf[j]      = g_gs[g * 64 + j];
    gf[j + 64] = g_gm[g * 64 + j];
    __syncthreads();
    float acc = bm1[j];
#pragma unroll 8
    for (int i = 0; i < 128; i++) acc += gf[i] * Wm1[i * 64 + j];
    float y = acc > 0.0f ? acc : 0.0f;
    y = (y - bn_m[j]) * rsqrtf(bn_v[j] + 1e-5f) * bn_g[j] + bn_b[j];
    __shared__ float red[64];
    red[j] = y * Wm2[j];
    __syncthreads();
    if (j == 0) {
        float t = 0.0f;
#pragma unroll
        for (int i = 0; i < 64; i++) t += red[i];
        out[g] = 1.0f / (1.0f + expf(-(t + bm2[0])));
    }
}

// ================= host launcher =================
extern "C" void kernel_launch(void* const* d_in, const int* in_sizes, int n_in,
                              void* d_out, int out_size) {
    (void)in_sizes; (void)n_in; (void)out_size;
    const float* h     = (const float*)d_in[0];
    const int*   src   = (const int*)d_in[1];
    const int*   dst   = (const int*)d_in[2];
    const int*   gid   = (const int*)d_in[3];
    const float* W0    = (const float*)d_in[4];
    const float* al0   = (const float*)d_in[5];
    const float* ar0   = (const float*)d_in[6];
    const float* b0    = (const float*)d_in[7];
    const float* resW0 = (const float*)d_in[8];
    const float* W1    = (const float*)d_in[9];
    const float* al1   = (const float*)d_in[10];
    const float* ar1   = (const float*)d_in[11];
    const float* b1    = (const float*)d_in[12];
    const float* W2    = (const float*)d_in[13];
    const float* al2   = (const float*)d_in[14];
    const float* ar2   = (const float*)d_in[15];
    const float* b2    = (const float*)d_in[16];
    const float* Wg    = (const float*)d_in[17];
    const float* bg    = (const float*)d_in[18];
    const float* Wm1   = (const float*)d_in[19];
    const float* bm1   = (const float*)d_in[20];
    const float* bng   = (const float*)d_in[21];
    const float* bnb   = (const float*)d_in[22];
    const float* bnm   = (const float*)d_in[23];
    const float* bnv   = (const float*)d_in[24];
    const float* Wm2   = (const float*)d_in[25];
    const float* bm2   = (const float*)d_in[26];

    float *p_res, *p_x;
    uint32_t *p_zh, *p_hh2, *p_hl2, *p_xh2, *p_xl2, *p_wh, *p_wl;
    cudaGetSymbolAddress((void**)&p_zh,  g_zh);
    cudaGetSymbolAddress((void**)&p_res, g_res);
    cudaGetSymbolAddress((void**)&p_x,   g_x);
    cudaGetSymbolAddress((void**)&p_hh2, g_hh2);
    cudaGetSymbolAddress((void**)&p_hl2, g_hl2);
    cudaGetSymbolAddress((void**)&p_xh2, g_xh2);
    cudaGetSymbolAddress((void**)&p_xl2, g_xl2);
    cudaGetSymbolAddress((void**)&p_wh,  g_wh);
    cudaGetSymbolAddress((void**)&p_wl,  g_wl);

    const int SMEM_GEMM = 61440;
    cudaFuncSetAttribute(gemm_h3, cudaFuncAttributeMaxDynamicSharedMemorySize, SMEM_GEMM);

    const int edgeB  = (EE + 255) / 256;
    const int nWarpB = (NN + 7) / 8;

    // ---- pre-split + init ----
    hsplit<<<(NN * 64 + 255) / 256, 256>>>(h);
    wsplit_all<<<(98304 + 255) / 256, 256>>>(W0, resW0, W1, W2);

    // ---- Layer 0 GEMMs merged (z + res in one launch) ----
    gemm_h3<<<dim3(8, (NN + 127) / 128), 256, SMEM_GEMM>>>(
        p_hh2, p_hl2, p_wh, p_wl, p_zh, p_res, NN, FF, al0, ar0);

    // ---- CSR build ----
    csr_hist<<<edgeB, 256>>>(dst);
    csr_scan<<<1, 1024>>>();
    csr_fill_k<<<edgeB, 256>>>(src, dst);

    // ---- Layer 0 combine ----
    gat_fused<<<nWarpB, 256>>>(p_zh, p_res, b0, p_x, 0, p_xh2, p_xl2);

    // ---- Layer 1 ----
    gemm_h3<<<dim3(4, (NN + 127) / 128), 256, SMEM_GEMM>>>(
        p_xh2, p_xl2, p_wh + 32768, p_wl + 32768, p_zh, nullptr, NN, KH, al1, ar1);
    gat_fused<<<nWarpB, 256>>>(p_zh, p_x, b1, p_x, 0, p_xh2, p_xl2);

    // ---- Layer 2 ----
    gemm_h3<<<dim3(4, (NN + 127) / 128), 256, SMEM_GEMM>>>(
        p_xh2, p_xl2, p_wh + 65536, p_wl + 65536, p_zh, nullptr, NN, KH, al2, ar2);
    gat_fused<<<nWarpB, 256>>>(p_zh, p_x, b2, nullptr, 1, nullptr, nullptr);

    // ---- Readout + MLP ----
    readout<<<nWarpB, 256>>>(gid, Wg, bg);
    mlp_head<<<GG, 64>>>(Wm1, bm1, bng, bnb, bnm, bnv, Wm2, bm2, (float*)d_out);
}

// round 13
// speedup vs baseline: 1.2308x; 1.0199x over previous
#include <cuda_runtime.h>
#include <cuda_fp16.h>
#include <math.h>
#include <stdint.h>

#define NN 50000
#define EE 400000
#define GG 512
#define FF 128
#define KK 4
#define HH 64
#define KH 256   // K*H
#define NEG_INF __int_as_float(0xff800000)

// ---------------- device scratch (static, no runtime allocation) ----------------
__device__ uint32_t g_zh[NN * 128];  // z as half2 [N][128]
__device__ float g_res[NN * KH];
__device__ float g_x[NN * KH];
__device__ float g_el[NN * KK];
__device__ float g_er[NN * KK];
__device__ float g_x3[NN * HH];
__device__ float g_gs[GG * HH];
__device__ float g_gm[GG * HH];
// fp16-split operand storage (half2 packed along K); lo is UNSCALED (x - fp16(x))
__device__ uint32_t g_hh2[NN * 64];
__device__ uint32_t g_hl2[NN * 64];
__device__ uint32_t g_xh2[NN * 128];
__device__ uint32_t g_xl2[NN * 128];
__device__ uint32_t g_wh[98304];   // [n][din/2]: W0@0, resW0@16384, W1@32768, W2@65536
__device__ uint32_t g_wl[98304];
// CSR
__device__ int g_rowptr[NN + 1];
__device__ int g_cnt[NN];
__device__ int g_fill[NN];
__device__ int g_csrc[EE];

__device__ __forceinline__ void atomicMaxF(float* addr, float v) {
    if (v >= 0.0f) atomicMax((int*)addr, __float_as_int(v));
    else           atomicMin((unsigned int*)addr, __float_as_uint(v));
}
__device__ __forceinline__ float leaky02(float v) { return v > 0.0f ? v : 0.2f * v; }

// split x into fp16 hi + fp16 lo (UNSCALED residual), packed as half2
__device__ __forceinline__ void splitpack(float a, float b, uint32_t& hi, uint32_t& lo) {
    __half ha = __float2half_rn(a), hb = __float2half_rn(b);
    __half2 hh = __halves2half2(ha, hb);
    hi = *(uint32_t*)&hh;
    float la = a - __half2float(ha);
    float lb = b - __half2float(hb);
    __half2 hl = __floats2half2_rn(la, lb);
    lo = *(uint32_t*)&hl;
}
__device__ __forceinline__ uint32_t packh2(float a, float b) {
    __half2 v = __floats2half2_rn(a, b);
    return *(uint32_t*)&v;
}

// ================= async-copy / ldmatrix helpers =================
__device__ __forceinline__ uint32_t s2u(const void* p) {
    return (uint32_t)__cvta_generic_to_shared(p);
}
__device__ __forceinline__ void cpasync16(uint32_t dst, const void* src, uint32_t sz) {
    asm volatile("cp.async.cg.shared.global [%0], [%1], 16, %2;"
                 :: "r"(dst), "l"(src), "r"(sz) : "memory");
}
__device__ __forceinline__ void cpcommit() {
    asm volatile("cp.async.commit_group;" ::: "memory");
}
template <int N>
__device__ __forceinline__ void cpwait() {
    asm volatile("cp.async.wait_group %0;" :: "n"(N) : "memory");
}
#define LDSM4(r, a) \
    asm volatile("ldmatrix.sync.aligned.m8n8.x4.shared.b16 {%0,%1,%2,%3}, [%4];" \
                 : "=r"((r)[0]), "=r"((r)[1]), "=r"((r)[2]), "=r"((r)[3]) : "r"(a))
#define MMA_F16(d, a, b0, b1) \
    asm volatile("mma.sync.aligned.m16n8k16.row.col.f32.f16.f16.f32 " \
                 "{%0,%1,%2,%3}, {%4,%5,%6,%7}, {%8,%9}, {%0,%1,%2,%3};" \
                 : "+f"((d)[0]), "+f"((d)[1]), "+f"((d)[2]), "+f"((d)[3]) \
                 : "r"((a)[0]), "r"((a)[1]), "r"((a)[2]), "r"((a)[3]), \
                   "r"(b0), "r"(b1))

// ================= pre-split + init (fused) =================
__global__ void hsplit(const float* __restrict__ h) {
    int idx = blockIdx.x * blockDim.x + threadIdx.x;
    if (idx < NN) { g_cnt[idx] = 0; g_fill[idx] = 0; }
    if (idx < GG * HH) { g_gs[idx] = 0.0f; g_gm[idx] = NEG_INF; }
    if (idx >= NN * 64) return;
    int row = idx >> 6, k2 = idx & 63;
    float2 v = *(const float2*)&h[row * 128 + k2 * 2];
    splitpack(v.x, v.y, g_hh2[idx], g_hl2[idx]);
}
__global__ void wsplit_all(const float* __restrict__ W0, const float* __restrict__ resW0,
                           const float* __restrict__ W1, const float* __restrict__ W2) {
    int idx = blockIdx.x * blockDim.x + threadIdx.x;
    if (idx >= 98304) return;
    const float* W; int off, dh, lid;
    if (idx < 16384)      { W = W0;    off = 0;     dh = 64;  lid = idx; }
    else if (idx < 32768) { W = resW0; off = 16384; dh = 64;  lid = idx - 16384; }
    else if (idx < 65536) { W = W1;    off = 32768; dh = 128; lid = idx - 32768; }
    else                  { W = W2;    off = 65536; dh = 128; lid = idx - 65536; }
    int nn = lid & 255, k2 = lid >> 8;
    float v0 = W[(2 * k2) * 256 + nn];
    float v1 = W[(2 * k2 + 1) * 256 + nn];
    splitpack(v0, v1, g_wh[off + nn * dh + k2], g_wl[off + nn * dh + k2]);
}

// ================= CSR build =================
__global__ void csr_hist(const int* __restrict__ dst) {
    int e = blockIdx.x * blockDim.x + threadIdx.x;
    if (e < EE) atomicAdd(&g_cnt[dst[e]], 1);
}
__global__ void csr_scan() {
    __shared__ int smW[32];
    __shared__ int sOff;
    int tid = threadIdx.x, lane = tid & 31, wid = tid >> 5;
    if (tid == 0) sOff = 0;
    __syncthreads();
    for (int base = 0; base < NN; base += 1024) {
        int i = base + tid;
        int v = (i < NN) ? g_cnt[i] : 0;
        int inc = v;
#pragma unroll
        for (int o = 1; o < 32; o <<= 1) {
            int t = __shfl_up_sync(0xffffffffu, inc, o);
            if (lane >= o) inc += t;
        }
        if (lane == 31) smW[wid] = inc;
        __syncthreads();
        if (wid == 0) {
            int t = smW[lane];
#pragma unroll
            for (int o = 1; o < 32; o <<= 1) {
                int u = __shfl_up_sync(0xffffffffu, t, o);
                if (lane >= o) t += u;
            }
            smW[lane] = t;
        }
        __syncthreads();
        int warpOff = wid ? smW[wid - 1] : 0;
        if (i < NN) g_rowptr[i] = sOff + warpOff + inc - v;
        int blockTot = smW[31];
        __syncthreads();
        if (tid == 0) sOff += blockTot;
        __syncthreads();
    }
    if (tid == 0) g_rowptr[NN] = sOff;
}
__global__ void csr_fill_k(const int* __restrict__ src, const int* __restrict__ dst) {
    int e = blockIdx.x * blockDim.x + threadIdx.x;
    if (e >= EE) return;
    int d = dst[e];
    int pos = g_rowptr[d] + atomicAdd(&g_fill[d], 1);
    g_csrc[pos] = src[e];
}

// ================= fp16-split GEMM (128x64, LDSM4-B, single-sync) =============
__global__ void __launch_bounds__(256, 3) gemm_h3(
        const uint32_t* __restrict__ Ah2, const uint32_t* __restrict__ Al2,
        const uint32_t* __restrict__ Bh2, const uint32_t* __restrict__ Bl2,
        uint32_t* __restrict__ zOut, float* __restrict__ Cres, int n, int din,
        const float* __restrict__ alp, const float* __restrict__ arp) {
    extern __shared__ __align__(16) uint8_t smx[];
    __shared__ float sEl[2][128], sEr[2][128];
    const int tid  = threadIdx.x;
    const int wid  = tid >> 5;
    const int lane = tid & 31;
    const int bx   = blockIdx.x;
    const bool isres = (Cres != nullptr) && (bx >= 4);
    const int row0  = blockIdx.y * 128;
    const int col0B = bx * 64;                    // row offset into stacked B
    const int col0C = isres ? (bx - 4) * 64 : bx * 64;
    const bool doattn = (alp != nullptr) && !isres;
    const int wm0  = (wid >> 1) * 32;
    const int wn0  = (wid & 1) * 32;
    const int grp  = lane >> 2;
    const int qid  = lane & 3;
    const int dh   = din >> 1;
    const int ntiles = dh >> 4;                   // k32 tiles

    const uint32_t uA = s2u(smx);
    const uint32_t uB = uA + 40960;

    float acc[2][4][4] = {};

    const int arow = tid >> 2;
    const int ach  = (tid & 3) * 4;

    auto load_tile = [&](int buf, int tile) {
        const int kof = tile * 16;
#pragma unroll
        for (int t = 0; t < 2; t++) {
            int row = arow + t * 64;
            int gr  = row0 + row;
            uint32_t sz = (gr < n) ? 16u : 0u;
            size_t off = (gr < n) ? ((size_t)gr * dh + kof + ach) : 0;
            uint32_t d = uA + buf * 10240 + (row * 20 + ach) * 4;
            cpasync16(d,         Ah2 + off, sz);
            cpasync16(d + 20480, Al2 + off, sz);
        }
        {
            int row = tid >> 2;
            size_t off = (size_t)(col0B + row) * dh + kof + ach;
            uint32_t d = uB + buf * 5120 + (row * 20 + ach) * 4;
            cpasync16(d,         Bh2 + off, 16u);
            cpasync16(d + 10240, Bl2 + off, 16u);
        }
        cpcommit();
    };

    load_tile(0, 0);
    for (int ti = 0; ti < ntiles; ti++) {
        cpwait<0>();
        __syncthreads();
        if (ti + 1 < ntiles) load_tile((ti + 1) & 1, ti + 1);
        const int buf = ti & 1;
        const uint32_t aB = uA + buf * 10240;
        const uint32_t bB = uB + buf * 5120;
#pragma unroll
        for (int ks = 0; ks < 2; ks++) {
            const int kb2 = ks * 8;
            uint32_t afh[2][4], afl[2][4], bh4[2][4], bl4[2][4];
#pragma unroll
            for (int mt = 0; mt < 2; mt++) {
                uint32_t ad = aB + (((wm0 + mt * 16 + (lane & 15)) * 20 + kb2 +
                                     ((lane >> 4) << 2)) << 2);
                LDSM4(afh[mt], ad);
                LDSM4(afl[mt], ad + 20480);
            }
            // B: m16n16 LDSM4 covers two adjacent n8 tiles per issue
#pragma unroll
            for (int ntp = 0; ntp < 2; ntp++) {
                int nrow = wn0 + ntp * 16 + (lane & 7) + ((lane >> 4) << 3);
                int koff = kb2 + (((lane >> 3) & 1) << 2);
                uint32_t bd = bB + ((nrow * 20 + koff) << 2);
                LDSM4(bh4[ntp], bd);
                LDSM4(bl4[ntp], bd + 10240);
            }
#pragma unroll
            for (int mt = 0; mt < 2; mt++)
#pragma unroll
                for (int ntp = 0; ntp < 2; ntp++)
#pragma unroll
                    for (int nb = 0; nb < 2; nb++) {
                        float* d = acc[mt][ntp * 2 + nb];
                        MMA_F16(d, afh[mt], bh4[ntp][nb * 2], bh4[ntp][nb * 2 + 1]);
                        MMA_F16(d, afh[mt], bl4[ntp][nb * 2], bl4[ntp][nb * 2 + 1]);
                        MMA_F16(d, afl[mt], bh4[ntp][nb * 2], bh4[ntp][nb * 2 + 1]);
                    }
        }
    }

    // ---- store: z as half2, res as fp32 ----
#pragma unroll
    for (int mt = 0; mt < 2; mt++) {
#pragma unroll
        for (int nt = 0; nt < 4; nt++) {
            int r  = row0 + wm0 + mt * 16 + grp;
            int cC = col0C + wn0 + nt * 8 + qid * 2;
            if (isres) {
                if (r < n)
                    *(float2*)&Cres[(size_t)r * KH + cC] =
                        make_float2(acc[mt][nt][0], acc[mt][nt][1]);
                if (r + 8 < n)
                    *(float2*)&Cres[(size_t)(r + 8) * KH + cC] =
                        make_float2(acc[mt][nt][2], acc[mt][nt][3]);
            } else {
                if (r < n)
                    zOut[(size_t)r * 128 + (cC >> 1)] = packh2(acc[mt][nt][0], acc[mt][nt][1]);
                if (r + 8 < n)
                    zOut[(size_t)(r + 8) * 128 + (cC >> 1)] = packh2(acc[mt][nt][2], acc[mt][nt][3]);
            }
        }
    }
    // ---- fused attention projections el/er for head bx ----
    if (doattn) {
        const int hd = bx;
        float alv[4][2], arv[4][2];
#pragma unroll
        for (int nt = 0; nt < 4; nt++)
#pragma unroll
            for (int j = 0; j < 2; j++) {
                int c = wn0 + nt * 8 + qid * 2 + j;
                alv[nt][j] = alp[hd * 64 + c];
                arv[nt][j] = arp[hd * 64 + c];
            }
#pragma unroll
        for (int mt = 0; mt < 2; mt++) {
            float ea = 0.f, eb = 0.f, ra = 0.f, rb = 0.f;
#pragma unroll
            for (int nt = 0; nt < 4; nt++) {
                ea += acc[mt][nt][0] * alv[nt][0] + acc[mt][nt][1] * alv[nt][1];
                eb += acc[mt][nt][2] * alv[nt][0] + acc[mt][nt][3] * alv[nt][1];
                ra += acc[mt][nt][0] * arv[nt][0] + acc[mt][nt][1] * arv[nt][1];
                rb += acc[mt][nt][2] * arv[nt][0] + acc[mt][nt][3] * arv[nt][1];
            }
#pragma unroll
            for (int o = 1; o < 4; o <<= 1) {
                ea += __shfl_down_sync(0xffffffffu, ea, o, 4);
                eb += __shfl_down_sync(0xffffffffu, eb, o, 4);
                ra += __shfl_down_sync(0xffffffffu, ra, o, 4);
                rb += __shfl_down_sync(0xffffffffu, rb, o, 4);
            }
            if (qid == 0) {
                int rr = wm0 + mt * 16 + grp;
                int hf = wn0 >> 5;
                sEl[hf][rr] = ea; sEl[hf][rr + 8] = eb;
                sEr[hf][rr] = ra; sEr[hf][rr + 8] = rb;
            }
        }
        __syncthreads();
        if (tid < 128) {
            int gr = row0 + tid;
            if (gr < n) {
                g_el[gr * 4 + hd] = sEl[0][tid] + sEl[1][tid];
                g_er[gr * 4 + hd] = sEr[0][tid] + sEr[1][tid];
            }
        }
    }
}

// ================= fused GAT attention + aggregation + combine (two-pass) ======
__global__ void gat_fused(const uint32_t* __restrict__ zh, const float* __restrict__ res,
                          const float* __restrict__ bias, float* __restrict__ xout,
                          int mode, uint32_t* __restrict__ xh2, uint32_t* __restrict__ xl2) {
    __shared__ float sm[8][256];
    const int wIB  = threadIdx.x >> 5;
    const int n    = (blockIdx.x * blockDim.x + threadIdx.x) >> 5;
    const int lane = threadIdx.x & 31;
    if (n >= NN) return;
    const int r0 = g_rowptr[n];
    const int nE = g_rowptr[n + 1] - r0;
    const float4 erv = *(const float4*)&g_er[n * 4];
    const int myK = lane >> 3;

    float m0 = NEG_INF, m1 = NEG_INF, m2 = NEG_INF, m3 = NEG_INF;
    for (int b = 0; b < nE; b += 32) {
        int idx = b + lane;
        if (idx < nE) {
            int s = g_csrc[r0 + idx];
            float4 l = *(const float4*)&g_el[s * 4];
            m0 = fmaxf(m0, leaky02(l.x + erv.x));
            m1 = fmaxf(m1, leaky02(l.y + erv.y));
            m2 = fmaxf(m2, leaky02(l.z + erv.z));
            m3 = fmaxf(m3, leaky02(l.w + erv.w));
        }
    }
#pragma unroll
    for (int off = 16; off; off >>= 1) {
        m0 = fmaxf(m0, __shfl_xor_sync(0xffffffffu, m0, off));
        m1 = fmaxf(m1, __shfl_xor_sync(0xffffffffu, m1, off));
        m2 = fmaxf(m2, __shfl_xor_sync(0xffffffffu, m2, off));
        m3 = fmaxf(m3, __shfl_xor_sync(0xffffffffu, m3, off));
    }

    float acc[8] = {};
    float sl0 = 0.f, sl1 = 0.f, sl2 = 0.f, sl3 = 0.f;
    for (int b = 0; b < nE; b += 32) {
        int idx = b + lane;
        int cnt = min(32, nE - b);
        float p0 = 0.f, p1 = 0.f, p2 = 0.f, p3 = 0.f;
        int sN = 0;
        if (idx < nE) {
            sN = g_csrc[r0 + idx];
            float4 l = *(const float4*)&g_el[sN * 4];
            p0 = __expf(leaky02(l.x + erv.x) - m0);
            p1 = __expf(leaky02(l.y + erv.y) - m1);
            p2 = __expf(leaky02(l.z + erv.z) - m2);
            p3 = __expf(leaky02(l.w + erv.w) - m3);
            sl0 += p0; sl1 += p1; sl2 += p2; sl3 += p3;
        }
        int i = 0;
        for (; i + 4 <= cnt; i += 4) {
            int ss[4]; float pa[4];
#pragma unroll
            for (int j = 0; j < 4; j++) {
                ss[j] = __shfl_sync(0xffffffffu, sN, i + j);
                float q0 = __shfl_sync(0xffffffffu, p0, i + j);
                float q1 = __shfl_sync(0xffffffffu, p1, i + j);
                float q2 = __shfl_sync(0xffffffffu, p2, i + j);
                float q3 = __shfl_sync(0xffffffffu, p3, i + j);
                pa[j] = (myK == 0) ? q0 : (myK == 1) ? q1 : (myK == 2) ? q2 : q3;
            }
            uint4 zv[4];
#pragma unroll
            for (int j = 0; j < 4; j++)
                zv[j] = *(const uint4*)(zh + (size_t)ss[j] * 128 + lane * 4);
#pragma unroll
            for (int j = 0; j < 4; j++) {
                float2 f0 = __half22float2(*(__half2*)&zv[j].x);
                float2 f1 = __half22float2(*(__half2*)&zv[j].y);
                float2 f2 = __half22float2(*(__half2*)&zv[j].z);
                float2 f3 = __half22float2(*(__half2*)&zv[j].w);
                acc[0] += pa[j] * f0.x; acc[1] += pa[j] * f0.y;
                acc[2] += pa[j] * f1.x; acc[3] += pa[j] * f1.y;
                acc[4] += pa[j] * f2.x; acc[5] += pa[j] * f2.y;
                acc[6] += pa[j] * f3.x; acc[7] += pa[j] * f3.y;
            }
        }
        for (; i < cnt; i++) {
            int ss   = __shfl_sync(0xffffffffu, sN, i);
            float q0 = __shfl_sync(0xffffffffu, p0, i);
            float q1 = __shfl_sync(0xffffffffu, p1, i);
            float q2 = __shfl_sync(0xffffffffu, p2, i);
            float q3 = __shfl_sync(0xffffffffu, p3, i);
            float pa = (myK == 0) ? q0 : (myK == 1) ? q1 : (myK == 2) ? q2 : q3;
            uint4 zv = *(const uint4*)(zh + (size_t)ss * 128 + lane * 4);
            float2 f0 = __half22float2(*(__half2*)&zv.x);
            float2 f1 = __half22float2(*(__half2*)&zv.y);
            float2 f2 = __half22float2(*(__half2*)&zv.z);
            float2 f3 = __half22float2(*(__half2*)&zv.w);
            acc[0] += pa * f0.x; acc[1] += pa * f0.y;
            acc[2] += pa * f1.x; acc[3] += pa * f1.y;
            acc[4] += pa * f2.x; acc[5] += pa * f2.y;
            acc[6] += pa * f3.x; acc[7] += pa * f3.y;
        }
    }
#pragma unroll
    for (int off = 16; off; off >>= 1) {
        sl0 += __shfl_xor_sync(0xffffffffu, sl0, off);
        sl1 += __shfl_xor_sync(0xffffffffu, sl1, off);
        sl2 += __shfl_xor_sync(0xffffffffu, sl2, off);
        sl3 += __shfl_xor_sync(0xffffffffu, sl3, off);
    }
    float sk = (myK == 0) ? sl0 : (myK == 1) ? sl1 : (myK == 2) ? sl2 : sl3;
    float inv = (nE > 0) ? (1.0f / sk) : 0.0f;

    const int base = n * KH + lane * 8;
    float v[8];
    const float4* rp = (const float4*)(res + base);
    const float4* bp = (const float4*)(bias + lane * 8);
    float4 r4a = rp[0], r4b = rp[1], b4a = bp[0], b4b = bp[1];
    v[0] = acc[0] * inv + r4a.x + b4a.x; v[1] = acc[1] * inv + r4a.y + b4a.y;
    v[2] = acc[2] * inv + r4a.z + b4a.z; v[3] = acc[3] * inv + r4a.w + b4a.w;
    v[4] = acc[4] * inv + r4b.x + b4b.x; v[5] = acc[5] * inv + r4b.y + b4b.y;
    v[6] = acc[6] * inv + r4b.z + b4b.z; v[7] = acc[7] * inv + r4b.w + b4b.w;
#pragma unroll
    for (int j = 0; j < 8; j++) v[j] = v[j] > 0.f ? v[j] : 0.f;

    if (mode == 0) {
        float4* op = (float4*)(xout + base);
        op[0] = make_float4(v[0], v[1], v[2], v[3]);
        op[1] = make_float4(v[4], v[5], v[6], v[7]);
        uint32_t oh[4], ol[4];
        splitpack(v[0], v[1], oh[0], ol[0]);
        splitpack(v[2], v[3], oh[1], ol[1]);
        splitpack(v[4], v[5], oh[2], ol[2]);
        splitpack(v[6], v[7], oh[3], ol[3]);
        *(uint4*)&xh2[(size_t)n * 128 + lane * 4] = make_uint4(oh[0], oh[1], oh[2], oh[3]);
        *(uint4*)&xl2[(size_t)n * 128 + lane * 4] = make_uint4(ol[0], ol[1], ol[2], ol[3]);
    } else {
#pragma unroll
        for (int j = 0; j < 8; j++) sm[wIB][lane * 8 + j] = v[j];
        __syncwarp();
        float h0 = (sm[wIB][lane]       + sm[wIB][64 + lane] +
                    sm[wIB][128 + lane] + sm[wIB][192 + lane]) * 0.25f;
        float h1 = (sm[wIB][32 + lane]  + sm[wIB][96 + lane] +
                    sm[wIB][160 + lane] + sm[wIB][224 + lane]) * 0.25f;
        g_x3[n * 64 + lane]      = h0;
        g_x3[n * 64 + lane + 32] = h1;
    }
}

// ================= readout + MLP =================
__global__ void readout(const int* __restrict__ gid, const float* __restrict__ Wg,
                        const float* __restrict__ bg) {
    int w    = (blockIdx.x * blockDim.x + threadIdx.x) >> 5;
    int lane = threadIdx.x & 31;
    if (w >= NN) return;
    int g = gid[w];
    const float* xr = g_x3 + (size_t)w * 64;
    float x0 = xr[lane], x1 = xr[lane + 32];
    float p = x0 * Wg[lane] + x1 * Wg[lane + 32];
#pragma unroll
    for (int off = 16; off; off >>= 1) p += __shfl_down_sync(0xffffffffu, p, off);
    p = __shfl_sync(0xffffffffu, p, 0);
    float wgt = 1.0f / (1.0f + expf(-(p + bg[0])));
    atomicAdd(&g_gs[g * 64 + lane],      wgt * x0);
    atomicAdd(&g_gs[g * 64 + lane + 32], wgt * x1);
    atomicMaxF(&g_gm[g * 64 + lane],      x0);
    atomicMaxF(&g_gm[g * 64 + lane + 32], x1);
}
__global__ void mlp_head(const float* __restrict__ Wm1, const float* __restrict__ bm1,
                         const float* __restrict__ bn_g, const float* __restrict__ bn_b,
                         const float* __restrict__ bn_m, const float* __restrict__ bn_v,
                         const float* __restrict__ Wm2, const float* __restrict__ bm2,
                         float* __restrict__ out) {
    int g = blockIdx.x, j = threadIdx.x;
    __shared__ float gf[128];
    gf[j]      = g_gs[g * 64 + j];
    gf[j + 64] = g_gm[g * 64 + j];
    __syncthreads();
    float acc = bm1[j];
#pragma unroll 8
    for (int i = 0; i < 128; i++) acc += gf[i] * Wm1[i * 64 + j];
    float y = acc > 0.0f ? acc : 0.0f;
    y = (y - bn_m[j]) * rsqrtf(bn_v[j] + 1e-5f) * bn_g[j] + bn_b[j];
    __shared__ float red[64];
    red[j] = y * Wm2[j];
    __syncthreads();
    if (j == 0) {
        float t = 0.0f;
#pragma unroll
        for (int i = 0; i < 64; i++) t += red[i];
        out[g] = 1.0f / (1.0f + expf(-(t + bm2[0])));
    }
}

// ================= host launcher =================
extern "C" void kernel_launch(void* const* d_in, const int* in_sizes, int n_in,
                              void* d_out, int out_size) {
    (void)in_sizes; (void)n_in; (void)out_size;
    const float* h     = (const float*)d_in[0];
    const int*   src   = (const int*)d_in[1];
    const int*   dst   = (const int*)d_in[2];
    const int*   gid   = (const int*)d_in[3];
    const float* W0    = (const float*)d_in[4];
    const float* al0   = (const float*)d_in[5];
    const float* ar0   = (const float*)d_in[6];
    const float* b0    = (const float*)d_in[7];
    const float* resW0 = (const float*)d_in[8];
    const float* W1    = (const float*)d_in[9];
    const float* al1   = (const float*)d_in[10];
    const float* ar1   = (const float*)d_in[11];
    const float* b1    = (const float*)d_in[12];
    const float* W2    = (const float*)d_in[13];
    const float* al2   = (const float*)d_in[14];
    const float* ar2   = (const float*)d_in[15];
    const float* b2    = (const float*)d_in[16];
    const float* Wg    = (const float*)d_in[17];
    const float* bg    = (const float*)d_in[18];
    const float* Wm1   = (const float*)d_in[19];
    const float* bm1   = (const float*)d_in[20];
    const float* bng   = (const float*)d_in[21];
    const float* bnb   = (const float*)d_in[22];
    const float* bnm   = (const float*)d_in[23];
    const float* bnv   = (const float*)d_in[24];
    const float* Wm2   = (const float*)d_in[25];
    const float* bm2   = (const float*)d_in[26];

    float *p_res, *p_x;
    uint32_t *p_zh, *p_hh2, *p_hl2, *p_xh2, *p_xl2, *p_wh, *p_wl;
    cudaGetSymbolAddress((void**)&p_zh,  g_zh);
    cudaGetSymbolAddress((void**)&p_res, g_res);
    cudaGetSymbolAddress((void**)&p_x,   g_x);
    cudaGetSymbolAddress((void**)&p_hh2, g_hh2);
    cudaGetSymbolAddress((void**)&p_hl2, g_hl2);
    cudaGetSymbolAddress((void**)&p_xh2, g_xh2);
    cudaGetSymbolAddress((void**)&p_xl2, g_xl2);
    cudaGetSymbolAddress((void**)&p_wh,  g_wh);
    cudaGetSymbolAddress((void**)&p_wl,  g_wl);

    const int SMEM_GEMM = 61440;
    cudaFuncSetAttribute(gemm_h3, cudaFuncAttributeMaxDynamicSharedMemorySize, SMEM_GEMM);

    const int edgeB  = (EE + 255) / 256;
    const int nWarpB = (NN + 7) / 8;

    // ---- pre-split + init ----
    hsplit<<<(NN * 64 + 255) / 256, 256>>>(h);
    wsplit_all<<<(98304 + 255) / 256, 256>>>(W0, resW0, W1, W2);

    // ---- Layer 0 GEMMs merged (z + res in one launch) ----
    gemm_h3<<<dim3(8, (NN + 127) / 128), 256, SMEM_GEMM>>>(
        p_hh2, p_hl2, p_wh, p_wl, p_zh, p_res, NN, FF, al0, ar0);

    // ---- CSR build ----
    csr_hist<<<edgeB, 256>>>(dst);
    csr_scan<<<1, 1024>>>();
    csr_fill_k<<<edgeB, 256>>>(src, dst);

    // ---- Layer 0 combine ----
    gat_fused<<<nWarpB, 256>>>(p_zh, p_res, b0, p_x, 0, p_xh2, p_xl2);

    // ---- Layer 1 ----
    gemm_h3<<<dim3(4, (NN + 127) / 128), 256, SMEM_GEMM>>>(
        p_xh2, p_xl2, p_wh + 32768, p_wl + 32768, p_zh, nullptr, NN, KH, al1, ar1);
    gat_fused<<<nWarpB, 256>>>(p_zh, p_x, b1, p_x, 0, p_xh2, p_xl2);

    // ---- Layer 2 ----
    gemm_h3<<<dim3(4, (NN + 127) / 128), 256, SMEM_GEMM>>>(
        p_xh2, p_xl2, p_wh + 65536, p_wl + 65536, p_zh, nullptr, NN, KH, al2, ar2);
    gat_fused<<<nWarpB, 256>>>(p_zh, p_x, b2, nullptr, 1, nullptr, nullptr);

    // ---- Readout + MLP ----
    readout<<<nWarpB, 256>>>(gid, Wg, bg);
    mlp_head<<<GG, 64>>>(Wm1, bm1, bng, bnb, bnm, bnv, Wm2, bm2, (float*)d_out);
}

// round 15
// speedup vs baseline: 1.4009x; 1.1382x over previous
#include <cuda_runtime.h>
#include <cuda_fp16.h>
#include <math.h>
#include <stdint.h>

#define NN 50000
#define EE 400000
#define GG 512
#define FF 128
#define KK 4
#define HH 64
#define KH 256   // K*H
#define NEG_INF __int_as_float(0xff800000)

// ---------------- device scratch (static, no runtime allocation) ----------------
__device__ uint32_t g_zh[NN * 128];  // z as half2 [N][128]
__device__ float g_res[NN * KH];
__device__ float g_x[NN * KH];
__device__ float g_el[NN * KK];
__device__ float g_er[NN * KK];
__device__ float g_x3[NN * HH];
__device__ float g_gs[GG * HH];
__device__ float g_gm[GG * HH];
// fp16 activations (half2 packed along K); weights split hi + lo (UNSCALED)
__device__ uint32_t g_hh2[NN * 64];
__device__ uint32_t g_xh2[NN * 128];
__device__ uint32_t g_wh[98304];   // [n][din/2]: W0@0, resW0@16384, W1@32768, W2@65536
__device__ uint32_t g_wl[98304];
// CSR
__device__ int g_rowptr[NN + 1];
__device__ int g_cnt[NN];
__device__ int g_fill[NN];
__device__ int g_csrc[EE];

__device__ __forceinline__ void atomicMaxF(float* addr, float v) {
    if (v >= 0.0f) atomicMax((int*)addr, __float_as_int(v));
    else           atomicMin((unsigned int*)addr, __float_as_uint(v));
}
__device__ __forceinline__ float leaky02(float v) { return v > 0.0f ? v : 0.2f * v; }

__device__ __forceinline__ void splitpack(float a, float b, uint32_t& hi, uint32_t& lo) {
    __half ha = __float2half_rn(a), hb = __float2half_rn(b);
    __half2 hh = __halves2half2(ha, hb);
    hi = *(uint32_t*)&hh;
    float la = a - __half2float(ha);
    float lb = b - __half2float(hb);
    __half2 hl = __floats2half2_rn(la, lb);
    lo = *(uint32_t*)&hl;
}
__device__ __forceinline__ uint32_t packh2(float a, float b) {
    __half2 v = __floats2half2_rn(a, b);
    return *(uint32_t*)&v;
}

// ================= async-copy / ldmatrix helpers =================
__device__ __forceinline__ uint32_t s2u(const void* p) {
    return (uint32_t)__cvta_generic_to_shared(p);
}
__device__ __forceinline__ void cpasync16(uint32_t dst, const void* src, uint32_t sz) {
    asm volatile("cp.async.cg.shared.global [%0], [%1], 16, %2;"
                 :: "r"(dst), "l"(src), "r"(sz) : "memory");
}
__device__ __forceinline__ void cpcommit() {
    asm volatile("cp.async.commit_group;" ::: "memory");
}
template <int N>
__device__ __forceinline__ void cpwait() {
    asm volatile("cp.async.wait_group %0;" :: "n"(N) : "memory");
}
#define LDSM4(r, a) \
    asm volatile("ldmatrix.sync.aligned.m8n8.x4.shared.b16 {%0,%1,%2,%3}, [%4];" \
                 : "=r"((r)[0]), "=r"((r)[1]), "=r"((r)[2]), "=r"((r)[3]) : "r"(a))
#define MMA_F16(d, a, b0, b1) \
    asm volatile("mma.sync.aligned.m16n8k16.row.col.f32.f16.f16.f32 " \
                 "{%0,%1,%2,%3}, {%4,%5,%6,%7}, {%8,%9}, {%0,%1,%2,%3};" \
                 : "+f"((d)[0]), "+f"((d)[1]), "+f"((d)[2]), "+f"((d)[3]) \
                 : "r"((a)[0]), "r"((a)[1]), "r"((a)[2]), "r"((a)[3]), \
                   "r"(b0), "r"(b1))

// ================= pre-split + init (fused) =================
__global__ void hsplit(const float* __restrict__ h) {
    int idx = blockIdx.x * blockDim.x + threadIdx.x;
    if (idx < NN) { g_cnt[idx] = 0; g_fill[idx] = 0; }
    if (idx < GG * HH) { g_gs[idx] = 0.0f; g_gm[idx] = NEG_INF; }
    if (idx >= NN * 64) return;
    int row = idx >> 6, k2 = idx & 63;
    float2 v = *(const float2*)&h[row * 128 + k2 * 2];
    g_hh2[idx] = packh2(v.x, v.y);
}
__global__ void wsplit_all(const float* __restrict__ W0, const float* __restrict__ resW0,
                           const float* __restrict__ W1, const float* __restrict__ W2) {
    int idx = blockIdx.x * blockDim.x + threadIdx.x;
    if (idx >= 98304) return;
    const float* W; int off, dh, lid;
    if (idx < 16384)      { W = W0;    off = 0;     dh = 64;  lid = idx; }
    else if (idx < 32768) { W = resW0; off = 16384; dh = 64;  lid = idx - 16384; }
    else if (idx < 65536) { W = W1;    off = 32768; dh = 128; lid = idx - 32768; }
    else                  { W = W2;    off = 65536; dh = 128; lid = idx - 65536; }
    int nn = lid & 255, k2 = lid >> 8;
    float v0 = W[(2 * k2) * 256 + nn];
    float v1 = W[(2 * k2 + 1) * 256 + nn];
    splitpack(v0, v1, g_wh[off + nn * dh + k2], g_wl[off + nn * dh + k2]);
}

// ================= CSR build =================
__global__ void csr_hist(const int* __restrict__ dst) {
    int e = blockIdx.x * blockDim.x + threadIdx.x;
    if (e < EE) atomicAdd(&g_cnt[dst[e]], 1);
}
__global__ void csr_scan() {
    __shared__ int smW[32];
    __shared__ int sOff;
    int tid = threadIdx.x, lane = tid & 31, wid = tid >> 5;
    if (tid == 0) sOff = 0;
    __syncthreads();
    for (int base = 0; base < NN; base += 1024) {
        int i = base + tid;
        int v = (i < NN) ? g_cnt[i] : 0;
        int inc = v;
#pragma unroll
        for (int o = 1; o < 32; o <<= 1) {
            int t = __shfl_up_sync(0xffffffffu, inc, o);
            if (lane >= o) inc += t;
        }
        if (lane == 31) smW[wid] = inc;
        __syncthreads();
        if (wid == 0) {
            int t = smW[lane];
#pragma unroll
            for (int o = 1; o < 32; o <<= 1) {
                int u = __shfl_up_sync(0xffffffffu, t, o);
                if (lane >= o) t += u;
            }
            smW[lane] = t;
        }
        __syncthreads();
        int warpOff = wid ? smW[wid - 1] : 0;
        if (i < NN) g_rowptr[i] = sOff + warpOff + inc - v;
        int blockTot = smW[31];
        __syncthreads();
        if (tid == 0) sOff += blockTot;
        __syncthreads();
    }
    if (tid == 0) g_rowptr[NN] = sOff;
}
__global__ void csr_fill_k(const int* __restrict__ src, const int* __restrict__ dst) {
    int e = blockIdx.x * blockDim.x + threadIdx.x;
    if (e >= EE) return;
    int d = dst[e];
    int pos = g_rowptr[d] + atomicAdd(&g_fill[d], 1);
    g_csrc[pos] = src[e];
}

// ================= fp16 GEMM, weight-split (128x64, 2-MMA) =====================
// D = Ah*(Bh+Bl); A fp16 activations, B weights split hi/lo.
// smem (40960B): A[2][128][20]@0 (buf stride 10240),
//                Bh[2][64][20]@20480 (buf stride 5120), Bl @ +10240.
__global__ void __launch_bounds__(256, 3) gemm_h3(
        const uint32_t* __restrict__ Ah2,
        const uint32_t* __restrict__ Bh2, const uint32_t* __restrict__ Bl2,
        uint32_t* __restrict__ zOut, float* __restrict__ Cres, int n, int din,
        const float* __restrict__ alp, const float* __restrict__ arp) {
    extern __shared__ __align__(16) uint8_t smx[];
    __shared__ float sEl[2][128], sEr[2][128];
    const int tid  = threadIdx.x;
    const int wid  = tid >> 5;
    const int lane = tid & 31;
    const int bx   = blockIdx.x;
    const bool isres = (Cres != nullptr) && (bx >= 4);
    const int row0  = blockIdx.y * 128;
    const int col0B = bx * 64;
    const int col0C = isres ? (bx - 4) * 64 : bx * 64;
    const bool doattn = (alp != nullptr) && !isres;
    const int wm0  = (wid >> 1) * 32;
    const int wn0  = (wid & 1) * 32;
    const int grp  = lane >> 2;
    const int qid  = lane & 3;
    const int dh   = din >> 1;
    const int ntiles = dh >> 4;

    const uint32_t uA = s2u(smx);
    const uint32_t uB = uA + 20480;

    float acc[2][4][4] = {};

    const int arow = tid >> 2;
    const int ach  = (tid & 3) * 4;

    auto load_tile = [&](int buf, int tile) {
        const int kof = tile * 16;
#pragma unroll
        for (int t = 0; t < 2; t++) {
            int row = arow + t * 64;
            int gr  = row0 + row;
            uint32_t sz = (gr < n) ? 16u : 0u;
            size_t off = (gr < n) ? ((size_t)gr * dh + kof + ach) : 0;
            cpasync16(uA + buf * 10240 + (row * 20 + ach) * 4, Ah2 + off, sz);
        }
        {
            int row = tid >> 2;
            size_t off = (size_t)(col0B + row) * dh + kof + ach;
            uint32_t d = uB + buf * 5120 + (row * 20 + ach) * 4;
            cpasync16(d,         Bh2 + off, 16u);
            cpasync16(d + 10240, Bl2 + off, 16u);
        }
        cpcommit();
    };

    load_tile(0, 0);
    for (int ti = 0; ti < ntiles; ti++) {
        cpwait<0>();
        __syncthreads();
        if (ti + 1 < ntiles) load_tile((ti + 1) & 1, ti + 1);
        const int buf = ti & 1;
        const uint32_t aB = uA + buf * 10240;
        const uint32_t bB = uB + buf * 5120;
#pragma unroll
        for (int ks = 0; ks < 2; ks++) {
            const int kb2 = ks * 8;
            uint32_t afh[2][4], bh4[2][4], bl4[2][4];
#pragma unroll
            for (int mt = 0; mt < 2; mt++) {
                uint32_t ad = aB + (((wm0 + mt * 16 + (lane & 15)) * 20 + kb2 +
                                     ((lane >> 4) << 2)) << 2);
                LDSM4(afh[mt], ad);
            }
#pragma unroll
            for (int ntp = 0; ntp < 2; ntp++) {
                int nrow = wn0 + ntp * 16 + (lane & 7) + ((lane >> 4) << 3);
                int koff = kb2 + (((lane >> 3) & 1) << 2);
                uint32_t bd = bB + ((nrow * 20 + koff) << 2);
                LDSM4(bh4[ntp], bd);
                LDSM4(bl4[ntp], bd + 10240);
            }
#pragma unroll
            for (int mt = 0; mt < 2; mt++)
#pragma unroll
                for (int ntp = 0; ntp < 2; ntp++)
#pragma unroll
                    for (int nb = 0; nb < 2; nb++) {
                        float* d = acc[mt][ntp * 2 + nb];
                        MMA_F16(d, afh[mt], bh4[ntp][nb * 2], bh4[ntp][nb * 2 + 1]);
                        MMA_F16(d, afh[mt], bl4[ntp][nb * 2], bl4[ntp][nb * 2 + 1]);
                    }
        }
    }

    // ---- store: z as half2, res as fp32 ----
#pragma unroll
    for (int mt = 0; mt < 2; mt++) {
#pragma unroll
        for (int nt = 0; nt < 4; nt++) {
            int r  = row0 + wm0 + mt * 16 + grp;
            int cC = col0C + wn0 + nt * 8 + qid * 2;
            if (isres) {
                if (r < n)
                    *(float2*)&Cres[(size_t)r * KH + cC] =
                        make_float2(acc[mt][nt][0], acc[mt][nt][1]);
                if (r + 8 < n)
                    *(float2*)&Cres[(size_t)(r + 8) * KH + cC] =
                        make_float2(acc[mt][nt][2], acc[mt][nt][3]);
            } else {
                if (r < n)
                    zOut[(size_t)r * 128 + (cC >> 1)] = packh2(acc[mt][nt][0], acc[mt][nt][1]);
                if (r + 8 < n)
                    zOut[(size_t)(r + 8) * 128 + (cC >> 1)] = packh2(acc[mt][nt][2], acc[mt][nt][3]);
            }
        }
    }
    // ---- fused attention projections el/er for head bx ----
    if (doattn) {
        const int hd = bx;
        float alv[4][2], arv[4][2];
#pragma unroll
        for (int nt = 0; nt < 4; nt++)
#pragma unroll
            for (int j = 0; j < 2; j++) {
                int c = wn0 + nt * 8 + qid * 2 + j;
                alv[nt][j] = alp[hd * 64 + c];
                arv[nt][j] = arp[hd * 64 + c];
            }
#pragma unroll
        for (int mt = 0; mt < 2; mt++) {
            float ea = 0.f, eb = 0.f, ra = 0.f, rb = 0.f;
#pragma unroll
            for (int nt = 0; nt < 4; nt++) {
                ea += acc[mt][nt][0] * alv[nt][0] + acc[mt][nt][1] * alv[nt][1];
                eb += acc[mt][nt][2] * alv[nt][0] + acc[mt][nt][3] * alv[nt][1];
                ra += acc[mt][nt][0] * arv[nt][0] + acc[mt][nt][1] * arv[nt][1];
                rb += acc[mt][nt][2] * arv[nt][0] + acc[mt][nt][3] * arv[nt][1];
            }
#pragma unroll
            for (int o = 1; o < 4; o <<= 1) {
                ea += __shfl_down_sync(0xffffffffu, ea, o, 4);
                eb += __shfl_down_sync(0xffffffffu, eb, o, 4);
                ra += __shfl_down_sync(0xffffffffu, ra, o, 4);
                rb += __shfl_down_sync(0xffffffffu, rb, o, 4);
            }
            if (qid == 0) {
                int rr = wm0 + mt * 16 + grp;
                int hf = wn0 >> 5;
                sEl[hf][rr] = ea; sEl[hf][rr + 8] = eb;
                sEr[hf][rr] = ra; sEr[hf][rr + 8] = rb;
            }
        }
        __syncthreads();
        if (tid < 128) {
            int gr = row0 + tid;
            if (gr < n) {
                g_el[gr * 4 + hd] = sEl[0][tid] + sEl[1][tid];
                g_er[gr * 4 + hd] = sEr[0][tid] + sEr[1][tid];
            }
        }
    }
}

// ================= fused GAT attention + aggregation + combine (two-pass) ======
__global__ void gat_fused(const uint32_t* __restrict__ zh, const float* __restrict__ res,
                          const float* __restrict__ bias, float* __restrict__ xout,
                          int mode, uint32_t* __restrict__ xh2) {
    __shared__ float sm[8][256];
    const int wIB  = threadIdx.x >> 5;
    const int n    = (blockIdx.x * blockDim.x + threadIdx.x) >> 5;
    const int lane = threadIdx.x & 31;
    if (n >= NN) return;
    const int r0 = g_rowptr[n];
    const int nE = g_rowptr[n + 1] - r0;
    const float4 erv = *(const float4*)&g_er[n * 4];
    const int myK = lane >> 3;

    float m0 = NEG_INF, m1 = NEG_INF, m2 = NEG_INF, m3 = NEG_INF;
    for (int b = 0; b < nE; b += 32) {
        int idx = b + lane;
        if (idx < nE) {
            int s = g_csrc[r0 + idx];
            float4 l = *(const float4*)&g_el[s * 4];
            m0 = fmaxf(m0, leaky02(l.x + erv.x));
            m1 = fmaxf(m1, leaky02(l.y + erv.y));
            m2 = fmaxf(m2, leaky02(l.z + erv.z));
            m3 = fmaxf(m3, leaky02(l.w + erv.w));
        }
    }
#pragma unroll
    for (int off = 16; off; off >>= 1) {
        m0 = fmaxf(m0, __shfl_xor_sync(0xffffffffu, m0, off));
        m1 = fmaxf(m1, __shfl_xor_sync(0xffffffffu, m1, off));
        m2 = fmaxf(m2, __shfl_xor_sync(0xffffffffu, m2, off));
        m3 = fmaxf(m3, __shfl_xor_sync(0xffffffffu, m3, off));
    }

    float acc[8] = {};
    float sl0 = 0.f, sl1 = 0.f, sl2 = 0.f, sl3 = 0.f;
    for (int b = 0; b < nE; b += 32) {
        int idx = b + lane;
        int cnt = min(32, nE - b);
        float p0 = 0.f, p1 = 0.f, p2 = 0.f, p3 = 0.f;
        int sN = 0;
        if (idx < nE) {
            sN = g_csrc[r0 + idx];
            float4 l = *(const float4*)&g_el[sN * 4];
            p0 = __expf(leaky02(l.x + erv.x) - m0);
            p1 = __expf(leaky02(l.y + erv.y) - m1);
            p2 = __expf(leaky02(l.z + erv.z) - m2);
            p3 = __expf(leaky02(l.w + erv.w) - m3);
            sl0 += p0; sl1 += p1; sl2 += p2; sl3 += p3;
        }
        int i = 0;
        for (; i + 4 <= cnt; i += 4) {
            int ss[4]; float pa[4];
#pragma unroll
            for (int j = 0; j < 4; j++) {
                ss[j] = __shfl_sync(0xffffffffu, sN, i + j);
                float q0 = __shfl_sync(0xffffffffu, p0, i + j);
                float q1 = __shfl_sync(0xffffffffu, p1, i + j);
                float q2 = __shfl_sync(0xffffffffu, p2, i + j);
                float q3 = __shfl_sync(0xffffffffu, p3, i + j);
                pa[j] = (myK == 0) ? q0 : (myK == 1) ? q1 : (myK == 2) ? q2 : q3;
            }
            uint4 zv[4];
#pragma unroll
            for (int j = 0; j < 4; j++)
                zv[j] = *(const uint4*)(zh + (size_t)ss[j] * 128 + lane * 4);
#pragma unroll
            for (int j = 0; j < 4; j++) {
                float2 f0 = __half22float2(*(__half2*)&zv[j].x);
                float2 f1 = __half22float2(*(__half2*)&zv[j].y);
                float2 f2 = __half22float2(*(__half2*)&zv[j].z);
                float2 f3 = __half22float2(*(__half2*)&zv[j].w);
                acc[0] += pa[j] * f0.x; acc[1] += pa[j] * f0.y;
                acc[2] += pa[j] * f1.x; acc[3] += pa[j] * f1.y;
                acc[4] += pa[j] * f2.x; acc[5] += pa[j] * f2.y;
                acc[6] += pa[j] * f3.x; acc[7] += pa[j] * f3.y;
            }
        }
        for (; i < cnt; i++) {
            int ss   = __shfl_sync(0xffffffffu, sN, i);
            float q0 = __shfl_sync(0xffffffffu, p0, i);
            float q1 = __shfl_sync(0xffffffffu, p1, i);
            float q2 = __shfl_sync(0xffffffffu, p2, i);
            float q3 = __shfl_sync(0xffffffffu, p3, i);
            float pa = (myK == 0) ? q0 : (myK == 1) ? q1 : (myK == 2) ? q2 : q3;
            uint4 zv = *(const uint4*)(zh + (size_t)ss * 128 + lane * 4);
            float2 f0 = __half22float2(*(__half2*)&zv.x);
            float2 f1 = __half22float2(*(__half2*)&zv.y);
            float2 f2 = __half22float2(*(__half2*)&zv.z);
            float2 f3 = __half22float2(*(__half2*)&zv.w);
            acc[0] += pa * f0.x; acc[1] += pa * f0.y;
            acc[2] += pa * f1.x; acc[3] += pa * f1.y;
            acc[4] += pa * f2.x; acc[5] += pa * f2.y;
            acc[6] += pa * f3.x; acc[7] += pa * f3.y;
        }
    }
#pragma unroll
    for (int off = 16; off; off >>= 1) {
        sl0 += __shfl_xor_sync(0xffffffffu, sl0, off);
        sl1 += __shfl_xor_sync(0xffffffffu, sl1, off);
        sl2 += __shfl_xor_sync(0xffffffffu, sl2, off);
        sl3 += __shfl_xor_sync(0xffffffffu, sl3, off);
    }
    float sk = (myK == 0) ? sl0 : (myK == 1) ? sl1 : (myK == 2) ? sl2 : sl3;
    float inv = (nE > 0) ? (1.0f / sk) : 0.0f;

    const int base = n * KH + lane * 8;
    float v[8];
    const float4* rp = (const float4*)(res + base);
    const float4* bp = (const float4*)(bias + lane * 8);
    float4 r4a = rp[0], r4b = rp[1], b4a = bp[0], b4b = bp[1];
    v[0] = acc[0] * inv + r4a.x + b4a.x; v[1] = acc[1] * inv + r4a.y + b4a.y;
    v[2] = acc[2] * inv + r4a.z + b4a.z; v[3] = acc[3] * inv + r4a.w + b4a.w;
    v[4] = acc[4] * inv + r4b.x + b4b.x; v[5] = acc[5] * inv + r4b.y + b4b.y;
    v[6] = acc[6] * inv + r4b.z + b4b.z; v[7] = acc[7] * inv + r4b.w + b4b.w;
#pragma unroll
    for (int j = 0; j < 8; j++) v[j] = v[j] > 0.f ? v[j] : 0.f;

    if (mode == 0) {
        float4* op = (float4*)(xout + base);
        op[0] = make_float4(v[0], v[1], v[2], v[3]);
        op[1] = make_float4(v[4], v[5], v[6], v[7]);
        *(uint4*)&xh2[(size_t)n * 128 + lane * 4] =
            make_uint4(packh2(v[0], v[1]), packh2(v[2], v[3]),
                       packh2(v[4], v[5]), packh2(v[6], v[7]));
    } else {
#pragma unroll
        for (int j = 0; j < 8; j++) sm[wIB][lane * 8 + j] = v[j];
        __syncwarp();
        float h0 = (sm[wIB][lane]       + sm[wIB][64 + lane] +
                    sm[wIB][128 + lane] + sm[wIB][192 + lane]) * 0.25f;
        float h1 = (sm[wIB][32 + lane]  + sm[wIB][96 + lane] +
                    sm[wIB][160 + lane] + sm[wIB][224 + lane]) * 0.25f;
        g_x3[n * 64 + lane]      = h0;
        g_x3[n * 64 + lane + 32] = h1;
    }
}

// ================= readout + MLP =================
__global__ void readout(const int* __restrict__ gid, const float* __restrict__ Wg,
                        const float* __restrict__ bg) {
    int w    = (blockIdx.x * blockDim.x + threadIdx.x) >> 5;
    int lane = threadIdx.x & 31;
    if (w >= NN) return;
    int g = gid[w];
    const float* xr = g_x3 + (size_t)w * 64;
    float x0 = xr[lane], x1 = xr[lane + 32];
    float p = x0 * Wg[lane] + x1 * Wg[lane + 32];
#pragma unroll
    for (int off = 16; off; off >>= 1) p += __shfl_down_sync(0xffffffffu, p, off);
    p = __shfl_sync(0xffffffffu, p, 0);
    float wgt = 1.0f / (1.0f + expf(-(p + bg[0])));
    atomicAdd(&g_gs[g * 64 + lane],      wgt * x0);
    atomicAdd(&g_gs[g * 64 + lane + 32], wgt * x1);
    atomicMaxF(&g_gm[g * 64 + lane],      x0);
    atomicMaxF(&g_gm[g * 64 + lane + 32], x1);
}
__global__ void mlp_head(const float* __restrict__ Wm1, const float* __restrict__ bm1,
                         const float* __restrict__ bn_g, const float* __restrict__ bn_b,
                         const float* __restrict__ bn_m, const float* __restrict__ bn_v,
                         const float* __restrict__ Wm2, const float* __restrict__ bm2,
                         float* __restrict__ out) {
    int g = blockIdx.x, j = threadIdx.x;
    __shared__ float gf[128];
    gf[j]      = g_gs[g * 64 + j];
    gf[j + 64] = g_gm[g * 64 + j];
    __syncthreads();
    float acc = bm1[j];
#pragma unroll 8
    for (int i = 0; i < 128; i++) acc += gf[i] * Wm1[i * 64 + j];
    float y = acc > 0.0f ? acc : 0.0f;
    y = (y - bn_m[j]) * rsqrtf(bn_v[j] + 1e-5f) * bn_g[j] + bn_b[j];
    __shared__ float red[64];
    red[j] = y * Wm2[j];
    __syncthreads();
    if (j == 0) {
        float t = 0.0f;
#pragma unroll
        for (int i = 0; i < 64; i++) t += red[i];
        out[g] = 1.0f / (1.0f + expf(-(t + bm2[0])));
    }
}

// ================= host launcher =================
extern "C" void kernel_launch(void* const* d_in, const int* in_sizes, int n_in,
                              void* d_out, int out_size) {
    (void)in_sizes; (void)n_in; (void)out_size;
    const float* h     = (const float*)d_in[0];
    const int*   src   = (const int*)d_in[1];
    const int*   dst   = (const int*)d_in[2];
    const int*   gid   = (const int*)d_in[3];
    const float* W0    = (const float*)d_in[4];
    const float* al0   = (const float*)d_in[5];
    const float* ar0   = (const float*)d_in[6];
    const float* b0    = (const float*)d_in[7];
    const float* resW0 = (const float*)d_in[8];
    const float* W1    = (const float*)d_in[9];
    const float* al1   = (const float*)d_in[10];
    const float* ar1   = (const float*)d_in[11];
    const float* b1    = (const float*)d_in[12];
    const float* W2    = (const float*)d_in[13];
    const float* al2   = (const float*)d_in[14];
    const float* ar2   = (const float*)d_in[15];
    const float* b2    = (const float*)d_in[16];
    const float* Wg    = (const float*)d_in[17];
    const float* bg    = (const float*)d_in[18];
    const float* Wm1   = (const float*)d_in[19];
    const float* bm1   = (const float*)d_in[20];
    const float* bng   = (const float*)d_in[21];
    const float* bnb   = (const float*)d_in[22];
    const float* bnm   = (const float*)d_in[23];
    const float* bnv   = (const float*)d_in[24];
    const float* Wm2   = (const float*)d_in[25];
    const float* bm2   = (const float*)d_in[26];

    float *p_res, *p_x;
    uint32_t *p_zh, *p_hh2, *p_xh2, *p_wh, *p_wl;
    cudaGetSymbolAddress((void**)&p_zh,  g_zh);
    cudaGetSymbolAddress((void**)&p_res, g_res);
    cudaGetSymbolAddress((void**)&p_x,   g_x);
    cudaGetSymbolAddress((void**)&p_hh2, g_hh2);
    cudaGetSymbolAddress((void**)&p_xh2, g_xh2);
    cudaGetSymbolAddress((void**)&p_wh,  g_wh);
    cudaGetSymbolAddress((void**)&p_wl,  g_wl);

    const int SMEM_GEMM = 40960;
    cudaFuncSetAttribute(gemm_h3, cudaFuncAttributeMaxDynamicSharedMemorySize, SMEM_GEMM);

    const int edgeB  = (EE + 255) / 256;
    const int nWarpB = (NN + 7) / 8;

    // ---- pre-split + init ----
    hsplit<<<(NN * 64 + 255) / 256, 256>>>(h);
    wsplit_all<<<(98304 + 255) / 256, 256>>>(W0, resW0, W1, W2);

    // ---- Layer 0 GEMMs merged (z + res in one launch) ----
    gemm_h3<<<dim3(8, (NN + 127) / 128), 256, SMEM_GEMM>>>(
        p_hh2, p_wh, p_wl, p_zh, p_res, NN, FF, al0, ar0);

    // ---- CSR build ----
    csr_hist<<<edgeB, 256>>>(dst);
    csr_scan<<<1, 1024>>>();
    csr_fill_k<<<edgeB, 256>>>(src, dst);

    // ---- Layer 0 combine ----
    gat_fused<<<nWarpB, 256>>>(p_zh, p_res, b0, p_x, 0, p_xh2);

    // ---- Layer 1 ----
    gemm_h3<<<dim3(4, (NN + 127) / 128), 256, SMEM_GEMM>>>(
        p_xh2, p_wh + 32768, p_wl + 32768, p_zh, nullptr, NN, KH, al1, ar1);
    gat_fused<<<nWarpB, 256>>>(p_zh, p_x, b1, p_x, 0, p_xh2);

    // ---- Layer 2 ----
    gemm_h3<<<dim3(4, (NN + 127) / 128), 256, SMEM_GEMM>>>(
        p_xh2, p_wh + 65536, p_wl + 65536, p_zh, nullptr, NN, KH, al2, ar2);
    gat_fused<<<nWarpB, 256>>>(p_zh, p_x, b2, nullptr, 1, nullptr);

    // ---- Readout + MLP ----
    readout<<<nWarpB, 256>>>(gid, Wg, bg);
    mlp_head<<<GG, 64>>>(Wm1, bm1, bng, bnb, bnm, bnv, Wm2, bm2, (float*)d_out);
}

// round 16
// speedup vs baseline: 1.4211x; 1.0144x over previous
#include <cuda_runtime.h>
#include <cuda_fp16.h>
#include <math.h>
#include <stdint.h>

#define NN 50000
#define EE 400000
#define GG 512
#define FF 128
#define KK 4
#define HH 64
#define KH 256   // K*H
#define NEG_INF __int_as_float(0xff800000)

// ---------------- device scratch (static, no runtime allocation) ----------------
__device__ uint32_t g_zh[NN * 128];  // z as half2 [N][128]
__device__ float g_res[NN * KH];
__device__ float g_x[NN * KH];
__device__ float g_el[NN * KK];
__device__ float g_er[NN * KK];
__device__ float g_gs[GG * HH];
__device__ float g_gm[GG * HH];
// fp16 activations (half2 packed along K); weights split hi + lo (UNSCALED)
__device__ uint32_t g_hh2[NN * 64];
__device__ uint32_t g_xh2[NN * 128];
__device__ uint32_t g_wh[98304];   // [n][din/2]: W0@0, resW0@16384, W1@32768, W2@65536
__device__ uint32_t g_wl[98304];
// CSR
__device__ int g_rowptr[NN + 1];
__device__ int g_cnt[NN];
__device__ int g_fill[NN];
__device__ int g_csrc[EE];

__device__ __forceinline__ void atomicMaxF(float* addr, float v) {
    if (v >= 0.0f) atomicMax((int*)addr, __float_as_int(v));
    else           atomicMin((unsigned int*)addr, __float_as_uint(v));
}
__device__ __forceinline__ float leaky02(float v) { return v > 0.0f ? v : 0.2f * v; }

__device__ __forceinline__ void splitpack(float a, float b, uint32_t& hi, uint32_t& lo) {
    __half ha = __float2half_rn(a), hb = __float2half_rn(b);
    __half2 hh = __halves2half2(ha, hb);
    hi = *(uint32_t*)&hh;
    float la = a - __half2float(ha);
    float lb = b - __half2float(hb);
    __half2 hl = __floats2half2_rn(la, lb);
    lo = *(uint32_t*)&hl;
}
__device__ __forceinline__ uint32_t packh2(float a, float b) {
    __half2 v = __floats2half2_rn(a, b);
    return *(uint32_t*)&v;
}

// ================= async-copy / ldmatrix helpers =================
__device__ __forceinline__ uint32_t s2u(const void* p) {
    return (uint32_t)__cvta_generic_to_shared(p);
}
__device__ __forceinline__ void cpasync16(uint32_t dst, const void* src, uint32_t sz) {
    asm volatile("cp.async.cg.shared.global [%0], [%1], 16, %2;"
                 :: "r"(dst), "l"(src), "r"(sz) : "memory");
}
__device__ __forceinline__ void cpcommit() {
    asm volatile("cp.async.commit_group;" ::: "memory");
}
template <int N>
__device__ __forceinline__ void cpwait() {
    asm volatile("cp.async.wait_group %0;" :: "n"(N) : "memory");
}
#define LDSM4(r, a) \
    asm volatile("ldmatrix.sync.aligned.m8n8.x4.shared.b16 {%0,%1,%2,%3}, [%4];" \
                 : "=r"((r)[0]), "=r"((r)[1]), "=r"((r)[2]), "=r"((r)[3]) : "r"(a))
#define MMA_F16(d, a, b0, b1) \
    asm volatile("mma.sync.aligned.m16n8k16.row.col.f32.f16.f16.f32 " \
                 "{%0,%1,%2,%3}, {%4,%5,%6,%7}, {%8,%9}, {%0,%1,%2,%3};" \
                 : "+f"((d)[0]), "+f"((d)[1]), "+f"((d)[2]), "+f"((d)[3]) \
                 : "r"((a)[0]), "r"((a)[1]), "r"((a)[2]), "r"((a)[3]), \
                   "r"(b0), "r"(b1))

// ================= pre-split + init (fused) =================
__global__ void hsplit(const float* __restrict__ h) {
    int idx = blockIdx.x * blockDim.x + threadIdx.x;
    if (idx < NN) g_cnt[idx] = 0;
    if (idx < GG * HH) { g_gs[idx] = 0.0f; g_gm[idx] = NEG_INF; }
    if (idx >= NN * 64) return;
    int row = idx >> 6, k2 = idx & 63;
    float2 v = *(const float2*)&h[row * 128 + k2 * 2];
    g_hh2[idx] = packh2(v.x, v.y);
}
__global__ void wsplit_all(const float* __restrict__ W0, const float* __restrict__ resW0,
                           const float* __restrict__ W1, const float* __restrict__ W2) {
    int idx = blockIdx.x * blockDim.x + threadIdx.x;
    if (idx >= 98304) return;
    const float* W; int off, dh, lid;
    if (idx < 16384)      { W = W0;    off = 0;     dh = 64;  lid = idx; }
    else if (idx < 32768) { W = resW0; off = 16384; dh = 64;  lid = idx - 16384; }
    else if (idx < 65536) { W = W1;    off = 32768; dh = 128; lid = idx - 32768; }
    else                  { W = W2;    off = 65536; dh = 128; lid = idx - 65536; }
    int nn = lid & 255, k2 = lid >> 8;
    float v0 = W[(2 * k2) * 256 + nn];
    float v1 = W[(2 * k2 + 1) * 256 + nn];
    splitpack(v0, v1, g_wh[off + nn * dh + k2], g_wl[off + nn * dh + k2]);
}

// ================= CSR build =================
__global__ void csr_hist(const int* __restrict__ dst) {
    int e = blockIdx.x * blockDim.x + threadIdx.x;
    if (e < EE) atomicAdd(&g_cnt[dst[e]], 1);
}
__global__ void csr_scan() {
    __shared__ int smW[32];
    __shared__ int sOff;
    int tid = threadIdx.x, lane = tid & 31, wid = tid >> 5;
    if (tid == 0) sOff = 0;
    __syncthreads();
    for (int base = 0; base < NN; base += 1024) {
        int i = base + tid;
        int v = (i < NN) ? g_cnt[i] : 0;
        int inc = v;
#pragma unroll
        for (int o = 1; o < 32; o <<= 1) {
            int t = __shfl_up_sync(0xffffffffu, inc, o);
            if (lane >= o) inc += t;
        }
        if (lane == 31) smW[wid] = inc;
        __syncthreads();
        if (wid == 0) {
            int t = smW[lane];
#pragma unroll
            for (int o = 1; o < 32; o <<= 1) {
                int u = __shfl_up_sync(0xffffffffu, t, o);
                if (lane >= o) t += u;
            }
            smW[lane] = t;
        }
        __syncthreads();
        int warpOff = wid ? smW[wid - 1] : 0;
        if (i < NN) {
            int start = sOff + warpOff + inc - v;
            g_rowptr[i] = start;
            g_fill[i]   = start;    // seed fill cursor = row start
        }
        int blockTot = smW[31];
        __syncthreads();
        if (tid == 0) sOff += blockTot;
        __syncthreads();
    }
    if (tid == 0) g_rowptr[NN] = sOff;
}
__global__ void csr_fill_k(const int* __restrict__ src, const int* __restrict__ dst) {
    int e = blockIdx.x * blockDim.x + threadIdx.x;
    if (e >= EE) return;
    int pos = atomicAdd(&g_fill[dst[e]], 1);
    g_csrc[pos] = src[e];
}

// ================= fp16 GEMM, weight-split (128x64, 2-MMA) =====================
// D = Ah*(Bh+Bl); A fp16 activations, B weights split hi/lo.
// smem (40960B): A[2][128][20]@0 (buf stride 10240),
//                Bh[2][64][20]@20480 (buf stride 5120), Bl @ +10240.
__global__ void __launch_bounds__(256, 3) gemm_h3(
        const uint32_t* __restrict__ Ah2,
        const uint32_t* __restrict__ Bh2, const uint32_t* __restrict__ Bl2,
        uint32_t* __restrict__ zOut, float* __restrict__ Cres, int n, int din,
        const float* __restrict__ alp, const float* __restrict__ arp) {
    extern __shared__ __align__(16) uint8_t smx[];
    __shared__ float sEl[2][128], sEr[2][128];
    const int tid  = threadIdx.x;
    const int wid  = tid >> 5;
    const int lane = tid & 31;
    const int bx   = blockIdx.x;
    const bool isres = (Cres != nullptr) && (bx >= 4);
    const int row0  = blockIdx.y * 128;
    const int col0B = bx * 64;
    const int col0C = isres ? (bx - 4) * 64 : bx * 64;
    const bool doattn = (alp != nullptr) && !isres;
    const int wm0  = (wid >> 1) * 32;
    const int wn0  = (wid & 1) * 32;
    const int grp  = lane >> 2;
    const int qid  = lane & 3;
    const int dh   = din >> 1;
    const int ntiles = dh >> 4;

    const uint32_t uA = s2u(smx);
    const uint32_t uB = uA + 20480;

    float acc[2][4][4] = {};

    const int arow = tid >> 2;
    const int ach  = (tid & 3) * 4;

    auto load_tile = [&](int buf, int tile) {
        const int kof = tile * 16;
#pragma unroll
        for (int t = 0; t < 2; t++) {
            int row = arow + t * 64;
            int gr  = row0 + row;
            uint32_t sz = (gr < n) ? 16u : 0u;
            size_t off = (gr < n) ? ((size_t)gr * dh + kof + ach) : 0;
            cpasync16(uA + buf * 10240 + (row * 20 + ach) * 4, Ah2 + off, sz);
        }
        {
            int row = tid >> 2;
            size_t off = (size_t)(col0B + row) * dh + kof + ach;
            uint32_t d = uB + buf * 5120 + (row * 20 + ach) * 4;
            cpasync16(d,         Bh2 + off, 16u);
            cpasync16(d + 10240, Bl2 + off, 16u);
        }
        cpcommit();
    };

    load_tile(0, 0);
    for (int ti = 0; ti < ntiles; ti++) {
        cpwait<0>();
        __syncthreads();
        if (ti + 1 < ntiles) load_tile((ti + 1) & 1, ti + 1);
        const int buf = ti & 1;
        const uint32_t aB = uA + buf * 10240;
        const uint32_t bB = uB + buf * 5120;
#pragma unroll
        for (int ks = 0; ks < 2; ks++) {
            const int kb2 = ks * 8;
            uint32_t afh[2][4], bh4[2][4], bl4[2][4];
#pragma unroll
            for (int mt = 0; mt < 2; mt++) {
                uint32_t ad = aB + (((wm0 + mt * 16 + (lane & 15)) * 20 + kb2 +
                                     ((lane >> 4) << 2)) << 2);
                LDSM4(afh[mt], ad);
            }
#pragma unroll
            for (int ntp = 0; ntp < 2; ntp++) {
                int nrow = wn0 + ntp * 16 + (lane & 7) + ((lane >> 4) << 3);
                int koff = kb2 + (((lane >> 3) & 1) << 2);
                uint32_t bd = bB + ((nrow * 20 + koff) << 2);
                LDSM4(bh4[ntp], bd);
                LDSM4(bl4[ntp], bd + 10240);
            }
#pragma unroll
            for (int mt = 0; mt < 2; mt++)
#pragma unroll
                for (int ntp = 0; ntp < 2; ntp++)
#pragma unroll
                    for (int nb = 0; nb < 2; nb++) {
                        float* d = acc[mt][ntp * 2 + nb];
                        MMA_F16(d, afh[mt], bh4[ntp][nb * 2], bh4[ntp][nb * 2 + 1]);
                        MMA_F16(d, afh[mt], bl4[ntp][nb * 2], bl4[ntp][nb * 2 + 1]);
                    }
        }
    }

    // ---- store: z as half2, res as fp32 ----
#pragma unroll
    for (int mt = 0; mt < 2; mt++) {
#pragma unroll
        for (int nt = 0; nt < 4; nt++) {
            int r  = row0 + wm0 + mt * 16 + grp;
            int cC = col0C + wn0 + nt * 8 + qid * 2;
            if (isres) {
                if (r < n)
                    *(float2*)&Cres[(size_t)r * KH + cC] =
                        make_float2(acc[mt][nt][0], acc[mt][nt][1]);
                if (r + 8 < n)
                    *(float2*)&Cres[(size_t)(r + 8) * KH + cC] =
                        make_float2(acc[mt][nt][2], acc[mt][nt][3]);
            } else {
                if (r < n)
                    zOut[(size_t)r * 128 + (cC >> 1)] = packh2(acc[mt][nt][0], acc[mt][nt][1]);
                if (r + 8 < n)
                    zOut[(size_t)(r + 8) * 128 + (cC >> 1)] = packh2(acc[mt][nt][2], acc[mt][nt][3]);
            }
        }
    }
    // ---- fused attention projections el/er for head bx ----
    if (doattn) {
        const int hd = bx;
        float alv[4][2], arv[4][2];
#pragma unroll
        for (int nt = 0; nt < 4; nt++)
#pragma unroll
            for (int j = 0; j < 2; j++) {
                int c = wn0 + nt * 8 + qid * 2 + j;
                alv[nt][j] = alp[hd * 64 + c];
                arv[nt][j] = arp[hd * 64 + c];
            }
#pragma unroll
        for (int mt = 0; mt < 2; mt++) {
            float ea = 0.f, eb = 0.f, ra = 0.f, rb = 0.f;
#pragma unroll
            for (int nt = 0; nt < 4; nt++) {
                ea += acc[mt][nt][0] * alv[nt][0] + acc[mt][nt][1] * alv[nt][1];
                eb += acc[mt][nt][2] * alv[nt][0] + acc[mt][nt][3] * alv[nt][1];
                ra += acc[mt][nt][0] * arv[nt][0] + acc[mt][nt][1] * arv[nt][1];
                rb += acc[mt][nt][2] * arv[nt][0] + acc[mt][nt][3] * arv[nt][1];
            }
#pragma unroll
            for (int o = 1; o < 4; o <<= 1) {
                ea += __shfl_down_sync(0xffffffffu, ea, o, 4);
                eb += __shfl_down_sync(0xffffffffu, eb, o, 4);
                ra += __shfl_down_sync(0xffffffffu, ra, o, 4);
                rb += __shfl_down_sync(0xffffffffu, rb, o, 4);
            }
            if (qid == 0) {
                int rr = wm0 + mt * 16 + grp;
                int hf = wn0 >> 5;
                sEl[hf][rr] = ea; sEl[hf][rr + 8] = eb;
                sEr[hf][rr] = ra; sEr[hf][rr + 8] = rb;
            }
        }
        __syncthreads();
        if (tid < 128) {
            int gr = row0 + tid;
            if (gr < n) {
                g_el[gr * 4 + hd] = sEl[0][tid] + sEl[1][tid];
                g_er[gr * 4 + hd] = sEr[0][tid] + sEr[1][tid];
            }
        }
    }
}

// ================= fused GAT attention + aggregation + combine (two-pass) ======
// mode 0: flatten -> fp32 xout + fp16 xh2
// mode 1: head-mean + FUSED WeightedSumAndMax readout (gid/Wg/bg)
__global__ void gat_fused(const uint32_t* __restrict__ zh, const float* __restrict__ res,
                          const float* __restrict__ bias, float* __restrict__ xout,
                          int mode, uint32_t* __restrict__ xh2,
                          const int* __restrict__ gid, const float* __restrict__ Wg,
                          const float* __restrict__ bg) {
    __shared__ float sm[8][256];
    const int wIB  = threadIdx.x >> 5;
    const int n    = (blockIdx.x * blockDim.x + threadIdx.x) >> 5;
    const int lane = threadIdx.x & 31;
    if (n >= NN) return;
    const int r0 = g_rowptr[n];
    const int nE = g_rowptr[n + 1] - r0;
    const float4 erv = *(const float4*)&g_er[n * 4];
    const int myK = lane >> 3;

    float m0 = NEG_INF, m1 = NEG_INF, m2 = NEG_INF, m3 = NEG_INF;
    for (int b = 0; b < nE; b += 32) {
        int idx = b + lane;
        if (idx < nE) {
            int s = g_csrc[r0 + idx];
            float4 l = *(const float4*)&g_el[s * 4];
            m0 = fmaxf(m0, leaky02(l.x + erv.x));
            m1 = fmaxf(m1, leaky02(l.y + erv.y));
            m2 = fmaxf(m2, leaky02(l.z + erv.z));
            m3 = fmaxf(m3, leaky02(l.w + erv.w));
        }
    }
#pragma unroll
    for (int off = 16; off; off >>= 1) {
        m0 = fmaxf(m0, __shfl_xor_sync(0xffffffffu, m0, off));
        m1 = fmaxf(m1, __shfl_xor_sync(0xffffffffu, m1, off));
        m2 = fmaxf(m2, __shfl_xor_sync(0xffffffffu, m2, off));
        m3 = fmaxf(m3, __shfl_xor_sync(0xffffffffu, m3, off));
    }

    float acc[8] = {};
    float sl0 = 0.f, sl1 = 0.f, sl2 = 0.f, sl3 = 0.f;
    for (int b = 0; b < nE; b += 32) {
        int idx = b + lane;
        int cnt = min(32, nE - b);
        float p0 = 0.f, p1 = 0.f, p2 = 0.f, p3 = 0.f;
        int sN = 0;
        if (idx < nE) {
            sN = g_csrc[r0 + idx];
            float4 l = *(const float4*)&g_el[sN * 4];
            p0 = __expf(leaky02(l.x + erv.x) - m0);
            p1 = __expf(leaky02(l.y + erv.y) - m1);
            p2 = __expf(leaky02(l.z + erv.z) - m2);
            p3 = __expf(leaky02(l.w + erv.w) - m3);
            sl0 += p0; sl1 += p1; sl2 += p2; sl3 += p3;
        }
        int i = 0;
        for (; i + 4 <= cnt; i += 4) {
            int ss[4]; float pa[4];
#pragma unroll
            for (int j = 0; j < 4; j++) {
                ss[j] = __shfl_sync(0xffffffffu, sN, i + j);
                float q0 = __shfl_sync(0xffffffffu, p0, i + j);
                float q1 = __shfl_sync(0xffffffffu, p1, i + j);
                float q2 = __shfl_sync(0xffffffffu, p2, i + j);
                float q3 = __shfl_sync(0xffffffffu, p3, i + j);
                pa[j] = (myK == 0) ? q0 : (myK == 1) ? q1 : (myK == 2) ? q2 : q3;
            }
            uint4 zv[4];
#pragma unroll
            for (int j = 0; j < 4; j++)
                zv[j] = *(const uint4*)(zh + (size_t)ss[j] * 128 + lane * 4);
#pragma unroll
            for (int j = 0; j < 4; j++) {
                float2 f0 = __half22float2(*(__half2*)&zv[j].x);
                float2 f1 = __half22float2(*(__half2*)&zv[j].y);
                float2 f2 = __half22float2(*(__half2*)&zv[j].z);
                float2 f3 = __half22float2(*(__half2*)&zv[j].w);
                acc[0] += pa[j] * f0.x; acc[1] += pa[j] * f0.y;
                acc[2] += pa[j] * f1.x; acc[3] += pa[j] * f1.y;
                acc[4] += pa[j] * f2.x; acc[5] += pa[j] * f2.y;
                acc[6] += pa[j] * f3.x; acc[7] += pa[j] * f3.y;
            }
        }
        for (; i < cnt; i++) {
            int ss   = __shfl_sync(0xffffffffu, sN, i);
            float q0 = __shfl_sync(0xffffffffu, p0, i);
            float q1 = __shfl_sync(0xffffffffu, p1, i);
            float q2 = __shfl_sync(0xffffffffu, p2, i);
            float q3 = __shfl_sync(0xffffffffu, p3, i);
            float pa = (myK == 0) ? q0 : (myK == 1) ? q1 : (myK == 2) ? q2 : q3;
            uint4 zv = *(const uint4*)(zh + (size_t)ss * 128 + lane * 4);
            float2 f0 = __half22float2(*(__half2*)&zv.x);
            float2 f1 = __half22float2(*(__half2*)&zv.y);
            float2 f2 = __half22float2(*(__half2*)&zv.z);
            float2 f3 = __half22float2(*(__half2*)&zv.w);
            acc[0] += pa * f0.x; acc[1] += pa * f0.y;
            acc[2] += pa * f1.x; acc[3] += pa * f1.y;
            acc[4] += pa * f2.x; acc[5] += pa * f2.y;
            acc[6] += pa * f3.x; acc[7] += pa * f3.y;
        }
    }
#pragma unroll
    for (int off = 16; off; off >>= 1) {
        sl0 += __shfl_xor_sync(0xffffffffu, sl0, off);
        sl1 += __shfl_xor_sync(0xffffffffu, sl1, off);
        sl2 += __shfl_xor_sync(0xffffffffu, sl2, off);
        sl3 += __shfl_xor_sync(0xffffffffu, sl3, off);
    }
    float sk = (myK == 0) ? sl0 : (myK == 1) ? sl1 : (myK == 2) ? sl2 : sl3;
    float inv = (nE > 0) ? (1.0f / sk) : 0.0f;

    const int base = n * KH + lane * 8;
    float v[8];
    const float4* rp = (const float4*)(res + base);
    const float4* bp = (const float4*)(bias + lane * 8);
    float4 r4a = rp[0], r4b = rp[1], b4a = bp[0], b4b = bp[1];
    v[0] = acc[0] * inv + r4a.x + b4a.x; v[1] = acc[1] * inv + r4a.y + b4a.y;
    v[2] = acc[2] * inv + r4a.z + b4a.z; v[3] = acc[3] * inv + r4a.w + b4a.w;
    v[4] = acc[4] * inv + r4b.x + b4b.x; v[5] = acc[5] * inv + r4b.y + b4b.y;
    v[6] = acc[6] * inv + r4b.z + b4b.z; v[7] = acc[7] * inv + r4b.w + b4b.w;
#pragma unroll
    for (int j = 0; j < 8; j++) v[j] = v[j] > 0.f ? v[j] : 0.f;

    if (mode == 0) {
        float4* op = (float4*)(xout + base);
        op[0] = make_float4(v[0], v[1], v[2], v[3]);
        op[1] = make_float4(v[4], v[5], v[6], v[7]);
        *(uint4*)&xh2[(size_t)n * 128 + lane * 4] =
            make_uint4(packh2(v[0], v[1]), packh2(v[2], v[3]),
                       packh2(v[4], v[5]), packh2(v[6], v[7]));
    } else {
        // head-mean + fused WeightedSumAndMax readout
#pragma unroll
        for (int j = 0; j < 8; j++) sm[wIB][lane * 8 + j] = v[j];
        __syncwarp();
        float h0 = (sm[wIB][lane]       + sm[wIB][64 + lane] +
                    sm[wIB][128 + lane] + sm[wIB][192 + lane]) * 0.25f;
        float h1 = (sm[wIB][32 + lane]  + sm[wIB][96 + lane] +
                    sm[wIB][160 + lane] + sm[wIB][224 + lane]) * 0.25f;
        float p = h0 * Wg[lane] + h1 * Wg[lane + 32];
#pragma unroll
        for (int off = 16; off; off >>= 1) p += __shfl_down_sync(0xffffffffu, p, off);
        p = __shfl_sync(0xffffffffu, p, 0);
        float wgt = 1.0f / (1.0f + expf(-(p + bg[0])));
        int g = gid[n];
        atomicAdd(&g_gs[g * 64 + lane],      wgt * h0);
        atomicAdd(&g_gs[g * 64 + lane + 32], wgt * h1);
        atomicMaxF(&g_gm[g * 64 + lane],      h0);
        atomicMaxF(&g_gm[g * 64 + lane + 32], h1);
    }
}

// ================= MLP head =================
__global__ void mlp_head(const float* __restrict__ Wm1, const float* __restrict__ bm1,
                         const float* __restrict__ bn_g, const float* __restrict__ bn_b,
                         const float* __restrict__ bn_m, const float* __restrict__ bn_v,
                         const float* __restrict__ Wm2, const float* __restrict__ bm2,
                         float* __restrict__ out) {
    int g = blockIdx.x, j = threadIdx.x;
    __shared__ float gf[128];
    gf[j]      = g_gs[g * 64 + j];
    gf[j + 64] = g_gm[g * 64 + j];
    __syncthreads();
    float acc = bm1[j];
#pragma unroll 8
    for (int i = 0; i < 128; i++) acc += gf[i] * Wm1[i * 64 + j];
    float y = acc > 0.0f ? acc : 0.0f;
    y = (y - bn_m[j]) * rsqrtf(bn_v[j] + 1e-5f) * bn_g[j] + bn_b[j];
    __shared__ float red[64];
    red[j] = y * Wm2[j];
    __syncthreads();
    if (j == 0) {
        float t = 0.0f;
#pragma unroll
        for (int i = 0; i < 64; i++) t += red[i];
        out[g] = 1.0f / (1.0f + expf(-(t + bm2[0])));
    }
}

// ================= host launcher =================
extern "C" void kernel_launch(void* const* d_in, const int* in_sizes, int n_in,
                              void* d_out, int out_size) {
    (void)in_sizes; (void)n_in; (void)out_size;
    const float* h     = (const float*)d_in[0];
    const int*   src   = (const int*)d_in[1];
    const int*   dst   = (const int*)d_in[2];
    const int*   gid   = (const int*)d_in[3];
    const float* W0    = (const float*)d_in[4];
    const float* al0   = (const float*)d_in[5];
    const float* ar0   = (const float*)d_in[6];
    const float* b0    = (const float*)d_in[7];
    const float* resW0 = (const float*)d_in[8];
    const float* W1    = (const float*)d_in[9];
    const float* al1   = (const float*)d_in[10];
    const float* ar1   = (const float*)d_in[11];
    const float* b1    = (const float*)d_in[12];
    const float* W2    = (const float*)d_in[13];
    const float* al2   = (const float*)d_in[14];
    const float* ar2   = (const float*)d_in[15];
    const float* b2    = (const float*)d_in[16];
    const float* Wg    = (const float*)d_in[17];
    const float* bg    = (const float*)d_in[18];
    const float* Wm1   = (const float*)d_in[19];
    const float* bm1   = (const float*)d_in[20];
    const float* bng   = (const float*)d_in[21];
    const float* bnb   = (const float*)d_in[22];
    const float* bnm   = (const float*)d_in[23];
    const float* bnv   = (const float*)d_in[24];
    const float* Wm2   = (const float*)d_in[25];
    const float* bm2   = (const float*)d_in[26];

    float *p_res, *p_x;
    uint32_t *p_zh, *p_hh2, *p_xh2, *p_wh, *p_wl;
    cudaGetSymbolAddress((void**)&p_zh,  g_zh);
    cudaGetSymbolAddress((void**)&p_res, g_res);
    cudaGetSymbolAddress((void**)&p_x,   g_x);
    cudaGetSymbolAddress((void**)&p_hh2, g_hh2);
    cudaGetSymbolAddress((void**)&p_xh2, g_xh2);
    cudaGetSymbolAddress((void**)&p_wh,  g_wh);
    cudaGetSymbolAddress((void**)&p_wl,  g_wl);

    const int SMEM_GEMM = 40960;
    cudaFuncSetAttribute(gemm_h3, cudaFuncAttributeMaxDynamicSharedMemorySize, SMEM_GEMM);

    const int edgeB  = (EE + 255) / 256;
    const int nWarpB = (NN + 7) / 8;

    // ---- pre-split + init ----
    hsplit<<<(NN * 64 + 255) / 256, 256>>>(h);
    wsplit_all<<<(98304 + 255) / 256, 256>>>(W0, resW0, W1, W2);

    // ---- Layer 0 GEMMs merged (z + res in one launch) ----
    gemm_h3<<<dim3(8, (NN + 127) / 128), 256, SMEM_GEMM>>>(
        p_hh2, p_wh, p_wl, p_zh, p_res, NN, FF, al0, ar0);

    // ---- CSR build ----
    csr_hist<<<edgeB, 256>>>(dst);
    csr_scan<<<1, 1024>>>();
    csr_fill_k<<<edgeB, 256>>>(src, dst);

    // ---- Layer 0 combine ----
    gat_fused<<<nWarpB, 256>>>(p_zh, p_res, b0, p_x, 0, p_xh2, nullptr, nullptr, nullptr);

    // ---- Layer 1 ----
    gemm_h3<<<dim3(4, (NN + 127) / 128), 256, SMEM_GEMM>>>(
        p_xh2, p_wh + 32768, p_wl + 32768, p_zh, nullptr, NN, KH, al1, ar1);
    gat_fused<<<nWarpB, 256>>>(p_zh, p_x, b1, p_x, 0, p_xh2, nullptr, nullptr, nullptr);

    // ---- Layer 2 (head-mean + fused readout) ----
    gemm_h3<<<dim3(4, (NN + 127) / 128), 256, SMEM_GEMM>>>(
        p_xh2, p_wh + 65536, p_wl + 65536, p_zh, nullptr, NN, KH, al2, ar2);
    gat_fused<<<nWarpB, 256>>>(p_zh, p_x, b2, nullptr, 1, nullptr, gid, Wg, bg);

    // ---- MLP head ----
    mlp_head<<<GG, 64>>>(Wm1, bm1, bng, bnb, bnm, bnv, Wm2, bm2, (float*)d_out);
}